// round 6
// baseline (speedup 1.0000x reference)
#include <cuda_runtime.h>
#include <cuda_bf16.h>
#include <cstdint>

// ---------------- problem constants ----------------
#define B_    4
#define L_    4096
#define DM_   1024
#define H_    16
#define D_    64
#define M_    128
#define BH_   64          // B*H
#define SEG_  32          // L/M
#define NTOK_ 16384       // B*L

// single dynamic-smem symbol for the whole TU
extern __shared__ char dynsm[];

// ---------------- scratch (device globals; no allocations allowed) ----------------
__device__ float g_Ql[BH_ * M_ * D_];          // fp32 landmarks (for k2)
__device__ float g_Kl[BH_ * M_ * D_];
__device__ float g_k3[(size_t)BH_ * M_ * L_];  // raw scores fp32
__device__ float g_k2[BH_ * M_ * M_];
__device__ float g_P [BH_ * M_ * M_];
__device__ float g_M1[BH_ * M_ * M_];
__device__ float g_M2[BH_ * M_ * M_];
__device__ float g_Va[BH_ * M_ * M_];
__device__ float g_Vb[BH_ * M_ * M_];
__device__ float g_k3v_part[4 * BH_ * M_ * D_];
__device__ float g_k3v[BH_ * M_ * D_];

// bf16 split buffers
__device__ __align__(16) __nv_bfloat16 g_ah[(size_t)NTOK_ * DM_];   // gemm A hi
__device__ __align__(16) __nv_bfloat16 g_al[(size_t)NTOK_ * DM_];   // gemm A lo
__device__ __align__(16) __nv_bfloat16 g_wh[DM_ * DM_];             // W^T hi [n][k]
__device__ __align__(16) __nv_bfloat16 g_wl[DM_ * DM_];
__device__ __align__(16) __nv_bfloat16 g_qh[(size_t)BH_ * L_ * D_]; // q split [bh][l][d]
__device__ __align__(16) __nv_bfloat16 g_ql[(size_t)BH_ * L_ * D_];
__device__ __align__(16) __nv_bfloat16 g_kh[(size_t)BH_ * L_ * D_];
__device__ __align__(16) __nv_bfloat16 g_kl[(size_t)BH_ * L_ * D_];
__device__ __align__(16) __nv_bfloat16 g_vh[(size_t)BH_ * L_ * D_];
__device__ __align__(16) __nv_bfloat16 g_vl[(size_t)BH_ * L_ * D_];
__device__ __align__(16) __nv_bfloat16 g_Qlh[BH_ * M_ * D_];
__device__ __align__(16) __nv_bfloat16 g_Qll[BH_ * M_ * D_];
__device__ __align__(16) __nv_bfloat16 g_Klh[BH_ * M_ * D_];
__device__ __align__(16) __nv_bfloat16 g_Kll[BH_ * M_ * D_];
__device__ __align__(16) __nv_bfloat16 g_k1h[(size_t)BH_ * L_ * M_]; // kernel_1 split [bh][l][m]
__device__ __align__(16) __nv_bfloat16 g_k1l[(size_t)BH_ * L_ * M_];
__device__ __align__(16) __nv_bfloat16 g_s3h[(size_t)BH_ * M_ * L_]; // softmaxed k3 split [bh][m][l]
__device__ __align__(16) __nv_bfloat16 g_s3l[(size_t)BH_ * M_ * L_];
__device__ __align__(16) __nv_bfloat16 g_y2th[BH_ * D_ * M_];        // y2^T split [bh][d][m]
__device__ __align__(16) __nv_bfloat16 g_y2tl[BH_ * D_ * M_];

// =====================================================================
// PTX helpers (baseline set only: mma.sync / ldmatrix / cp.async)
// =====================================================================
__device__ __forceinline__ uint32_t smem_to_u32(const void* p) {
    uint32_t a;
    asm("{ .reg .u64 t; cvta.to.shared.u64 t, %1; cvt.u32.u64 %0, t; }" : "=r"(a) : "l"(p));
    return a;
}
__device__ __forceinline__ void ldsm4(uint32_t* r, uint32_t addr) {
    asm volatile("ldmatrix.sync.aligned.m8n8.x4.shared.b16 {%0,%1,%2,%3}, [%4];"
        : "=r"(r[0]), "=r"(r[1]), "=r"(r[2]), "=r"(r[3]) : "r"(addr));
}
__device__ __forceinline__ void ldsm4t(uint32_t* r, uint32_t addr) {
    asm volatile("ldmatrix.sync.aligned.m8n8.x4.trans.shared.b16 {%0,%1,%2,%3}, [%4];"
        : "=r"(r[0]), "=r"(r[1]), "=r"(r[2]), "=r"(r[3]) : "r"(addr));
}
__device__ __forceinline__ void mma16816(float* d, const uint32_t* a, const uint32_t* b) {
    asm volatile("mma.sync.aligned.m16n8k16.row.col.f32.bf16.bf16.f32 "
        "{%0,%1,%2,%3}, {%4,%5,%6,%7}, {%8,%9}, {%0,%1,%2,%3};"
        : "+f"(d[0]), "+f"(d[1]), "+f"(d[2]), "+f"(d[3])
        : "r"(a[0]), "r"(a[1]), "r"(a[2]), "r"(a[3]), "r"(b[0]), "r"(b[1]));
}
#define CP_ASYNC16(dst, src) \
    asm volatile("cp.async.cg.shared.global [%0], [%1], 16;" :: "r"(dst), "l"(src))
#define CP_COMMIT()  asm volatile("cp.async.commit_group;" ::: "memory")
#define CP_WAIT(n)   asm volatile("cp.async.wait_group %0;" :: "n"(n) : "memory")

__device__ __forceinline__ void split_bf16(float v, __nv_bfloat16& h, __nv_bfloat16& l) {
    h = __float2bfloat16(v);
    l = __float2bfloat16(v - __bfloat162float(h));
}

// =====================================================================
// conversion kernels (fp32 -> bf16 hi/lo split)
// =====================================================================
__global__ void conv_act_kernel(const float* __restrict__ src)
{
    size_t i4 = (size_t)blockIdx.x * 256 + threadIdx.x;
    float4 v = *(const float4*)&src[i4 * 4];
    __nv_bfloat16 h[4], l[4];
    float a[4] = {v.x, v.y, v.z, v.w};
    #pragma unroll
    for (int i = 0; i < 4; i++) split_bf16(a[i], h[i], l[i]);
    *(uint2*)&g_ah[i4 * 4] = *(uint2*)h;
    *(uint2*)&g_al[i4 * 4] = *(uint2*)l;
}

__global__ void conv_wt_kernel(const float* __restrict__ W)
{
    __shared__ float t[32][33];
    int x = blockIdx.x * 32 + threadIdx.x;
    int y = blockIdx.y * 32 + threadIdx.y;
    #pragma unroll
    for (int j = 0; j < 32; j += 8) t[threadIdx.y + j][threadIdx.x] = W[(size_t)(y + j) * 1024 + x];
    __syncthreads();
    int xo = blockIdx.y * 32 + threadIdx.x;
    int yo = blockIdx.x * 32 + threadIdx.y;
    #pragma unroll
    for (int j = 0; j < 32; j += 8) {
        float v = t[threadIdx.x][threadIdx.y + j];
        __nv_bfloat16 h, l; split_bf16(v, h, l);
        g_wh[(size_t)(yo + j) * 1024 + xo] = h;
        g_wl[(size_t)(yo + j) * 1024 + xo] = l;
    }
}

// =====================================================================
// main projection GEMM — 3-stage cp.async pipeline, ONE sync per chunk
// =====================================================================
#define PITCH   40
#define TSZ     (128 * PITCH * 2)
#define BUFSZ   (4 * TSZ)            // 40960 per stage
#define NSTAGE  3
#define OFF_AH  0
#define OFF_AL  (1 * TSZ)
#define OFF_BH  (2 * TSZ)
#define OFF_BL  (3 * TSZ)

__global__ __launch_bounds__(256) void gemm_mma_kernel(
    const __nv_bfloat16* __restrict__ Ah, const __nv_bfloat16* __restrict__ Al,
    const float* __restrict__ bias, float* __restrict__ outp, int mode)
{
    char* smem = dynsm;
    const uint32_t sbase = smem_to_u32(smem);

    const int tid  = threadIdx.x;
    const int lane = tid & 31;
    const int w    = tid >> 5;
    const int wm   = w >> 2;
    const int wn   = w & 3;
    const int n0 = blockIdx.x * 128;
    const int m0 = blockIdx.y * 128;

    float acc[4][4][4];
    #pragma unroll
    for (int i = 0; i < 4; i++)
        #pragma unroll
        for (int j = 0; j < 4; j++)
            #pragma unroll
            for (int t = 0; t < 4; t++) acc[i][j][t] = 0.f;

    auto load_chunk = [&](int c, int buf) {
        const int k0 = c * 32;
        const uint32_t sb = sbase + buf * BUFSZ;
        #pragma unroll
        for (int i = 0; i < 8; i++) {
            int q = tid + i * 256;
            int arr = q >> 9;
            int r   = (q >> 2) & 127;
            int c4  = q & 3;
            uint32_t dst = sb + arr * TSZ + r * 80 + c4 * 16;
            const __nv_bfloat16* src;
            if      (arr == 0) src = &Ah  [(size_t)(m0 + r) * 1024 + k0 + c4 * 8];
            else if (arr == 1) src = &Al  [(size_t)(m0 + r) * 1024 + k0 + c4 * 8];
            else if (arr == 2) src = &g_wh[(size_t)(n0 + r) * 1024 + k0 + c4 * 8];
            else               src = &g_wl[(size_t)(n0 + r) * 1024 + k0 + c4 * 8];
            CP_ASYNC16(dst, src);
        }
        CP_COMMIT();
    };

    auto compute_chunk = [&](int buf) {
        const uint32_t S = sbase + buf * BUFSZ;
        #pragma unroll
        for (int k16 = 0; k16 < 2; k16++) {
            const uint32_t kb = (uint32_t)(k16 * 32);
            uint32_t af[2][4][4];
            #pragma unroll
            for (int term = 0; term < 2; term++) {
                uint32_t base = S + (term ? OFF_AL : OFF_AH);
                #pragma unroll
                for (int mt = 0; mt < 4; mt++) {
                    uint32_t addr = base
                        + (uint32_t)((wm * 64 + mt * 16 + (lane & 15)) * 80)
                        + kb + (uint32_t)((lane >> 4) * 16);
                    ldsm4(af[term][mt], addr);
                }
            }
            uint32_t bf[2][2][4];
            #pragma unroll
            for (int term = 0; term < 2; term++) {
                uint32_t base = S + (term ? OFF_BL : OFF_BH);
                #pragma unroll
                for (int np = 0; np < 2; np++) {
                    uint32_t nrow = (uint32_t)(wn * 32 + np * 16 + ((lane >> 4) * 8) + (lane & 7));
                    uint32_t addr = base + nrow * 80 + kb + (uint32_t)(((lane >> 3) & 1) * 16);
                    ldsm4(bf[term][np], addr);
                }
            }
            #pragma unroll
            for (int mt = 0; mt < 4; mt++) {
                #pragma unroll
                for (int nt = 0; nt < 4; nt++) {
                    float* d = acc[mt][nt];
                    const uint32_t* bh_ = &bf[0][nt >> 1][(nt & 1) * 2];
                    const uint32_t* bl_ = &bf[1][nt >> 1][(nt & 1) * 2];
                    mma16816(d, af[0][mt], bh_);
                    mma16816(d, af[0][mt], bl_);
                    mma16816(d, af[1][mt], bh_);
                }
            }
        }
    };

    // 3-stage pipeline: wait(1) -> sync -> issue load(c+2) -> compute(c)
    load_chunk(0, 0);
    load_chunk(1, 1);
    #pragma unroll 1
    for (int c = 0; c < 32; c++) {
        if (c < 31) { CP_WAIT(1); } else { CP_WAIT(0); }
        __syncthreads();
        if (c + 2 < 32) {
            int nb = (c + 2) % NSTAGE;
            load_chunk(c + 2, nb);
        }
        compute_chunk(c % NSTAGE);
    }

    #pragma unroll
    for (int mt = 0; mt < 4; mt++) {
        #pragma unroll
        for (int nt = 0; nt < 4; nt++) {
            int c = n0 + wn * 32 + nt * 8 + (lane & 3) * 2;
            float b0 = bias[c], b1 = bias[c + 1];
            #pragma unroll
            for (int half = 0; half < 2; half++) {
                int r = m0 + wm * 64 + mt * 16 + (lane >> 2) + half * 8;
                float vx = acc[mt][nt][half * 2 + 0] + b0;
                float vy = acc[mt][nt][half * 2 + 1] + b1;
                if (mode == 3) {
                    float2 t = {vx, vy};
                    *(float2*)&outp[(size_t)r * 1024 + c] = t;
                } else {
                    __nv_bfloat16* dh = (mode == 0) ? g_qh : ((mode == 1) ? g_kh : g_vh);
                    __nv_bfloat16* dl = (mode == 0) ? g_ql : ((mode == 1) ? g_kl : g_vl);
                    int b = r >> 12, l = r & 4095;
                    int h = c >> 6, d = c & 63;
                    size_t o = (((size_t)(b * 16 + h) * 4096) + l) * 64 + d;
                    __nv_bfloat16 hp[2], lp[2];
                    split_bf16(vx, hp[0], lp[0]);
                    split_bf16(vy, hp[1], lp[1]);
                    *(uint32_t*)&dh[o] = *(uint32_t*)hp;
                    *(uint32_t*)&dl[o] = *(uint32_t*)lp;
                }
            }
        }
    }
}

// =====================================================================
// landmark pooling from split q/k; writes fp32 + split landmarks
// =====================================================================
__global__ void pool_kernel()
{
    int idx = blockIdx.x * blockDim.x + threadIdx.x;   // BH*M*D
    int d  = idx & 63;
    int m  = (idx >> 6) & 127;
    int bh = idx >> 13;
    size_t base = ((size_t)bh * L_ + m * SEG_) * D_ + d;
    float sq = 0.f, sk = 0.f;
    #pragma unroll
    for (int s = 0; s < SEG_; s++) {
        sq += __bfloat162float(g_qh[base + s * D_]) + __bfloat162float(g_ql[base + s * D_]);
        sk += __bfloat162float(g_kh[base + s * D_]) + __bfloat162float(g_kl[base + s * D_]);
    }
    float mq = sq * (1.f / SEG_), mk = sk * (1.f / SEG_);
    g_Ql[idx] = mq; g_Kl[idx] = mk;
    __nv_bfloat16 h, l;
    split_bf16(mq, h, l); g_Qlh[idx] = h; g_Qll[idx] = l;
    split_bf16(mk, h, l); g_Klh[idx] = h; g_Kll[idx] = l;
}

// =====================================================================
// k1: C[128 tok][128 lm] = q_blk @ Kl^T (split mma) + fused softmax -> split bf16
// smem: Ah 0 | Al 18432 | Bh 36864 | Bl 55296  (pitch 144 B); dyn smem 73728
// =====================================================================
__global__ __launch_bounds__(256) void k1_mma_kernel()
{
    char* sm = dynsm;
    const uint32_t sb = smem_to_u32(sm);
    int bh = blockIdx.y, l0 = blockIdx.x * 128, tid = threadIdx.x;
    int lane = tid & 31, w = tid >> 5;

    {
        const __nv_bfloat16* qh = g_qh + ((size_t)bh * L_ + l0) * D_;
        const __nv_bfloat16* ql = g_ql + ((size_t)bh * L_ + l0) * D_;
        const __nv_bfloat16* kh = g_Klh + bh * (M_ * D_);
        const __nv_bfloat16* kl = g_Kll + bh * (M_ * D_);
        #pragma unroll
        for (int i = 0; i < 4; i++) {
            int q = tid + i * 256;              // 0..1023
            int row = q >> 3, c8 = q & 7;
            uint32_t so = (uint32_t)(row * 144 + c8 * 16);
            size_t go = (size_t)row * 64 + c8 * 8;
            *(uint4*)(sm + 0     + so) = *(const uint4*)&qh[go];
            *(uint4*)(sm + 18432 + so) = *(const uint4*)&ql[go];
            *(uint4*)(sm + 36864 + so) = *(const uint4*)&kh[go];
            *(uint4*)(sm + 55296 + so) = *(const uint4*)&kl[go];
        }
    }
    __syncthreads();

    int wm = w >> 2, wn = w & 3;
    float acc[4][4][4];
    #pragma unroll
    for (int i = 0; i < 4; i++)
        #pragma unroll
        for (int j = 0; j < 4; j++)
            #pragma unroll
            for (int t = 0; t < 4; t++) acc[i][j][t] = 0.f;

    #pragma unroll
    for (int k16 = 0; k16 < 4; k16++) {
        uint32_t af[2][4][4];
        #pragma unroll
        for (int term = 0; term < 2; term++)
            #pragma unroll
            for (int mt = 0; mt < 4; mt++) {
                uint32_t addr = sb + term * 18432
                    + (uint32_t)((wm * 64 + mt * 16 + (lane & 15)) * 144)
                    + (uint32_t)(k16 * 32) + (uint32_t)((lane >> 4) * 16);
                ldsm4(af[term][mt], addr);
            }
        uint32_t bf[2][2][4];
        #pragma unroll
        for (int term = 0; term < 2; term++)
            #pragma unroll
            for (int np = 0; np < 2; np++) {
                uint32_t nrow = (uint32_t)(wn * 32 + np * 16 + ((lane >> 4) * 8) + (lane & 7));
                uint32_t addr = sb + 36864 + term * 18432 + nrow * 144
                    + (uint32_t)(k16 * 32) + (uint32_t)(((lane >> 3) & 1) * 16);
                ldsm4(bf[term][np], addr);
            }
        #pragma unroll
        for (int mt = 0; mt < 4; mt++)
            #pragma unroll
            for (int nt = 0; nt < 4; nt++) {
                float* d = acc[mt][nt];
                const uint32_t* bh_ = &bf[0][nt >> 1][(nt & 1) * 2];
                const uint32_t* bl_ = &bf[1][nt >> 1][(nt & 1) * 2];
                mma16816(d, af[0][mt], bh_);
                mma16816(d, af[0][mt], bl_);
                mma16816(d, af[1][mt], bh_);
            }
    }
    __syncthreads();

    float* S = (float*)sm;
    #pragma unroll
    for (int mt = 0; mt < 4; mt++)
        #pragma unroll
        for (int nt = 0; nt < 4; nt++)
            #pragma unroll
            for (int half = 0; half < 2; half++) {
                int row = wm * 64 + mt * 16 + (lane >> 2) + half * 8;
                int col = wn * 32 + nt * 8 + (lane & 3) * 2;
                S[row * 128 + col]     = acc[mt][nt][half * 2 + 0];
                S[row * 128 + col + 1] = acc[mt][nt][half * 2 + 1];
            }
    __syncthreads();

    for (int rr = 0; rr < 16; rr++) {
        int row = w * 16 + rr;
        float x0 = S[row * 128 + lane],      x1 = S[row * 128 + lane + 32];
        float x2 = S[row * 128 + lane + 64], x3 = S[row * 128 + lane + 96];
        float mx = fmaxf(fmaxf(x0, x1), fmaxf(x2, x3));
        #pragma unroll
        for (int o = 16; o; o >>= 1) mx = fmaxf(mx, __shfl_xor_sync(0xffffffffu, mx, o));
        float e0 = __expf(x0 - mx), e1 = __expf(x1 - mx);
        float e2 = __expf(x2 - mx), e3 = __expf(x3 - mx);
        float s = e0 + e1 + e2 + e3;
        #pragma unroll
        for (int o = 16; o; o >>= 1) s += __shfl_xor_sync(0xffffffffu, s, o);
        float inv = 1.f / s;
        size_t ob = ((size_t)bh * L_ + l0 + row) * 128;
        float vv[4] = {e0 * inv, e1 * inv, e2 * inv, e3 * inv};
        #pragma unroll
        for (int j = 0; j < 4; j++) {
            __nv_bfloat16 h, l; split_bf16(vv[j], h, l);
            g_k1h[ob + lane + 32 * j] = h;
            g_k1l[ob + lane + 32 * j] = l;
        }
    }
}

// =====================================================================
// k3 scores: C[m=128][l=128 blk] = Ql @ k_blk^T (split mma) -> raw fp32 g_k3
// dyn smem 73728
// =====================================================================
__global__ __launch_bounds__(256) void k3score_mma_kernel()
{
    char* sm = dynsm;
    const uint32_t sb = smem_to_u32(sm);
    int bh = blockIdx.y, l0 = blockIdx.x * 128, tid = threadIdx.x;
    int lane = tid & 31, w = tid >> 5;

    {
        const __nv_bfloat16* ah = g_Qlh + bh * (M_ * D_);
        const __nv_bfloat16* al = g_Qll + bh * (M_ * D_);
        const __nv_bfloat16* bhp = g_kh + ((size_t)bh * L_ + l0) * D_;
        const __nv_bfloat16* blp = g_kl + ((size_t)bh * L_ + l0) * D_;
        #pragma unroll
        for (int i = 0; i < 4; i++) {
            int q = tid + i * 256;
            int row = q >> 3, c8 = q & 7;
            uint32_t so = (uint32_t)(row * 144 + c8 * 16);
            size_t go = (size_t)row * 64 + c8 * 8;
            *(uint4*)(sm + 0     + so) = *(const uint4*)&ah[go];
            *(uint4*)(sm + 18432 + so) = *(const uint4*)&al[go];
            *(uint4*)(sm + 36864 + so) = *(const uint4*)&bhp[go];
            *(uint4*)(sm + 55296 + so) = *(const uint4*)&blp[go];
        }
    }
    __syncthreads();

    int wm = w >> 2, wn = w & 3;
    float acc[4][4][4];
    #pragma unroll
    for (int i = 0; i < 4; i++)
        #pragma unroll
        for (int j = 0; j < 4; j++)
            #pragma unroll
            for (int t = 0; t < 4; t++) acc[i][j][t] = 0.f;

    #pragma unroll
    for (int k16 = 0; k16 < 4; k16++) {
        uint32_t af[2][4][4];
        #pragma unroll
        for (int term = 0; term < 2; term++)
            #pragma unroll
            for (int mt = 0; mt < 4; mt++) {
                uint32_t addr = sb + term * 18432
                    + (uint32_t)((wm * 64 + mt * 16 + (lane & 15)) * 144)
                    + (uint32_t)(k16 * 32) + (uint32_t)((lane >> 4) * 16);
                ldsm4(af[term][mt], addr);
            }
        uint32_t bf[2][2][4];
        #pragma unroll
        for (int term = 0; term < 2; term++)
            #pragma unroll
            for (int np = 0; np < 2; np++) {
                uint32_t nrow = (uint32_t)(wn * 32 + np * 16 + ((lane >> 4) * 8) + (lane & 7));
                uint32_t addr = sb + 36864 + term * 18432 + nrow * 144
                    + (uint32_t)(k16 * 32) + (uint32_t)(((lane >> 3) & 1) * 16);
                ldsm4(bf[term][np], addr);
            }
        #pragma unroll
        for (int mt = 0; mt < 4; mt++)
            #pragma unroll
            for (int nt = 0; nt < 4; nt++) {
                float* d = acc[mt][nt];
                const uint32_t* bh_ = &bf[0][nt >> 1][(nt & 1) * 2];
                const uint32_t* bl_ = &bf[1][nt >> 1][(nt & 1) * 2];
                mma16816(d, af[0][mt], bh_);
                mma16816(d, af[0][mt], bl_);
                mma16816(d, af[1][mt], bh_);
            }
    }

    float* o = g_k3 + (size_t)bh * M_ * L_;
    #pragma unroll
    for (int mt = 0; mt < 4; mt++)
        #pragma unroll
        for (int nt = 0; nt < 4; nt++)
            #pragma unroll
            for (int half = 0; half < 2; half++) {
                int m_r = wm * 64 + mt * 16 + (lane >> 2) + half * 8;
                int l_c = l0 + wn * 32 + nt * 8 + (lane & 3) * 2;
                float2 t = {acc[mt][nt][half * 2 + 0], acc[mt][nt][half * 2 + 1]};
                *(float2*)&o[(size_t)m_r * L_ + l_c] = t;
            }
}

// =====================================================================
// row softmax over 4096; reads fp32 g_k3, writes split bf16 g_s3
// =====================================================================
__global__ __launch_bounds__(256) void softmax4096_kernel()
{
    size_t row = blockIdx.x;
    const float* p = g_k3 + row * 4096;
    int tid = threadIdx.x;
    float v[16];
    float mx = -1e30f;
    #pragma unroll
    for (int i = 0; i < 4; i++) {
        float4 t = *(const float4*)&p[i * 1024 + tid * 4];
        v[i * 4 + 0] = t.x; v[i * 4 + 1] = t.y; v[i * 4 + 2] = t.z; v[i * 4 + 3] = t.w;
        mx = fmaxf(mx, fmaxf(fmaxf(t.x, t.y), fmaxf(t.z, t.w)));
    }
    __shared__ float smx[8], ssm[8], sres;
    #pragma unroll
    for (int o = 16; o; o >>= 1) mx = fmaxf(mx, __shfl_xor_sync(0xffffffffu, mx, o));
    if ((tid & 31) == 0) smx[tid >> 5] = mx;
    __syncthreads();
    if (tid == 0) {
        float m = smx[0];
        #pragma unroll
        for (int i = 1; i < 8; i++) m = fmaxf(m, smx[i]);
        sres = m;
    }
    __syncthreads();
    float MX = sres;
    float s = 0.f;
    #pragma unroll
    for (int i = 0; i < 16; i++) { v[i] = __expf(v[i] - MX); s += v[i]; }
    #pragma unroll
    for (int o = 16; o; o >>= 1) s += __shfl_xor_sync(0xffffffffu, s, o);
    if ((tid & 31) == 0) ssm[tid >> 5] = s;
    __syncthreads();
    if (tid == 0) {
        float t = 0.f;
        #pragma unroll
        for (int i = 0; i < 8; i++) t += ssm[i];
        sres = 1.f / t;
    }
    __syncthreads();
    float inv = sres;
    #pragma unroll
    for (int i = 0; i < 4; i++) {
        __nv_bfloat16 hh[4], ll[4];
        #pragma unroll
        for (int t = 0; t < 4; t++) split_bf16(v[i * 4 + t] * inv, hh[t], ll[t]);
        *(uint2*)&g_s3h[row * 4096 + i * 1024 + tid * 4] = *(uint2*)hh;
        *(uint2*)&g_s3l[row * 4096 + i * 1024 + tid * 4] = *(uint2*)ll;
    }
}

// =====================================================================
// kernel_2 = softmax(Q_l @ K_l^T) fused (fp32, tiny). block per head.
// =====================================================================
__global__ __launch_bounds__(256) void k2_kernel()
{
    float* sm = (float*)dynsm;
    float* Qlt = sm;
    float* Klt = sm + 8192;
    float* S   = sm + 16384;
    int bh = blockIdx.x, tid = threadIdx.x;

    const float* Ql = g_Ql + bh * 8192;
    const float* Kl = g_Kl + bh * 8192;
    #pragma unroll
    for (int i = 0; i < 8; i++) {
        int f = i * 1024 + tid * 4; int m = f >> 6, d0 = f & 63;
        float4 tq = *(const float4*)&Ql[f];
        float4 tk = *(const float4*)&Kl[f];
        Qlt[(d0 + 0) * 128 + m] = tq.x; Qlt[(d0 + 1) * 128 + m] = tq.y;
        Qlt[(d0 + 2) * 128 + m] = tq.z; Qlt[(d0 + 3) * 128 + m] = tq.w;
        Klt[(d0 + 0) * 128 + m] = tk.x; Klt[(d0 + 1) * 128 + m] = tk.y;
        Klt[(d0 + 2) * 128 + m] = tk.z; Klt[(d0 + 3) * 128 + m] = tk.w;
    }
    __syncthreads();

    int tm = tid >> 4, tn = tid & 15;
    float acc[8][8] = {};
    for (int d = 0; d < 64; d++) {
        float4 a0 = *(const float4*)&Qlt[d * 128 + tm * 8];
        float4 a1 = *(const float4*)&Qlt[d * 128 + tm * 8 + 4];
        float4 b0 = *(const float4*)&Klt[d * 128 + tn * 8];
        float4 b1 = *(const float4*)&Klt[d * 128 + tn * 8 + 4];
        float av[8] = {a0.x, a0.y, a0.z, a0.w, a1.x, a1.y, a1.z, a1.w};
        float bv[8] = {b0.x, b0.y, b0.z, b0.w, b1.x, b1.y, b1.z, b1.w};
        #pragma unroll
        for (int i = 0; i < 8; i++)
            #pragma unroll
            for (int j = 0; j < 8; j++) acc[i][j] += av[i] * bv[j];
    }
    #pragma unroll
    for (int i = 0; i < 8; i++)
        #pragma unroll
        for (int j = 0; j < 8; j++) S[(tm * 8 + i) * 128 + tn * 8 + j] = acc[i][j];
    __syncthreads();

    int lane = tid & 31, w = tid >> 5;
    for (int rr = 0; rr < 16; rr++) {
        int row = w * 16 + rr;
        float x0 = S[row * 128 + lane],      x1 = S[row * 128 + lane + 32];
        float x2 = S[row * 128 + lane + 64], x3 = S[row * 128 + lane + 96];
        float mx = fmaxf(fmaxf(x0, x1), fmaxf(x2, x3));
        #pragma unroll
        for (int o = 16; o; o >>= 1) mx = fmaxf(mx, __shfl_xor_sync(0xffffffffu, mx, o));
        float e0 = __expf(x0 - mx), e1 = __expf(x1 - mx);
        float e2 = __expf(x2 - mx), e3 = __expf(x3 - mx);
        float s = e0 + e1 + e2 + e3;
        #pragma unroll
        for (int o = 16; o; o >>= 1) s += __shfl_xor_sync(0xffffffffu, s, o);
        float inv = 1.f / s;
        float* o = g_k2 + bh * 16384 + row * 128;
        o[lane] = e0 * inv; o[lane + 32] = e1 * inv; o[lane + 64] = e2 * inv; o[lane + 96] = e3 * inv;
    }
}

// =====================================================================
// V0 = K^T / max(colsum(K))
// =====================================================================
__global__ __launch_bounds__(256) void vinit_kernel()
{
    int bh = blockIdx.x, tid = threadIdx.x;
    const float* K = g_k2 + bh * 16384;
    __shared__ float cs[128];
    __shared__ float sscale;
    if (tid < 128) {
        float s = 0.f;
        for (int r = 0; r < 128; r++) s += K[r * 128 + tid];
        cs[tid] = s;
    }
    __syncthreads();
    if (tid == 0) {
        float m = cs[0];
        for (int i = 1; i < 128; i++) m = fmaxf(m, cs[i]);
        sscale = 1.f / m;
    }
    __syncthreads();
    float scale = sscale;
    for (int f = tid; f < 16384; f += 256) {
        int i = f >> 7, j = f & 127;
        g_Va[bh * 16384 + f] = scale * K[j * 128 + i];
    }
}

// =====================================================================
// batched 128x128 bmm for Newton-Schulz (fp32)
// =====================================================================
__device__ __forceinline__ float* bufsel(int s)
{
    switch (s) {
        case 0: return g_k2; case 1: return g_P; case 2: return g_M1;
        case 3: return g_M2; case 4: return g_Va; default: return g_Vb;
    }
}

__global__ __launch_bounds__(256) void bmm_kernel(int as, int bs, int cs2, int os,
                                                  float alpha, float beta)
{
    float* sm = (float*)dynsm;
    float* Bs = sm;
    float* At = sm + 16384;
    int bh = blockIdx.y, r0 = blockIdx.x * 32, tid = threadIdx.x;
    const float* A  = bufsel(as)  + bh * 16384;
    const float* Bm = bufsel(bs)  + bh * 16384;
    const float* C  = bufsel(cs2) + bh * 16384;
    float* O        = bufsel(os)  + bh * 16384;

    #pragma unroll
    for (int i = 0; i < 16; i++) {
        int f = i * 1024 + tid * 4;
        *(float4*)&Bs[f] = *(const float4*)&Bm[f];
    }
    #pragma unroll
    for (int i = 0; i < 4; i++) {
        int f = i * 1024 + tid * 4; int r = f >> 7, k0 = f & 127;
        float4 t = *(const float4*)&A[(r0 + r) * 128 + k0];
        At[(k0 + 0) * 32 + r] = t.x; At[(k0 + 1) * 32 + r] = t.y;
        At[(k0 + 2) * 32 + r] = t.z; At[(k0 + 3) * 32 + r] = t.w;
    }
    __syncthreads();

    int rb = (tid >> 5) * 4, cb = (tid & 31) * 4;
    float acc[4][4] = {};
    for (int k = 0; k < 128; k++) {
        float a0 = At[k * 32 + rb + 0], a1 = At[k * 32 + rb + 1];
        float a2 = At[k * 32 + rb + 2], a3 = At[k * 32 + rb + 3];
        float4 b = *(const float4*)&Bs[k * 128 + cb];
        acc[0][0] += a0 * b.x; acc[0][1] += a0 * b.y; acc[0][2] += a0 * b.z; acc[0][3] += a0 * b.w;
        acc[1][0] += a1 * b.x; acc[1][1] += a1 * b.y; acc[1][2] += a1 * b.z; acc[1][3] += a1 * b.w;
        acc[2][0] += a2 * b.x; acc[2][1] += a2 * b.y; acc[2][2] += a2 * b.z; acc[2][3] += a2 * b.w;
        acc[3][0] += a3 * b.x; acc[3][1] += a3 * b.y; acc[3][2] += a3 * b.z; acc[3][3] += a3 * b.w;
    }
    #pragma unroll
    for (int i = 0; i < 4; i++)
        #pragma unroll
        for (int j = 0; j < 4; j++) {
            int idx = (r0 + rb + i) * 128 + cb + j;
            O[idx] = alpha * acc[i][j] + beta * C[idx];
        }
}

// =====================================================================
// k3v: partial C[m=128][d=64] = softmax(k3)_split @ v_split
// 3-stage cp.async pipeline, one sync per chunk. dyn smem 165888
// =====================================================================
#define KV_STG 55296

__global__ __launch_bounds__(256) void k3v_mma_kernel()
{
    char* sm = dynsm;
    const uint32_t sb = smem_to_u32(sm);
    int s = blockIdx.x, bh = blockIdx.y, tid = threadIdx.x;
    int lane = tid & 31, w = tid >> 5;
    int wm = w >> 1, wn = w & 1;
    const size_t abase = (size_t)bh * M_ * L_;
    const size_t vbase = (size_t)bh * L_ * D_;

    float acc[2][4][4];
    #pragma unroll
    for (int i = 0; i < 2; i++)
        #pragma unroll
        for (int j = 0; j < 4; j++)
            #pragma unroll
            for (int t = 0; t < 4; t++) acc[i][j][t] = 0.f;

    auto load = [&](int ck, int buf) {
        int k0 = s * 1024 + ck * 64;
        uint32_t S = sb + buf * KV_STG;
        #pragma unroll
        for (int i = 0; i < 8; i++) {               // A: scores split
            int q = tid + i * 256;
            int arr = q >> 10, row = (q >> 3) & 127, c8 = q & 7;
            uint32_t dst = S + arr * 18432 + (uint32_t)(row * 144 + c8 * 16);
            const __nv_bfloat16* src = (arr ? g_s3l : g_s3h) + abase + (size_t)row * L_ + k0 + c8 * 8;
            CP_ASYNC16(dst, src);
        }
        #pragma unroll
        for (int i = 0; i < 4; i++) {               // B: v split
            int q = tid + i * 256;
            int arr = q >> 9, row = (q >> 3) & 63, c8 = q & 7;
            uint32_t dst = S + 36864 + arr * 9216 + (uint32_t)(row * 144 + c8 * 16);
            const __nv_bfloat16* src = (arr ? g_vl : g_vh) + vbase + (size_t)(k0 + row) * D_ + c8 * 8;
            CP_ASYNC16(dst, src);
        }
        CP_COMMIT();
    };

    auto compute = [&](int buf) {
        uint32_t S = sb + buf * KV_STG;
        #pragma unroll
        for (int k16 = 0; k16 < 4; k16++) {
            uint32_t af[2][2][4];
            #pragma unroll
            for (int term = 0; term < 2; term++)
                #pragma unroll
                for (int mt = 0; mt < 2; mt++) {
                    uint32_t addr = S + term * 18432
                        + (uint32_t)((wm * 32 + mt * 16 + (lane & 15)) * 144)
                        + (uint32_t)(k16 * 32) + (uint32_t)((lane >> 4) * 16);
                    ldsm4(af[term][mt], addr);
                }
            uint32_t bf[2][2][4];
            #pragma unroll
            for (int term = 0; term < 2; term++)
                #pragma unroll
                for (int np = 0; np < 2; np++) {
                    uint32_t addr = S + 36864 + term * 9216
                        + (uint32_t)((k16 * 16 + (lane & 15)) * 144)
                        + (uint32_t)((wn * 32 + np * 16 + (lane >> 4) * 8) * 2);
                    ldsm4t(bf[term][np], addr);
                }
            #pragma unroll
            for (int mt = 0; mt < 2; mt++)
                #pragma unroll
                for (int nt = 0; nt < 4; nt++) {
                    float* d = acc[mt][nt];
                    const uint32_t* bh_ = &bf[0][nt >> 1][(nt & 1) * 2];
                    const uint32_t* bl_ = &bf[1][nt >> 1][(nt & 1) * 2];
                    mma16816(d, af[0][mt], bh_);
                    mma16816(d, af[0][mt], bl_);
                    mma16816(d, af[1][mt], bh_);
                }
        }
    };

    load(0, 0);
    load(1, 1);
    #pragma unroll 1
    for (int ck = 0; ck < 16; ck++) {
        if (ck < 15) { CP_WAIT(1); } else { CP_WAIT(0); }
        __syncthreads();
        if (ck + 2 < 16) load(ck + 2, (ck + 2) % 3);
        compute(ck % 3);
    }

    #pragma unroll
    for (int mt = 0; mt < 2; mt++)
        #pragma unroll
        for (int nt = 0; nt < 4; nt++)
            #pragma unroll
            for (int half = 0; half < 2; half++) {
                int m_r = wm * 32 + mt * 16 + (lane >> 2) + half * 8;
                int d_c = wn * 32 + nt * 8 + (lane & 3) * 2;
                float2 t = {acc[mt][nt][half * 2 + 0], acc[mt][nt][half * 2 + 1]};
                *(float2*)&g_k3v_part[((size_t)(s * 64 + bh) * 128 + m_r) * 64 + d_c] = t;
            }
}

__global__ void k3v_reduce_kernel()
{
    int idx = blockIdx.x * blockDim.x + threadIdx.x;  // 524288
    float s = 0.f;
    #pragma unroll
    for (int p = 0; p < 4; p++) s += g_k3v_part[(size_t)p * 524288 + idx];
    g_k3v[idx] = s;
}

// =====================================================================
// y2 = inv(g_Va) @ k3v per head (fp32); epilogue emits y2^T split bf16
// =====================================================================
__global__ __launch_bounds__(256) void y2_kernel()
{
    float* sm = (float*)dynsm;
    float* At = sm;
    float* Bs = sm + 16384;
    int bh = blockIdx.x, tid = threadIdx.x;
    const float* inv = g_Va + bh * 16384;
    const float* kv  = g_k3v + bh * 8192;

    #pragma unroll
    for (int i = 0; i < 16; i++) {
        int f = i * 1024 + tid * 4; int r = f >> 7, k0 = f & 127;
        float4 t = *(const float4*)&inv[f];
        At[(k0 + 0) * 128 + r] = t.x; At[(k0 + 1) * 128 + r] = t.y;
        At[(k0 + 2) * 128 + r] = t.z; At[(k0 + 3) * 128 + r] = t.w;
    }
    #pragma unroll
    for (int i = 0; i < 8; i++) {
        int f = i * 1024 + tid * 4;
        *(float4*)&Bs[f] = *(const float4*)&kv[f];
    }
    __syncthreads();

    int rt = tid >> 4, ct = tid & 15;
    float acc[8][4] = {};
    for (int k = 0; k < 128; k++) {
        float4 a0 = *(const float4*)&At[k * 128 + rt * 8];
        float4 a1 = *(const float4*)&At[k * 128 + rt * 8 + 4];
        float4 b  = *(const float4*)&Bs[k * 64 + ct * 4];
        float av[8] = {a0.x, a0.y, a0.z, a0.w, a1.x, a1.y, a1.z, a1.w};
        #pragma unroll
        for (int i = 0; i < 8; i++) {
            acc[i][0] += av[i] * b.x; acc[i][1] += av[i] * b.y;
            acc[i][2] += av[i] * b.z; acc[i][3] += av[i] * b.w;
        }
    }
    // transposed split store: y2t[bh][d][m]
    #pragma unroll
    for (int i = 0; i < 8; i++)
        #pragma unroll
        for (int j = 0; j < 4; j++) {
            __nv_bfloat16 h, l; split_bf16(acc[i][j], h, l);
            size_t o = (size_t)bh * 8192 + (ct * 4 + j) * 128 + rt * 8 + i;
            g_y2th[o] = h;
            g_y2tl[o] = l;
        }
}

// =====================================================================
// x1: C[l=128][d=64] = kernel1_split @ y2t_split (mma) -> g_ah/g_al split
// smem: Ah 0 | Al 34816 | Bh 69632 | Bl 87040 ; dyn smem 104448 (pitch 272 B)
// =====================================================================
__global__ __launch_bounds__(256) void x1_mma_kernel()
{
    char* sm = dynsm;
    const uint32_t sb = smem_to_u32(sm);
    int bh = blockIdx.y, l0 = blockIdx.x * 128, tid = threadIdx.x;
    int lane = tid & 31, w = tid >> 5;
    int wm = w >> 1, wn = w & 1;

    {
        const __nv_bfloat16* ah = g_k1h + ((size_t)bh * L_ + l0) * 128;
        const __nv_bfloat16* al = g_k1l + ((size_t)bh * L_ + l0) * 128;
        #pragma unroll
        for (int i = 0; i < 16; i++) {
            int q = tid + i * 256;                 // 0..4095
            int arr = q >> 11, row = (q >> 4) & 127, c16 = q & 15;
            uint32_t so = (uint32_t)(arr * 34816 + row * 272 + c16 * 16);
            const __nv_bfloat16* src = (arr ? al : ah) + (size_t)row * 128 + c16 * 8;
            *(uint4*)(sm + so) = *(const uint4*)src;
        }
        const __nv_bfloat16* bhp = g_y2th + (size_t)bh * 8192;
        const __nv_bfloat16* blp = g_y2tl + (size_t)bh * 8192;
        #pragma unroll
        for (int i = 0; i < 8; i++) {
            int q = tid + i * 256;                 // 0..2047
            int arr = q >> 10, row = (q >> 4) & 63, c16 = q & 15;
            uint32_t so = (uint32_t)(69632 + arr * 17408 + row * 272 + c16 * 16);
            const __nv_bfloat16* src = (arr ? blp : bhp) + (size_t)row * 128 + c16 * 8;
            *(uint4*)(sm + so) = *(const uint4*)src;
        }
    }
    __syncthreads();

    float acc[2][4][4];
    #pragma unroll
    for (int i = 0; i < 2; i++)
        #pragma unroll
        for (int j = 0; j < 4; j++)
            #pragma unroll
            for (int t = 0; t < 4; t++) acc[i][j][t] = 0.f;

    #pragma unroll
    for (int k16 = 0; k16 < 8; k16++) {
        uint32_t af[2][2][4];
        #pragma unroll
        for (int term = 0; term < 2; term++)
            #pragma unroll
            for (int mt = 0; mt < 2; mt++) {
                uint32_t addr = sb + term * 34816
                    + (uint32_t)((wm * 32 + mt * 16 + (lane & 15)) * 272)
                    + (uint32_t)(k16 * 32) + (uint32_t)((lane >> 4) * 16);
                ldsm4(af[term][mt], addr);
            }
        uint32_t bf[2][2][4];
        #pragma unroll
        for (int term = 0; term < 2; term++)
            #pragma unroll
            for (int np = 0; np < 2; np++) {
                uint32_t nrow = (uint32_t)(wn * 32 + np * 16 + ((lane >> 4) * 8) + (lane & 7));
                uint32_t addr = sb + 69632 + term * 17408 + nrow * 272
                    + (uint32_t)(k16 * 32) + (uint32_t)(((lane >> 3) & 1) * 16);
                ldsm4(bf[term][np], addr);
            }
        #pragma unroll
        for (int mt = 0; mt < 2; mt++)
            #pragma unroll
            for (int nt = 0; nt < 4; nt++) {
                float* d = acc[mt][nt];
                const uint32_t* bh_ = &bf[0][nt >> 1][(nt & 1) * 2];
                const uint32_t* bl_ = &bf[1][nt >> 1][(nt & 1) * 2];
                mma16816(d, af[0][mt], bh_);
                mma16816(d, af[0][mt], bl_);
                mma16816(d, af[1][mt], bh_);
            }
    }

    int b = bh >> 4, h = bh & 15;
    #pragma unroll
    for (int mt = 0; mt < 2; mt++)
        #pragma unroll
        for (int nt = 0; nt < 4; nt++)
            #pragma unroll
            for (int half = 0; half < 2; half++) {
                int l = l0 + wm * 32 + mt * 16 + (lane >> 2) + half * 8;
                int d_c = wn * 32 + nt * 8 + (lane & 3) * 2;
                size_t o = ((size_t)(b * L_ + l)) * DM_ + h * 64 + d_c;
                __nv_bfloat16 hp[2], lp[2];
                split_bf16(acc[mt][nt][half * 2 + 0], hp[0], lp[0]);
                split_bf16(acc[mt][nt][half * 2 + 1], hp[1], lp[1]);
                *(uint32_t*)&g_ah[o] = *(uint32_t*)hp;
                *(uint32_t*)&g_al[o] = *(uint32_t*)lp;
            }
}

// =====================================================================
// launch
// =====================================================================
extern "C" void kernel_launch(void* const* d_in, const int* in_sizes, int n_in,
                              void* d_out, int out_size)
{
    const float* queries = (const float*)d_in[0];
    const float* keys    = (const float*)d_in[1];
    const float* values  = (const float*)d_in[2];
    const float* Wq = (const float*)d_in[3];
    const float* bq = (const float*)d_in[4];
    const float* Wk = (const float*)d_in[5];
    const float* bk = (const float*)d_in[6];
    const float* Wv = (const float*)d_in[7];
    const float* bv = (const float*)d_in[8];
    const float* Wo = (const float*)d_in[9];
    const float* bo = (const float*)d_in[10];
    float* out = (float*)d_out;

    cudaFuncSetAttribute(gemm_mma_kernel,    cudaFuncAttributeMaxDynamicSharedMemorySize, 122880);
    cudaFuncSetAttribute(k1_mma_kernel,      cudaFuncAttributeMaxDynamicSharedMemorySize, 73728);
    cudaFuncSetAttribute(k3score_mma_kernel, cudaFuncAttributeMaxDynamicSharedMemorySize, 73728);
    cudaFuncSetAttribute(k3v_mma_kernel,     cudaFuncAttributeMaxDynamicSharedMemorySize, 165888);
    cudaFuncSetAttribute(x1_mma_kernel,      cudaFuncAttributeMaxDynamicSharedMemorySize, 104448);
    cudaFuncSetAttribute(k2_kernel,          cudaFuncAttributeMaxDynamicSharedMemorySize, 131072);
    cudaFuncSetAttribute(bmm_kernel,         cudaFuncAttributeMaxDynamicSharedMemorySize, 81920);
    cudaFuncSetAttribute(y2_kernel,          cudaFuncAttributeMaxDynamicSharedMemorySize, 98304);

    __nv_bfloat16 *ahp = nullptr, *alp = nullptr;
    cudaGetSymbolAddress((void**)&ahp, g_ah);
    cudaGetSymbolAddress((void**)&alp, g_al);

    dim3 wt_grid(32, 32), wt_blk(32, 8);
    dim3 gemm_grid(8, 128);

    // projections -> split bf16 q/k/v
    conv_wt_kernel<<<wt_grid, wt_blk>>>(Wq);
    conv_act_kernel<<<16384, 256>>>(queries);
    gemm_mma_kernel<<<gemm_grid, 256, 122880>>>(ahp, alp, bq, nullptr, 0);
    conv_wt_kernel<<<wt_grid, wt_blk>>>(Wk);
    conv_act_kernel<<<16384, 256>>>(keys);
    gemm_mma_kernel<<<gemm_grid, 256, 122880>>>(ahp, alp, bk, nullptr, 1);
    conv_wt_kernel<<<wt_grid, wt_blk>>>(Wv);
    conv_act_kernel<<<16384, 256>>>(values);
    gemm_mma_kernel<<<gemm_grid, 256, 122880>>>(ahp, alp, bv, nullptr, 2);

    // landmarks
    pool_kernel<<<2048, 256>>>();

    // kernel_1 (tensor-core, fused softmax)
    k1_mma_kernel<<<dim3(32, 64), 256, 73728>>>();

    // kernel_3 scores (tensor-core) + softmax -> split
    k3score_mma_kernel<<<dim3(32, 64), 256, 73728>>>();
    softmax4096_kernel<<<8192, 256>>>();

    // kernel_2 + Newton-Schulz (fp32)
    k2_kernel<<<64, 256, 131072>>>();
    vinit_kernel<<<64, 256>>>();
    int cur = 4, nxt = 5;
    for (int it = 0; it < 6; it++) {
        bmm_kernel<<<dim3(4, 64), 256, 81920>>>(0,   cur, 0,   1,   1.0f,  0.0f);
        bmm_kernel<<<dim3(4, 64), 256, 81920>>>(1,   1,   1,   2,  -1.0f,  7.0f);
        bmm_kernel<<<dim3(4, 64), 256, 81920>>>(1,   2,   1,   3,  -1.0f, 15.0f);
        bmm_kernel<<<dim3(4, 64), 256, 81920>>>(cur, 3,   cur, nxt, -0.25f, 3.25f);
        int t = cur; cur = nxt; nxt = t;
    }
    // cur == 4 (g_Va) holds the pseudo-inverse

    // kernel_3 @ v (tensor-core, 3-stage split-K 4)
    k3v_mma_kernel<<<dim3(4, 64), 256, 165888>>>();
    k3v_reduce_kernel<<<2048, 256>>>();

    // y2 (fp32 + transposed split epilogue), x1 (tensor-core) -> g_ah/g_al
    y2_kernel<<<64, 256, 98304>>>();
    x1_mma_kernel<<<dim3(32, 64), 256, 104448>>>();

    // output projection
    conv_wt_kernel<<<wt_grid, wt_blk>>>(Wo);
    gemm_mma_kernel<<<gemm_grid, 256, 122880>>>(ahp, alp, bo, out, 3);
}

// round 7
// speedup vs baseline: 1.0227x; 1.0227x over previous
#include <cuda_runtime.h>
#include <cuda_bf16.h>
#include <cstdint>

// ---------------- problem constants ----------------
#define B_    4
#define L_    4096
#define DM_   1024
#define H_    16
#define D_    64
#define M_    128
#define BH_   64          // B*H
#define SEG_  32          // L/M
#define NTOK_ 16384       // B*L

// single dynamic-smem symbol for the whole TU
extern __shared__ char dynsm[];

// ---------------- scratch (device globals; no allocations allowed) ----------------
__device__ float g_Ql[BH_ * M_ * D_];          // fp32 landmarks (for k2)
__device__ float g_Kl[BH_ * M_ * D_];
__device__ float g_k3[(size_t)BH_ * M_ * L_];  // raw scores fp32
__device__ float g_k2[BH_ * M_ * M_];
__device__ float g_P [BH_ * M_ * M_];
__device__ float g_M1[BH_ * M_ * M_];
__device__ float g_M2[BH_ * M_ * M_];
__device__ float g_Va[BH_ * M_ * M_];
__device__ float g_Vb[BH_ * M_ * M_];
__device__ float g_k3v_part[4 * BH_ * M_ * D_];
__device__ float g_k3v[BH_ * M_ * D_];

// bf16 split buffers (3 slots for fused QKV; slot 0 reused by output proj)
__device__ __align__(16) __nv_bfloat16 g_ah[(size_t)3 * NTOK_ * DM_];
__device__ __align__(16) __nv_bfloat16 g_al[(size_t)3 * NTOK_ * DM_];
__device__ __align__(16) __nv_bfloat16 g_wh[3 * DM_ * DM_];
__device__ __align__(16) __nv_bfloat16 g_wl[3 * DM_ * DM_];
__device__ __align__(16) __nv_bfloat16 g_qh[(size_t)BH_ * L_ * D_]; // q split [bh][l][d]
__device__ __align__(16) __nv_bfloat16 g_ql[(size_t)BH_ * L_ * D_];
__device__ __align__(16) __nv_bfloat16 g_kh[(size_t)BH_ * L_ * D_];
__device__ __align__(16) __nv_bfloat16 g_kl[(size_t)BH_ * L_ * D_];
__device__ __align__(16) __nv_bfloat16 g_vh[(size_t)BH_ * L_ * D_];
__device__ __align__(16) __nv_bfloat16 g_vl[(size_t)BH_ * L_ * D_];
__device__ __align__(16) __nv_bfloat16 g_Qlh[BH_ * M_ * D_];
__device__ __align__(16) __nv_bfloat16 g_Qll[BH_ * M_ * D_];
__device__ __align__(16) __nv_bfloat16 g_Klh[BH_ * M_ * D_];
__device__ __align__(16) __nv_bfloat16 g_Kll[BH_ * M_ * D_];
__device__ __align__(16) __nv_bfloat16 g_k1h[(size_t)BH_ * L_ * M_]; // kernel_1 split
__device__ __align__(16) __nv_bfloat16 g_k1l[(size_t)BH_ * L_ * M_];
__device__ __align__(16) __nv_bfloat16 g_s3h[(size_t)BH_ * M_ * L_]; // softmaxed k3 split
__device__ __align__(16) __nv_bfloat16 g_s3l[(size_t)BH_ * M_ * L_];
__device__ __align__(16) __nv_bfloat16 g_y2th[BH_ * D_ * M_];        // y2^T split [bh][d][m]
__device__ __align__(16) __nv_bfloat16 g_y2tl[BH_ * D_ * M_];

// =====================================================================
// PTX helpers (baseline set only: mma.sync / ldmatrix / cp.async)
// =====================================================================
__device__ __forceinline__ uint32_t smem_to_u32(const void* p) {
    uint32_t a;
    asm("{ .reg .u64 t; cvta.to.shared.u64 t, %1; cvt.u32.u64 %0, t; }" : "=r"(a) : "l"(p));
    return a;
}
__device__ __forceinline__ void ldsm4(uint32_t* r, uint32_t addr) {
    asm volatile("ldmatrix.sync.aligned.m8n8.x4.shared.b16 {%0,%1,%2,%3}, [%4];"
        : "=r"(r[0]), "=r"(r[1]), "=r"(r[2]), "=r"(r[3]) : "r"(addr));
}
__device__ __forceinline__ void ldsm4t(uint32_t* r, uint32_t addr) {
    asm volatile("ldmatrix.sync.aligned.m8n8.x4.trans.shared.b16 {%0,%1,%2,%3}, [%4];"
        : "=r"(r[0]), "=r"(r[1]), "=r"(r[2]), "=r"(r[3]) : "r"(addr));
}
__device__ __forceinline__ void mma16816(float* d, const uint32_t* a, const uint32_t* b) {
    asm volatile("mma.sync.aligned.m16n8k16.row.col.f32.bf16.bf16.f32 "
        "{%0,%1,%2,%3}, {%4,%5,%6,%7}, {%8,%9}, {%0,%1,%2,%3};"
        : "+f"(d[0]), "+f"(d[1]), "+f"(d[2]), "+f"(d[3])
        : "r"(a[0]), "r"(a[1]), "r"(a[2]), "r"(a[3]), "r"(b[0]), "r"(b[1]));
}
#define CP_ASYNC16(dst, src) \
    asm volatile("cp.async.cg.shared.global [%0], [%1], 16;" :: "r"(dst), "l"(src))
#define CP_COMMIT()  asm volatile("cp.async.commit_group;" ::: "memory")
#define CP_WAIT(n)   asm volatile("cp.async.wait_group %0;" :: "n"(n) : "memory")

__device__ __forceinline__ void split_bf16(float v, __nv_bfloat16& h, __nv_bfloat16& l) {
    h = __float2bfloat16(v);
    l = __float2bfloat16(v - __bfloat162float(h));
}

// =====================================================================
// conversion kernels (fp32 -> bf16 hi/lo split)
// =====================================================================
__global__ void conv_act3_kernel(const float* __restrict__ s0,
                                 const float* __restrict__ s1,
                                 const float* __restrict__ s2)
{
    int z = blockIdx.y;
    const float* src = (z == 0) ? s0 : ((z == 1) ? s1 : s2);
    size_t i4 = (size_t)blockIdx.x * 256 + threadIdx.x;
    float4 v = *(const float4*)&src[i4 * 4];
    __nv_bfloat16 h[4], l[4];
    float a[4] = {v.x, v.y, v.z, v.w};
    #pragma unroll
    for (int i = 0; i < 4; i++) split_bf16(a[i], h[i], l[i]);
    size_t o = (size_t)z * NTOK_ * DM_ + i4 * 4;
    *(uint2*)&g_ah[o] = *(uint2*)h;
    *(uint2*)&g_al[o] = *(uint2*)l;
}

__global__ void conv_wt_kernel(const float* __restrict__ W, int slot)
{
    __shared__ float t[32][33];
    int x = blockIdx.x * 32 + threadIdx.x;
    int y = blockIdx.y * 32 + threadIdx.y;
    #pragma unroll
    for (int j = 0; j < 32; j += 8) t[threadIdx.y + j][threadIdx.x] = W[(size_t)(y + j) * 1024 + x];
    __syncthreads();
    int xo = blockIdx.y * 32 + threadIdx.x;
    int yo = blockIdx.x * 32 + threadIdx.y;
    size_t base = (size_t)slot * DM_ * DM_;
    #pragma unroll
    for (int j = 0; j < 32; j += 8) {
        float v = t[threadIdx.x][threadIdx.y + j];
        __nv_bfloat16 h, l; split_bf16(v, h, l);
        g_wh[base + (size_t)(yo + j) * 1024 + xo] = h;
        g_wl[base + (size_t)(yo + j) * 1024 + xo] = l;
    }
}

// =====================================================================
// projection GEMM — BK=16, 4-stage cp.async pipeline, ONE sync per chunk,
// 2 CTAs/SM (smem 98304, regs capped at 128).
// mode = -1: fused QKV (z = blockIdx.z selects slot + destination)
// mode =  3: output projection (slot 0 operands, fp32 out + bias in b0p)
// =====================================================================
#define TS16   6144                 // one operand array: 128 rows x 48 B
#define STG16  (4 * TS16)           // 24576 per stage
#define GSM    (4 * STG16)          // 98304 total

__global__ __launch_bounds__(256, 2) void gemm_mma_kernel(
    const float* __restrict__ b0p, const float* __restrict__ b1p,
    const float* __restrict__ b2p, float* __restrict__ outp, int mode)
{
    const uint32_t sbase = smem_to_u32(dynsm);
    const int z = (mode == 3) ? 0 : blockIdx.z;
    const float* bias = (mode == 3) ? b0p : ((z == 0) ? b0p : ((z == 1) ? b1p : b2p));
    const __nv_bfloat16* Ah = g_ah + (size_t)z * NTOK_ * DM_;
    const __nv_bfloat16* Al = g_al + (size_t)z * NTOK_ * DM_;
    const __nv_bfloat16* Wh = g_wh + (size_t)z * DM_ * DM_;
    const __nv_bfloat16* Wl = g_wl + (size_t)z * DM_ * DM_;

    const int tid  = threadIdx.x;
    const int lane = tid & 31;
    const int w    = tid >> 5;
    const int wm   = w >> 2;
    const int wn   = w & 3;
    const int n0 = blockIdx.x * 128;
    const int m0 = blockIdx.y * 128;

    float acc[4][4][4];
    #pragma unroll
    for (int i = 0; i < 4; i++)
        #pragma unroll
        for (int j = 0; j < 4; j++)
            #pragma unroll
            for (int t = 0; t < 4; t++) acc[i][j][t] = 0.f;

    auto load_chunk = [&](int c, int buf) {
        const int k0 = c * 16;
        const uint32_t sb = sbase + buf * STG16;
        #pragma unroll
        for (int i = 0; i < 4; i++) {
            int q = tid + i * 256;            // 0..1023
            int arr = q >> 8;
            int r   = (q >> 1) & 127;
            int hf  = q & 1;
            uint32_t dst = sb + arr * TS16 + r * 48 + hf * 16;
            const __nv_bfloat16* src;
            if      (arr == 0) src = &Ah[(size_t)(m0 + r) * 1024 + k0 + hf * 8];
            else if (arr == 1) src = &Al[(size_t)(m0 + r) * 1024 + k0 + hf * 8];
            else if (arr == 2) src = &Wh[(size_t)(n0 + r) * 1024 + k0 + hf * 8];
            else               src = &Wl[(size_t)(n0 + r) * 1024 + k0 + hf * 8];
            CP_ASYNC16(dst, src);
        }
        CP_COMMIT();
    };

    auto compute_chunk = [&](int buf) {
        const uint32_t S = sbase + buf * STG16;
        // B fragments, both terms (16 regs)
        uint32_t bf[2][2][4];
        #pragma unroll
        for (int term = 0; term < 2; term++)
            #pragma unroll
            for (int np = 0; np < 2; np++) {
                uint32_t nrow = (uint32_t)(wn * 32 + np * 16 + ((lane >> 4) * 8) + (lane & 7));
                uint32_t addr = S + 2 * TS16 + term * TS16 + nrow * 48
                    + (uint32_t)(((lane >> 3) & 1) * 16);
                ldsm4(bf[term][np], addr);
            }
        // A hi fragments (16 regs), then hi*Bh + hi*Bl
        uint32_t af[4][4];
        #pragma unroll
        for (int mt = 0; mt < 4; mt++) {
            uint32_t addr = S + (uint32_t)((wm * 64 + mt * 16 + (lane & 15)) * 48)
                + (uint32_t)((lane >> 4) * 16);
            ldsm4(af[mt], addr);
        }
        #pragma unroll
        for (int mt = 0; mt < 4; mt++)
            #pragma unroll
            for (int nt = 0; nt < 4; nt++) {
                float* d = acc[mt][nt];
                mma16816(d, af[mt], &bf[0][nt >> 1][(nt & 1) * 2]);
                mma16816(d, af[mt], &bf[1][nt >> 1][(nt & 1) * 2]);
            }
        // A lo fragments (reuse regs), lo*Bh
        #pragma unroll
        for (int mt = 0; mt < 4; mt++) {
            uint32_t addr = S + TS16 + (uint32_t)((wm * 64 + mt * 16 + (lane & 15)) * 48)
                + (uint32_t)((lane >> 4) * 16);
            ldsm4(af[mt], addr);
        }
        #pragma unroll
        for (int mt = 0; mt < 4; mt++)
            #pragma unroll
            for (int nt = 0; nt < 4; nt++)
                mma16816(acc[mt][nt], af[mt], &bf[0][nt >> 1][(nt & 1) * 2]);
    };

    // 4-stage pipeline: wait(2) -> sync -> load(c+3) -> compute(c)
    load_chunk(0, 0);
    load_chunk(1, 1);
    load_chunk(2, 2);
    #pragma unroll 1
    for (int c = 0; c < 64; c++) {
        if      (c < 62) { CP_WAIT(2); }
        else if (c == 62) { CP_WAIT(1); }
        else              { CP_WAIT(0); }
        __syncthreads();
        if (c + 3 < 64) load_chunk(c + 3, (c + 3) & 3);
        compute_chunk(c & 3);
    }

    #pragma unroll
    for (int mt = 0; mt < 4; mt++) {
        #pragma unroll
        for (int nt = 0; nt < 4; nt++) {
            int c = n0 + wn * 32 + nt * 8 + (lane & 3) * 2;
            float b0 = bias[c], b1 = bias[c + 1];
            #pragma unroll
            for (int half = 0; half < 2; half++) {
                int r = m0 + wm * 64 + mt * 16 + (lane >> 2) + half * 8;
                float vx = acc[mt][nt][half * 2 + 0] + b0;
                float vy = acc[mt][nt][half * 2 + 1] + b1;
                if (mode == 3) {
                    float2 t = {vx, vy};
                    *(float2*)&outp[(size_t)r * 1024 + c] = t;
                } else {
                    __nv_bfloat16* dh = (z == 0) ? g_qh : ((z == 1) ? g_kh : g_vh);
                    __nv_bfloat16* dl = (z == 0) ? g_ql : ((z == 1) ? g_kl : g_vl);
                    int b = r >> 12, l = r & 4095;
                    int h = c >> 6, d = c & 63;
                    size_t o = (((size_t)(b * 16 + h) * 4096) + l) * 64 + d;
                    __nv_bfloat16 hp[2], lp[2];
                    split_bf16(vx, hp[0], lp[0]);
                    split_bf16(vy, hp[1], lp[1]);
                    *(uint32_t*)&dh[o] = *(uint32_t*)hp;
                    *(uint32_t*)&dl[o] = *(uint32_t*)lp;
                }
            }
        }
    }
}

// =====================================================================
// landmark pooling from split q/k; writes fp32 + split landmarks
// =====================================================================
__global__ void pool_kernel()
{
    int idx = blockIdx.x * blockDim.x + threadIdx.x;   // BH*M*D
    int d  = idx & 63;
    int m  = (idx >> 6) & 127;
    int bh = idx >> 13;
    size_t base = ((size_t)bh * L_ + m * SEG_) * D_ + d;
    float sq = 0.f, sk = 0.f;
    #pragma unroll
    for (int s = 0; s < SEG_; s++) {
        sq += __bfloat162float(g_qh[base + s * D_]) + __bfloat162float(g_ql[base + s * D_]);
        sk += __bfloat162float(g_kh[base + s * D_]) + __bfloat162float(g_kl[base + s * D_]);
    }
    float mq = sq * (1.f / SEG_), mk = sk * (1.f / SEG_);
    g_Ql[idx] = mq; g_Kl[idx] = mk;
    __nv_bfloat16 h, l;
    split_bf16(mq, h, l); g_Qlh[idx] = h; g_Qll[idx] = l;
    split_bf16(mk, h, l); g_Klh[idx] = h; g_Kll[idx] = l;
}

// =====================================================================
// k1: C[128 tok][128 lm] = q_blk @ Kl^T (split mma) + fused softmax -> split bf16
// smem: Ah 0 | Al 18432 | Bh 36864 | Bl 55296  (pitch 144 B); dyn smem 73728
// =====================================================================
__global__ __launch_bounds__(256) void k1_mma_kernel()
{
    char* sm = dynsm;
    const uint32_t sb = smem_to_u32(sm);
    int bh = blockIdx.y, l0 = blockIdx.x * 128, tid = threadIdx.x;
    int lane = tid & 31, w = tid >> 5;

    {
        const __nv_bfloat16* qh = g_qh + ((size_t)bh * L_ + l0) * D_;
        const __nv_bfloat16* ql = g_ql + ((size_t)bh * L_ + l0) * D_;
        const __nv_bfloat16* kh = g_Klh + bh * (M_ * D_);
        const __nv_bfloat16* kl = g_Kll + bh * (M_ * D_);
        #pragma unroll
        for (int i = 0; i < 4; i++) {
            int q = tid + i * 256;              // 0..1023
            int row = q >> 3, c8 = q & 7;
            uint32_t so = (uint32_t)(row * 144 + c8 * 16);
            size_t go = (size_t)row * 64 + c8 * 8;
            *(uint4*)(sm + 0     + so) = *(const uint4*)&qh[go];
            *(uint4*)(sm + 18432 + so) = *(const uint4*)&ql[go];
            *(uint4*)(sm + 36864 + so) = *(const uint4*)&kh[go];
            *(uint4*)(sm + 55296 + so) = *(const uint4*)&kl[go];
        }
    }
    __syncthreads();

    int wm = w >> 2, wn = w & 3;
    float acc[4][4][4];
    #pragma unroll
    for (int i = 0; i < 4; i++)
        #pragma unroll
        for (int j = 0; j < 4; j++)
            #pragma unroll
            for (int t = 0; t < 4; t++) acc[i][j][t] = 0.f;

    #pragma unroll
    for (int k16 = 0; k16 < 4; k16++) {
        uint32_t af[2][4][4];
        #pragma unroll
        for (int term = 0; term < 2; term++)
            #pragma unroll
            for (int mt = 0; mt < 4; mt++) {
                uint32_t addr = sb + term * 18432
                    + (uint32_t)((wm * 64 + mt * 16 + (lane & 15)) * 144)
                    + (uint32_t)(k16 * 32) + (uint32_t)((lane >> 4) * 16);
                ldsm4(af[term][mt], addr);
            }
        uint32_t bf[2][2][4];
        #pragma unroll
        for (int term = 0; term < 2; term++)
            #pragma unroll
            for (int np = 0; np < 2; np++) {
                uint32_t nrow = (uint32_t)(wn * 32 + np * 16 + ((lane >> 4) * 8) + (lane & 7));
                uint32_t addr = sb + 36864 + term * 18432 + nrow * 144
                    + (uint32_t)(k16 * 32) + (uint32_t)(((lane >> 3) & 1) * 16);
                ldsm4(bf[term][np], addr);
            }
        #pragma unroll
        for (int mt = 0; mt < 4; mt++)
            #pragma unroll
            for (int nt = 0; nt < 4; nt++) {
                float* d = acc[mt][nt];
                const uint32_t* bh_ = &bf[0][nt >> 1][(nt & 1) * 2];
                const uint32_t* bl_ = &bf[1][nt >> 1][(nt & 1) * 2];
                mma16816(d, af[0][mt], bh_);
                mma16816(d, af[0][mt], bl_);
                mma16816(d, af[1][mt], bh_);
            }
    }
    __syncthreads();

    float* S = (float*)sm;
    #pragma unroll
    for (int mt = 0; mt < 4; mt++)
        #pragma unroll
        for (int nt = 0; nt < 4; nt++)
            #pragma unroll
            for (int half = 0; half < 2; half++) {
                int row = wm * 64 + mt * 16 + (lane >> 2) + half * 8;
                int col = wn * 32 + nt * 8 + (lane & 3) * 2;
                S[row * 128 + col]     = acc[mt][nt][half * 2 + 0];
                S[row * 128 + col + 1] = acc[mt][nt][half * 2 + 1];
            }
    __syncthreads();

    for (int rr = 0; rr < 16; rr++) {
        int row = w * 16 + rr;
        float x0 = S[row * 128 + lane],      x1 = S[row * 128 + lane + 32];
        float x2 = S[row * 128 + lane + 64], x3 = S[row * 128 + lane + 96];
        float mx = fmaxf(fmaxf(x0, x1), fmaxf(x2, x3));
        #pragma unroll
        for (int o = 16; o; o >>= 1) mx = fmaxf(mx, __shfl_xor_sync(0xffffffffu, mx, o));
        float e0 = __expf(x0 - mx), e1 = __expf(x1 - mx);
        float e2 = __expf(x2 - mx), e3 = __expf(x3 - mx);
        float s = e0 + e1 + e2 + e3;
        #pragma unroll
        for (int o = 16; o; o >>= 1) s += __shfl_xor_sync(0xffffffffu, s, o);
        float inv = 1.f / s;
        size_t ob = ((size_t)bh * L_ + l0 + row) * 128;
        float vv[4] = {e0 * inv, e1 * inv, e2 * inv, e3 * inv};
        #pragma unroll
        for (int j = 0; j < 4; j++) {
            __nv_bfloat16 h, l; split_bf16(vv[j], h, l);
            g_k1h[ob + lane + 32 * j] = h;
            g_k1l[ob + lane + 32 * j] = l;
        }
    }
}

// =====================================================================
// k3 scores: C[m=128][l=128 blk] = Ql @ k_blk^T (split mma) -> raw fp32 g_k3
// dyn smem 73728
// =====================================================================
__global__ __launch_bounds__(256) void k3score_mma_kernel()
{
    char* sm = dynsm;
    const uint32_t sb = smem_to_u32(sm);
    int bh = blockIdx.y, l0 = blockIdx.x * 128, tid = threadIdx.x;
    int lane = tid & 31, w = tid >> 5;

    {
        const __nv_bfloat16* ah = g_Qlh + bh * (M_ * D_);
        const __nv_bfloat16* al = g_Qll + bh * (M_ * D_);
        const __nv_bfloat16* bhp = g_kh + ((size_t)bh * L_ + l0) * D_;
        const __nv_bfloat16* blp = g_kl + ((size_t)bh * L_ + l0) * D_;
        #pragma unroll
        for (int i = 0; i < 4; i++) {
            int q = tid + i * 256;
            int row = q >> 3, c8 = q & 7;
            uint32_t so = (uint32_t)(row * 144 + c8 * 16);
            size_t go = (size_t)row * 64 + c8 * 8;
            *(uint4*)(sm + 0     + so) = *(const uint4*)&ah[go];
            *(uint4*)(sm + 18432 + so) = *(const uint4*)&al[go];
            *(uint4*)(sm + 36864 + so) = *(const uint4*)&bhp[go];
            *(uint4*)(sm + 55296 + so) = *(const uint4*)&blp[go];
        }
    }
    __syncthreads();

    int wm = w >> 2, wn = w & 3;
    float acc[4][4][4];
    #pragma unroll
    for (int i = 0; i < 4; i++)
        #pragma unroll
        for (int j = 0; j < 4; j++)
            #pragma unroll
            for (int t = 0; t < 4; t++) acc[i][j][t] = 0.f;

    #pragma unroll
    for (int k16 = 0; k16 < 4; k16++) {
        uint32_t af[2][4][4];
        #pragma unroll
        for (int term = 0; term < 2; term++)
            #pragma unroll
            for (int mt = 0; mt < 4; mt++) {
                uint32_t addr = sb + term * 18432
                    + (uint32_t)((wm * 64 + mt * 16 + (lane & 15)) * 144)
                    + (uint32_t)(k16 * 32) + (uint32_t)((lane >> 4) * 16);
                ldsm4(af[term][mt], addr);
            }
        uint32_t bf[2][2][4];
        #pragma unroll
        for (int term = 0; term < 2; term++)
            #pragma unroll
            for (int np = 0; np < 2; np++) {
                uint32_t nrow = (uint32_t)(wn * 32 + np * 16 + ((lane >> 4) * 8) + (lane & 7));
                uint32_t addr = sb + 36864 + term * 18432 + nrow * 144
                    + (uint32_t)(k16 * 32) + (uint32_t)(((lane >> 3) & 1) * 16);
                ldsm4(bf[term][np], addr);
            }
        #pragma unroll
        for (int mt = 0; mt < 4; mt++)
            #pragma unroll
            for (int nt = 0; nt < 4; nt++) {
                float* d = acc[mt][nt];
                const uint32_t* bh_ = &bf[0][nt >> 1][(nt & 1) * 2];
                const uint32_t* bl_ = &bf[1][nt >> 1][(nt & 1) * 2];
                mma16816(d, af[0][mt], bh_);
                mma16816(d, af[0][mt], bl_);
                mma16816(d, af[1][mt], bh_);
            }
    }

    float* o = g_k3 + (size_t)bh * M_ * L_;
    #pragma unroll
    for (int mt = 0; mt < 4; mt++)
        #pragma unroll
        for (int nt = 0; nt < 4; nt++)
            #pragma unroll
            for (int half = 0; half < 2; half++) {
                int m_r = wm * 64 + mt * 16 + (lane >> 2) + half * 8;
                int l_c = l0 + wn * 32 + nt * 8 + (lane & 3) * 2;
                float2 t = {acc[mt][nt][half * 2 + 0], acc[mt][nt][half * 2 + 1]};
                *(float2*)&o[(size_t)m_r * L_ + l_c] = t;
            }
}

// =====================================================================
// row softmax over 4096; reads fp32 g_k3, writes split bf16 g_s3
// =====================================================================
__global__ __launch_bounds__(256) void softmax4096_kernel()
{
    size_t row = blockIdx.x;
    const float* p = g_k3 + row * 4096;
    int tid = threadIdx.x;
    float v[16];
    float mx = -1e30f;
    #pragma unroll
    for (int i = 0; i < 4; i++) {
        float4 t = *(const float4*)&p[i * 1024 + tid * 4];
        v[i * 4 + 0] = t.x; v[i * 4 + 1] = t.y; v[i * 4 + 2] = t.z; v[i * 4 + 3] = t.w;
        mx = fmaxf(mx, fmaxf(fmaxf(t.x, t.y), fmaxf(t.z, t.w)));
    }
    __shared__ float smx[8], ssm[8], sres;
    #pragma unroll
    for (int o = 16; o; o >>= 1) mx = fmaxf(mx, __shfl_xor_sync(0xffffffffu, mx, o));
    if ((tid & 31) == 0) smx[tid >> 5] = mx;
    __syncthreads();
    if (tid == 0) {
        float m = smx[0];
        #pragma unroll
        for (int i = 1; i < 8; i++) m = fmaxf(m, smx[i]);
        sres = m;
    }
    __syncthreads();
    float MX = sres;
    float s = 0.f;
    #pragma unroll
    for (int i = 0; i < 16; i++) { v[i] = __expf(v[i] - MX); s += v[i]; }
    #pragma unroll
    for (int o = 16; o; o >>= 1) s += __shfl_xor_sync(0xffffffffu, s, o);
    if ((tid & 31) == 0) ssm[tid >> 5] = s;
    __syncthreads();
    if (tid == 0) {
        float t = 0.f;
        #pragma unroll
        for (int i = 0; i < 8; i++) t += ssm[i];
        sres = 1.f / t;
    }
    __syncthreads();
    float inv = sres;
    #pragma unroll
    for (int i = 0; i < 4; i++) {
        __nv_bfloat16 hh[4], ll[4];
        #pragma unroll
        for (int t = 0; t < 4; t++) split_bf16(v[i * 4 + t] * inv, hh[t], ll[t]);
        *(uint2*)&g_s3h[row * 4096 + i * 1024 + tid * 4] = *(uint2*)hh;
        *(uint2*)&g_s3l[row * 4096 + i * 1024 + tid * 4] = *(uint2*)ll;
    }
}

// =====================================================================
// kernel_2 = softmax(Q_l @ K_l^T) fused (fp32, tiny). block per head.
// =====================================================================
__global__ __launch_bounds__(256) void k2_kernel()
{
    float* sm = (float*)dynsm;
    float* Qlt = sm;
    float* Klt = sm + 8192;
    float* S   = sm + 16384;
    int bh = blockIdx.x, tid = threadIdx.x;

    const float* Ql = g_Ql + bh * 8192;
    const float* Kl = g_Kl + bh * 8192;
    #pragma unroll
    for (int i = 0; i < 8; i++) {
        int f = i * 1024 + tid * 4; int m = f >> 6, d0 = f & 63;
        float4 tq = *(const float4*)&Ql[f];
        float4 tk = *(const float4*)&Kl[f];
        Qlt[(d0 + 0) * 128 + m] = tq.x; Qlt[(d0 + 1) * 128 + m] = tq.y;
        Qlt[(d0 + 2) * 128 + m] = tq.z; Qlt[(d0 + 3) * 128 + m] = tq.w;
        Klt[(d0 + 0) * 128 + m] = tk.x; Klt[(d0 + 1) * 128 + m] = tk.y;
        Klt[(d0 + 2) * 128 + m] = tk.z; Klt[(d0 + 3) * 128 + m] = tk.w;
    }
    __syncthreads();

    int tm = tid >> 4, tn = tid & 15;
    float acc[8][8] = {};
    for (int d = 0; d < 64; d++) {
        float4 a0 = *(const float4*)&Qlt[d * 128 + tm * 8];
        float4 a1 = *(const float4*)&Qlt[d * 128 + tm * 8 + 4];
        float4 b0 = *(const float4*)&Klt[d * 128 + tn * 8];
        float4 b1 = *(const float4*)&Klt[d * 128 + tn * 8 + 4];
        float av[8] = {a0.x, a0.y, a0.z, a0.w, a1.x, a1.y, a1.z, a1.w};
        float bv[8] = {b0.x, b0.y, b0.z, b0.w, b1.x, b1.y, b1.z, b1.w};
        #pragma unroll
        for (int i = 0; i < 8; i++)
            #pragma unroll
            for (int j = 0; j < 8; j++) acc[i][j] += av[i] * bv[j];
    }
    #pragma unroll
    for (int i = 0; i < 8; i++)
        #pragma unroll
        for (int j = 0; j < 8; j++) S[(tm * 8 + i) * 128 + tn * 8 + j] = acc[i][j];
    __syncthreads();

    int lane = tid & 31, w = tid >> 5;
    for (int rr = 0; rr < 16; rr++) {
        int row = w * 16 + rr;
        float x0 = S[row * 128 + lane],      x1 = S[row * 128 + lane + 32];
        float x2 = S[row * 128 + lane + 64], x3 = S[row * 128 + lane + 96];
        float mx = fmaxf(fmaxf(x0, x1), fmaxf(x2, x3));
        #pragma unroll
        for (int o = 16; o; o >>= 1) mx = fmaxf(mx, __shfl_xor_sync(0xffffffffu, mx, o));
        float e0 = __expf(x0 - mx), e1 = __expf(x1 - mx);
        float e2 = __expf(x2 - mx), e3 = __expf(x3 - mx);
        float s = e0 + e1 + e2 + e3;
        #pragma unroll
        for (int o = 16; o; o >>= 1) s += __shfl_xor_sync(0xffffffffu, s, o);
        float inv = 1.f / s;
        float* o = g_k2 + bh * 16384 + row * 128;
        o[lane] = e0 * inv; o[lane + 32] = e1 * inv; o[lane + 64] = e2 * inv; o[lane + 96] = e3 * inv;
    }
}

// =====================================================================
// V0 = K^T / max(colsum(K))
// =====================================================================
__global__ __launch_bounds__(256) void vinit_kernel()
{
    int bh = blockIdx.x, tid = threadIdx.x;
    const float* K = g_k2 + bh * 16384;
    __shared__ float cs[128];
    __shared__ float sscale;
    if (tid < 128) {
        float s = 0.f;
        for (int r = 0; r < 128; r++) s += K[r * 128 + tid];
        cs[tid] = s;
    }
    __syncthreads();
    if (tid == 0) {
        float m = cs[0];
        for (int i = 1; i < 128; i++) m = fmaxf(m, cs[i]);
        sscale = 1.f / m;
    }
    __syncthreads();
    float scale = sscale;
    for (int f = tid; f < 16384; f += 256) {
        int i = f >> 7, j = f & 127;
        g_Va[bh * 16384 + f] = scale * K[j * 128 + i];
    }
}

// =====================================================================
// batched 128x128 bmm for Newton-Schulz (fp32)
// =====================================================================
__device__ __forceinline__ float* bufsel(int s)
{
    switch (s) {
        case 0: return g_k2; case 1: return g_P; case 2: return g_M1;
        case 3: return g_M2; case 4: return g_Va; default: return g_Vb;
    }
}

__global__ __launch_bounds__(256) void bmm_kernel(int as, int bs, int cs2, int os,
                                                  float alpha, float beta)
{
    float* sm = (float*)dynsm;
    float* Bs = sm;
    float* At = sm + 16384;
    int bh = blockIdx.y, r0 = blockIdx.x * 32, tid = threadIdx.x;
    const float* A  = bufsel(as)  + bh * 16384;
    const float* Bm = bufsel(bs)  + bh * 16384;
    const float* C  = bufsel(cs2) + bh * 16384;
    float* O        = bufsel(os)  + bh * 16384;

    #pragma unroll
    for (int i = 0; i < 16; i++) {
        int f = i * 1024 + tid * 4;
        *(float4*)&Bs[f] = *(const float4*)&Bm[f];
    }
    #pragma unroll
    for (int i = 0; i < 4; i++) {
        int f = i * 1024 + tid * 4; int r = f >> 7, k0 = f & 127;
        float4 t = *(const float4*)&A[(r0 + r) * 128 + k0];
        At[(k0 + 0) * 32 + r] = t.x; At[(k0 + 1) * 32 + r] = t.y;
        At[(k0 + 2) * 32 + r] = t.z; At[(k0 + 3) * 32 + r] = t.w;
    }
    __syncthreads();

    int rb = (tid >> 5) * 4, cb = (tid & 31) * 4;
    float acc[4][4] = {};
    for (int k = 0; k < 128; k++) {
        float a0 = At[k * 32 + rb + 0], a1 = At[k * 32 + rb + 1];
        float a2 = At[k * 32 + rb + 2], a3 = At[k * 32 + rb + 3];
        float4 b = *(const float4*)&Bs[k * 128 + cb];
        acc[0][0] += a0 * b.x; acc[0][1] += a0 * b.y; acc[0][2] += a0 * b.z; acc[0][3] += a0 * b.w;
        acc[1][0] += a1 * b.x; acc[1][1] += a1 * b.y; acc[1][2] += a1 * b.z; acc[1][3] += a1 * b.w;
        acc[2][0] += a2 * b.x; acc[2][1] += a2 * b.y; acc[2][2] += a2 * b.z; acc[2][3] += a2 * b.w;
        acc[3][0] += a3 * b.x; acc[3][1] += a3 * b.y; acc[3][2] += a3 * b.z; acc[3][3] += a3 * b.w;
    }
    #pragma unroll
    for (int i = 0; i < 4; i++)
        #pragma unroll
        for (int j = 0; j < 4; j++) {
            int idx = (r0 + rb + i) * 128 + cb + j;
            O[idx] = alpha * acc[i][j] + beta * C[idx];
        }
}

// =====================================================================
// k3v: partial C[m=128][d=64] = softmax(k3)_split @ v_split (mma, split-K 4)
// 2-stage pipeline (round-5 config). dyn smem 110592
// =====================================================================
#define KV_STG 55296

__global__ __launch_bounds__(256) void k3v_mma_kernel()
{
    char* sm = dynsm;
    const uint32_t sb = smem_to_u32(sm);
    int s = blockIdx.x, bh = blockIdx.y, tid = threadIdx.x;
    int lane = tid & 31, w = tid >> 5;
    int wm = w >> 1, wn = w & 1;
    const size_t abase = (size_t)bh * M_ * L_;
    const size_t vbase = (size_t)bh * L_ * D_;

    float acc[2][4][4];
    #pragma unroll
    for (int i = 0; i < 2; i++)
        #pragma unroll
        for (int j = 0; j < 4; j++)
            #pragma unroll
            for (int t = 0; t < 4; t++) acc[i][j][t] = 0.f;

    auto load = [&](int ck, int buf) {
        int k0 = s * 1024 + ck * 64;
        uint32_t S = sb + buf * KV_STG;
        #pragma unroll
        for (int i = 0; i < 8; i++) {               // A: scores split
            int q = tid + i * 256;
            int arr = q >> 10, row = (q >> 3) & 127, c8 = q & 7;
            uint32_t dst = S + arr * 18432 + (uint32_t)(row * 144 + c8 * 16);
            const __nv_bfloat16* src = (arr ? g_s3l : g_s3h) + abase + (size_t)row * L_ + k0 + c8 * 8;
            CP_ASYNC16(dst, src);
        }
        #pragma unroll
        for (int i = 0; i < 4; i++) {               // B: v split
            int q = tid + i * 256;
            int arr = q >> 9, row = (q >> 3) & 63, c8 = q & 7;
            uint32_t dst = S + 36864 + arr * 9216 + (uint32_t)(row * 144 + c8 * 16);
            const __nv_bfloat16* src = (arr ? g_vl : g_vh) + vbase + (size_t)(k0 + row) * D_ + c8 * 8;
            CP_ASYNC16(dst, src);
        }
        CP_COMMIT();
    };

    auto compute = [&](int buf) {
        uint32_t S = sb + buf * KV_STG;
        #pragma unroll
        for (int k16 = 0; k16 < 4; k16++) {
            uint32_t af[2][2][4];
            #pragma unroll
            for (int term = 0; term < 2; term++)
                #pragma unroll
                for (int mt = 0; mt < 2; mt++) {
                    uint32_t addr = S + term * 18432
                        + (uint32_t)((wm * 32 + mt * 16 + (lane & 15)) * 144)
                        + (uint32_t)(k16 * 32) + (uint32_t)((lane >> 4) * 16);
                    ldsm4(af[term][mt], addr);
                }
            uint32_t bf[2][2][4];
            #pragma unroll
            for (int term = 0; term < 2; term++)
                #pragma unroll
                for (int np = 0; np < 2; np++) {
                    uint32_t addr = S + 36864 + term * 9216
                        + (uint32_t)((k16 * 16 + (lane & 15)) * 144)
                        + (uint32_t)((wn * 32 + np * 16 + (lane >> 4) * 8) * 2);
                    ldsm4t(bf[term][np], addr);
                }
            #pragma unroll
            for (int mt = 0; mt < 2; mt++)
                #pragma unroll
                for (int nt = 0; nt < 4; nt++) {
                    float* d = acc[mt][nt];
                    const uint32_t* bh_ = &bf[0][nt >> 1][(nt & 1) * 2];
                    const uint32_t* bl_ = &bf[1][nt >> 1][(nt & 1) * 2];
                    mma16816(d, af[0][mt], bh_);
                    mma16816(d, af[0][mt], bl_);
                    mma16816(d, af[1][mt], bh_);
                }
        }
    };

    load(0, 0);
    #pragma unroll 1
    for (int ck = 0; ck < 16; ck++) {
        if (ck + 1 < 16) {
            load(ck + 1, (ck + 1) & 1);
            CP_WAIT(1);
        } else {
            CP_WAIT(0);
        }
        __syncthreads();
        compute(ck & 1);
        __syncthreads();
    }

    #pragma unroll
    for (int mt = 0; mt < 2; mt++)
        #pragma unroll
        for (int nt = 0; nt < 4; nt++)
            #pragma unroll
            for (int half = 0; half < 2; half++) {
                int m_r = wm * 32 + mt * 16 + (lane >> 2) + half * 8;
                int d_c = wn * 32 + nt * 8 + (lane & 3) * 2;
                float2 t = {acc[mt][nt][half * 2 + 0], acc[mt][nt][half * 2 + 1]};
                *(float2*)&g_k3v_part[((size_t)(s * 64 + bh) * 128 + m_r) * 64 + d_c] = t;
            }
}

__global__ void k3v_reduce_kernel()
{
    int idx = blockIdx.x * blockDim.x + threadIdx.x;  // 524288
    float s = 0.f;
    #pragma unroll
    for (int p = 0; p < 4; p++) s += g_k3v_part[(size_t)p * 524288 + idx];
    g_k3v[idx] = s;
}

// =====================================================================
// y2 = inv(g_Va) @ k3v per head (fp32); epilogue emits y2^T split bf16
// =====================================================================
__global__ __launch_bounds__(256) void y2_kernel()
{
    float* sm = (float*)dynsm;
    float* At = sm;
    float* Bs = sm + 16384;
    int bh = blockIdx.x, tid = threadIdx.x;
    const float* inv = g_Va + bh * 16384;
    const float* kv  = g_k3v + bh * 8192;

    #pragma unroll
    for (int i = 0; i < 16; i++) {
        int f = i * 1024 + tid * 4; int r = f >> 7, k0 = f & 127;
        float4 t = *(const float4*)&inv[f];
        At[(k0 + 0) * 128 + r] = t.x; At[(k0 + 1) * 128 + r] = t.y;
        At[(k0 + 2) * 128 + r] = t.z; At[(k0 + 3) * 128 + r] = t.w;
    }
    #pragma unroll
    for (int i = 0; i < 8; i++) {
        int f = i * 1024 + tid * 4;
        *(float4*)&Bs[f] = *(const float4*)&kv[f];
    }
    __syncthreads();

    int rt = tid >> 4, ct = tid & 15;
    float acc[8][4] = {};
    for (int k = 0; k < 128; k++) {
        float4 a0 = *(const float4*)&At[k * 128 + rt * 8];
        float4 a1 = *(const float4*)&At[k * 128 + rt * 8 + 4];
        float4 b  = *(const float4*)&Bs[k * 64 + ct * 4];
        float av[8] = {a0.x, a0.y, a0.z, a0.w, a1.x, a1.y, a1.z, a1.w};
        #pragma unroll
        for (int i = 0; i < 8; i++) {
            acc[i][0] += av[i] * b.x; acc[i][1] += av[i] * b.y;
            acc[i][2] += av[i] * b.z; acc[i][3] += av[i] * b.w;
        }
    }
    // transposed split store: y2t[bh][d][m]
    #pragma unroll
    for (int i = 0; i < 8; i++)
        #pragma unroll
        for (int j = 0; j < 4; j++) {
            __nv_bfloat16 h, l; split_bf16(acc[i][j], h, l);
            size_t o = (size_t)bh * 8192 + (ct * 4 + j) * 128 + rt * 8 + i;
            g_y2th[o] = h;
            g_y2tl[o] = l;
        }
}

// =====================================================================
// x1: C[l=128][d=64] = kernel1_split @ y2t_split (mma) -> g_ah/g_al slot 0
// smem: Ah 0 | Al 34816 | Bh 69632 | Bl 87040 ; dyn smem 104448 (pitch 272 B)
// =====================================================================
__global__ __launch_bounds__(256) void x1_mma_kernel()
{
    char* sm = dynsm;
    const uint32_t sb = smem_to_u32(sm);
    int bh = blockIdx.y, l0 = blockIdx.x * 128, tid = threadIdx.x;
    int lane = tid & 31, w = tid >> 5;
    int wm = w >> 1, wn = w & 1;

    {
        const __nv_bfloat16* ah = g_k1h + ((size_t)bh * L_ + l0) * 128;
        const __nv_bfloat16* al = g_k1l + ((size_t)bh * L_ + l0) * 128;
        #pragma unroll
        for (int i = 0; i < 16; i++) {
            int q = tid + i * 256;                 // 0..4095
            int arr = q >> 11, row = (q >> 4) & 127, c16 = q & 15;
            uint32_t so = (uint32_t)(arr * 34816 + row * 272 + c16 * 16);
            const __nv_bfloat16* src = (arr ? al : ah) + (size_t)row * 128 + c16 * 8;
            *(uint4*)(sm + so) = *(const uint4*)src;
        }
        const __nv_bfloat16* bhp = g_y2th + (size_t)bh * 8192;
        const __nv_bfloat16* blp = g_y2tl + (size_t)bh * 8192;
        #pragma unroll
        for (int i = 0; i < 8; i++) {
            int q = tid + i * 256;                 // 0..2047
            int arr = q >> 10, row = (q >> 4) & 63, c16 = q & 15;
            uint32_t so = (uint32_t)(69632 + arr * 17408 + row * 272 + c16 * 16);
            const __nv_bfloat16* src = (arr ? blp : bhp) + (size_t)row * 128 + c16 * 8;
            *(uint4*)(sm + so) = *(const uint4*)src;
        }
    }
    __syncthreads();

    float acc[2][4][4];
    #pragma unroll
    for (int i = 0; i < 2; i++)
        #pragma unroll
        for (int j = 0; j < 4; j++)
            #pragma unroll
            for (int t = 0; t < 4; t++) acc[i][j][t] = 0.f;

    #pragma unroll
    for (int k16 = 0; k16 < 8; k16++) {
        uint32_t af[2][2][4];
        #pragma unroll
        for (int term = 0; term < 2; term++)
            #pragma unroll
            for (int mt = 0; mt < 2; mt++) {
                uint32_t addr = sb + term * 34816
                    + (uint32_t)((wm * 32 + mt * 16 + (lane & 15)) * 272)
                    + (uint32_t)(k16 * 32) + (uint32_t)((lane >> 4) * 16);
                ldsm4(af[term][mt], addr);
            }
        uint32_t bf[2][2][4];
        #pragma unroll
        for (int term = 0; term < 2; term++)
            #pragma unroll
            for (int np = 0; np < 2; np++) {
                uint32_t nrow = (uint32_t)(wn * 32 + np * 16 + ((lane >> 4) * 8) + (lane & 7));
                uint32_t addr = sb + 69632 + term * 17408 + nrow * 272
                    + (uint32_t)(k16 * 32) + (uint32_t)(((lane >> 3) & 1) * 16);
                ldsm4(bf[term][np], addr);
            }
        #pragma unroll
        for (int mt = 0; mt < 2; mt++)
            #pragma unroll
            for (int nt = 0; nt < 4; nt++) {
                float* d = acc[mt][nt];
                const uint32_t* bh_ = &bf[0][nt >> 1][(nt & 1) * 2];
                const uint32_t* bl_ = &bf[1][nt >> 1][(nt & 1) * 2];
                mma16816(d, af[0][mt], bh_);
                mma16816(d, af[0][mt], bl_);
                mma16816(d, af[1][mt], bh_);
            }
    }

    int b = bh >> 4, h = bh & 15;
    #pragma unroll
    for (int mt = 0; mt < 2; mt++)
        #pragma unroll
        for (int nt = 0; nt < 4; nt++)
            #pragma unroll
            for (int half = 0; half < 2; half++) {
                int l = l0 + wm * 32 + mt * 16 + (lane >> 2) + half * 8;
                int d_c = wn * 32 + nt * 8 + (lane & 3) * 2;
                size_t o = ((size_t)(b * L_ + l)) * DM_ + h * 64 + d_c;
                __nv_bfloat16 hp[2], lp[2];
                split_bf16(acc[mt][nt][half * 2 + 0], hp[0], lp[0]);
                split_bf16(acc[mt][nt][half * 2 + 1], hp[1], lp[1]);
                *(uint32_t*)&g_ah[o] = *(uint32_t*)hp;
                *(uint32_t*)&g_al[o] = *(uint32_t*)lp;
            }
}

// =====================================================================
// launch
// =====================================================================
extern "C" void kernel_launch(void* const* d_in, const int* in_sizes, int n_in,
                              void* d_out, int out_size)
{
    const float* queries = (const float*)d_in[0];
    const float* keys    = (const float*)d_in[1];
    const float* values  = (const float*)d_in[2];
    const float* Wq = (const float*)d_in[3];
    const float* bq = (const float*)d_in[4];
    const float* Wk = (const float*)d_in[5];
    const float* bk = (const float*)d_in[6];
    const float* Wv = (const float*)d_in[7];
    const float* bv = (const float*)d_in[8];
    const float* Wo = (const float*)d_in[9];
    const float* bo = (const float*)d_in[10];
    float* out = (float*)d_out;

    cudaFuncSetAttribute(gemm_mma_kernel,    cudaFuncAttributeMaxDynamicSharedMemorySize, GSM);
    cudaFuncSetAttribute(k1_mma_kernel,      cudaFuncAttributeMaxDynamicSharedMemorySize, 73728);
    cudaFuncSetAttribute(k3score_mma_kernel, cudaFuncAttributeMaxDynamicSharedMemorySize, 73728);
    cudaFuncSetAttribute(k3v_mma_kernel,     cudaFuncAttributeMaxDynamicSharedMemorySize, 110592);
    cudaFuncSetAttribute(x1_mma_kernel,      cudaFuncAttributeMaxDynamicSharedMemorySize, 104448);
    cudaFuncSetAttribute(k2_kernel,          cudaFuncAttributeMaxDynamicSharedMemorySize, 131072);
    cudaFuncSetAttribute(bmm_kernel,         cudaFuncAttributeMaxDynamicSharedMemorySize, 81920);
    cudaFuncSetAttribute(y2_kernel,          cudaFuncAttributeMaxDynamicSharedMemorySize, 98304);

    dim3 wt_grid(32, 32), wt_blk(32, 8);

    // weight + activation splits (3 slots), then ONE fused QKV GEMM launch
    conv_wt_kernel<<<wt_grid, wt_blk>>>(Wq, 0);
    conv_wt_kernel<<<wt_grid, wt_blk>>>(Wk, 1);
    conv_wt_kernel<<<wt_grid, wt_blk>>>(Wv, 2);
    conv_act3_kernel<<<dim3(16384, 3), 256>>>(queries, keys, values);
    gemm_mma_kernel<<<dim3(8, 128, 3), 256, GSM>>>(bq, bk, bv, nullptr, -1);

    // landmarks
    pool_kernel<<<2048, 256>>>();

    // kernel_1 (tensor-core, fused softmax)
    k1_mma_kernel<<<dim3(32, 64), 256, 73728>>>();

    // kernel_3 scores (tensor-core) + softmax -> split
    k3score_mma_kernel<<<dim3(32, 64), 256, 73728>>>();
    softmax4096_kernel<<<8192, 256>>>();

    // kernel_2 + Newton-Schulz (fp32)
    k2_kernel<<<64, 256, 131072>>>();
    vinit_kernel<<<64, 256>>>();
    int cur = 4, nxt = 5;
    for (int it = 0; it < 6; it++) {
        bmm_kernel<<<dim3(4, 64), 256, 81920>>>(0,   cur, 0,   1,   1.0f,  0.0f);
        bmm_kernel<<<dim3(4, 64), 256, 81920>>>(1,   1,   1,   2,  -1.0f,  7.0f);
        bmm_kernel<<<dim3(4, 64), 256, 81920>>>(1,   2,   1,   3,  -1.0f, 15.0f);
        bmm_kernel<<<dim3(4, 64), 256, 81920>>>(cur, 3,   cur, nxt, -0.25f, 3.25f);
        int t = cur; cur = nxt; nxt = t;
    }
    // cur == 4 (g_Va) holds the pseudo-inverse

    // kernel_3 @ v (tensor-core, 2-stage split-K 4)
    k3v_mma_kernel<<<dim3(4, 64), 256, 110592>>>();
    k3v_reduce_kernel<<<2048, 256>>>();

    // y2 (fp32 + transposed split epilogue), x1 (tensor-core) -> g_ah/g_al slot 0
    y2_kernel<<<64, 256, 98304>>>();
    x1_mma_kernel<<<dim3(32, 64), 256, 104448>>>();

    // output projection (slot 0)
    conv_wt_kernel<<<wt_grid, wt_blk>>>(Wo, 0);
    gemm_mma_kernel<<<dim3(8, 128, 1), 256, GSM>>>(bo, nullptr, nullptr, out, 3);
}

// round 8
// speedup vs baseline: 1.1266x; 1.1016x over previous
#include <cuda_runtime.h>
#include <cuda_bf16.h>
#include <cstdint>

// ---------------- problem constants ----------------
#define B_    4
#define L_    4096
#define DM_   1024
#define H_    16
#define D_    64
#define M_    128
#define BH_   64          // B*H
#define SEG_  32          // L/M
#define NTOK_ 16384       // B*L

// single dynamic-smem symbol for the whole TU
extern __shared__ char dynsm[];

// ---------------- scratch (device globals; no allocations allowed) ----------------
__device__ float g_Ql[BH_ * M_ * D_];          // fp32 landmarks (for k2)
__device__ float g_Kl[BH_ * M_ * D_];
__device__ float g_k3[(size_t)BH_ * M_ * L_];  // raw scores fp32
__device__ float g_k2[BH_ * M_ * M_];
__device__ float g_P [BH_ * M_ * M_];
__device__ float g_M1[BH_ * M_ * M_];
__device__ float g_M2[BH_ * M_ * M_];
__device__ float g_Va[BH_ * M_ * M_];
__device__ float g_Vb[BH_ * M_ * M_];
__device__ float g_k3v_part[4 * BH_ * M_ * D_];
__device__ float g_k3v[BH_ * M_ * D_];

// bf16 split buffers (A: 3 slots for fused QKV, slot 0 reused by x1/out-proj;
// W: 4 slots, slot 3 = Wo)
__device__ __align__(16) __nv_bfloat16 g_ah[(size_t)3 * NTOK_ * DM_];
__device__ __align__(16) __nv_bfloat16 g_al[(size_t)3 * NTOK_ * DM_];
__device__ __align__(16) __nv_bfloat16 g_wh[4 * DM_ * DM_];
__device__ __align__(16) __nv_bfloat16 g_wl[4 * DM_ * DM_];
__device__ __align__(16) __nv_bfloat16 g_qh[(size_t)BH_ * L_ * D_]; // q split [bh][l][d]
__device__ __align__(16) __nv_bfloat16 g_ql[(size_t)BH_ * L_ * D_];
__device__ __align__(16) __nv_bfloat16 g_kh[(size_t)BH_ * L_ * D_];
__device__ __align__(16) __nv_bfloat16 g_kl[(size_t)BH_ * L_ * D_];
__device__ __align__(16) __nv_bfloat16 g_vh[(size_t)BH_ * L_ * D_];
__device__ __align__(16) __nv_bfloat16 g_vl[(size_t)BH_ * L_ * D_];
__device__ __align__(16) __nv_bfloat16 g_Qlh[BH_ * M_ * D_];
__device__ __align__(16) __nv_bfloat16 g_Qll[BH_ * M_ * D_];
__device__ __align__(16) __nv_bfloat16 g_Klh[BH_ * M_ * D_];
__device__ __align__(16) __nv_bfloat16 g_Kll[BH_ * M_ * D_];
__device__ __align__(16) __nv_bfloat16 g_k1h[(size_t)BH_ * L_ * M_]; // kernel_1 split
__device__ __align__(16) __nv_bfloat16 g_k1l[(size_t)BH_ * L_ * M_];
__device__ __align__(16) __nv_bfloat16 g_s3h[(size_t)BH_ * M_ * L_]; // softmaxed k3 split
__device__ __align__(16) __nv_bfloat16 g_s3l[(size_t)BH_ * M_ * L_];
__device__ __align__(16) __nv_bfloat16 g_y2th[BH_ * D_ * M_];        // y2^T split [bh][d][m]
__device__ __align__(16) __nv_bfloat16 g_y2tl[BH_ * D_ * M_];

// =====================================================================
// PTX helpers (baseline set only: mma.sync / ldmatrix / cp.async)
// =====================================================================
__device__ __forceinline__ uint32_t smem_to_u32(const void* p) {
    uint32_t a;
    asm("{ .reg .u64 t; cvta.to.shared.u64 t, %1; cvt.u32.u64 %0, t; }" : "=r"(a) : "l"(p));
    return a;
}
__device__ __forceinline__ void ldsm4(uint32_t* r, uint32_t addr) {
    asm volatile("ldmatrix.sync.aligned.m8n8.x4.shared.b16 {%0,%1,%2,%3}, [%4];"
        : "=r"(r[0]), "=r"(r[1]), "=r"(r[2]), "=r"(r[3]) : "r"(addr));
}
__device__ __forceinline__ void ldsm4t(uint32_t* r, uint32_t addr) {
    asm volatile("ldmatrix.sync.aligned.m8n8.x4.trans.shared.b16 {%0,%1,%2,%3}, [%4];"
        : "=r"(r[0]), "=r"(r[1]), "=r"(r[2]), "=r"(r[3]) : "r"(addr));
}
__device__ __forceinline__ void mma16816(float* d, const uint32_t* a, const uint32_t* b) {
    asm volatile("mma.sync.aligned.m16n8k16.row.col.f32.bf16.bf16.f32 "
        "{%0,%1,%2,%3}, {%4,%5,%6,%7}, {%8,%9}, {%0,%1,%2,%3};"
        : "+f"(d[0]), "+f"(d[1]), "+f"(d[2]), "+f"(d[3])
        : "r"(a[0]), "r"(a[1]), "r"(a[2]), "r"(a[3]), "r"(b[0]), "r"(b[1]));
}
#define CP_ASYNC16(dst, src) \
    asm volatile("cp.async.cg.shared.global [%0], [%1], 16;" :: "r"(dst), "l"(src))
#define CP_COMMIT()  asm volatile("cp.async.commit_group;" ::: "memory")
#define CP_WAIT(n)   asm volatile("cp.async.wait_group %0;" :: "n"(n) : "memory")

__device__ __forceinline__ void split_bf16(float v, __nv_bfloat16& h, __nv_bfloat16& l) {
    h = __float2bfloat16(v);
    l = __float2bfloat16(v - __bfloat162float(h));
}

// =====================================================================
// conversion kernels (fp32 -> bf16 hi/lo split)
// =====================================================================
__global__ void conv_act3_kernel(const float* __restrict__ s0,
                                 const float* __restrict__ s1,
                                 const float* __restrict__ s2)
{
    int z = blockIdx.y;
    const float* src = (z == 0) ? s0 : ((z == 1) ? s1 : s2);
    size_t i4 = (size_t)blockIdx.x * 256 + threadIdx.x;
    float4 v = *(const float4*)&src[i4 * 4];
    __nv_bfloat16 h[4], l[4];
    float a[4] = {v.x, v.y, v.z, v.w};
    #pragma unroll
    for (int i = 0; i < 4; i++) split_bf16(a[i], h[i], l[i]);
    size_t o = (size_t)z * NTOK_ * DM_ + i4 * 4;
    *(uint2*)&g_ah[o] = *(uint2*)h;
    *(uint2*)&g_al[o] = *(uint2*)l;
}

__global__ void conv_wt_kernel(const float* __restrict__ W, int slot)
{
    __shared__ float t[32][33];
    int x = blockIdx.x * 32 + threadIdx.x;
    int y = blockIdx.y * 32 + threadIdx.y;
    #pragma unroll
    for (int j = 0; j < 32; j += 8) t[threadIdx.y + j][threadIdx.x] = W[(size_t)(y + j) * 1024 + x];
    __syncthreads();
    int xo = blockIdx.y * 32 + threadIdx.x;
    int yo = blockIdx.x * 32 + threadIdx.y;
    size_t base = (size_t)slot * DM_ * DM_;
    #pragma unroll
    for (int j = 0; j < 32; j += 8) {
        float v = t[threadIdx.x][threadIdx.y + j];
        __nv_bfloat16 h, l; split_bf16(v, h, l);
        g_wh[base + (size_t)(yo + j) * 1024 + xo] = h;
        g_wl[base + (size_t)(yo + j) * 1024 + xo] = l;
    }
}

// =====================================================================
// projection GEMM — round-5 core: BK=32, 2-stage cp.async, 81920 B smem.
// mode = -1: fused QKV (z = blockIdx.z selects A slot z, W slot z, dest q/k/v)
// mode =  3: output projection (A slot 0, W slot 3, fp32 out, bias = b0p)
// =====================================================================
#define PITCH   40
#define TSZ     (128 * PITCH * 2)   // 10240
#define BUFSZ   (4 * TSZ)           // 40960 per stage
#define OFF_AH  0
#define OFF_AL  (1 * TSZ)
#define OFF_BH  (2 * TSZ)
#define OFF_BL  (3 * TSZ)

__global__ __launch_bounds__(256) void gemm_mma_kernel(
    const float* __restrict__ b0p, const float* __restrict__ b1p,
    const float* __restrict__ b2p, float* __restrict__ outp, int mode)
{
    char* smem = dynsm;
    const uint32_t sbase = smem_to_u32(smem);

    const int z  = (mode == 3) ? 0 : blockIdx.z;
    const int wz = (mode == 3) ? 3 : z;
    const float* bias = (mode == 3) ? b0p : ((z == 0) ? b0p : ((z == 1) ? b1p : b2p));
    const __nv_bfloat16* Ah = g_ah + (size_t)z * NTOK_ * DM_;
    const __nv_bfloat16* Al = g_al + (size_t)z * NTOK_ * DM_;
    const __nv_bfloat16* Wh = g_wh + (size_t)wz * DM_ * DM_;
    const __nv_bfloat16* Wl = g_wl + (size_t)wz * DM_ * DM_;

    const int tid  = threadIdx.x;
    const int lane = tid & 31;
    const int w    = tid >> 5;
    const int wm   = w >> 2;
    const int wn   = w & 3;
    const int n0 = blockIdx.x * 128;
    const int m0 = blockIdx.y * 128;

    float acc[4][4][4];
    #pragma unroll
    for (int i = 0; i < 4; i++)
        #pragma unroll
        for (int j = 0; j < 4; j++)
            #pragma unroll
            for (int t = 0; t < 4; t++) acc[i][j][t] = 0.f;

    auto load_chunk = [&](int c, int buf) {
        const int k0 = c * 32;
        const uint32_t sb = sbase + buf * BUFSZ;
        #pragma unroll
        for (int i = 0; i < 8; i++) {
            int q = tid + i * 256;
            int arr = q >> 9;
            int r   = (q >> 2) & 127;
            int c4  = q & 3;
            uint32_t dst = sb + arr * TSZ + r * 80 + c4 * 16;
            const __nv_bfloat16* src;
            if      (arr == 0) src = &Ah[(size_t)(m0 + r) * 1024 + k0 + c4 * 8];
            else if (arr == 1) src = &Al[(size_t)(m0 + r) * 1024 + k0 + c4 * 8];
            else if (arr == 2) src = &Wh[(size_t)(n0 + r) * 1024 + k0 + c4 * 8];
            else               src = &Wl[(size_t)(n0 + r) * 1024 + k0 + c4 * 8];
            CP_ASYNC16(dst, src);
        }
        CP_COMMIT();
    };

    auto compute_chunk = [&](int buf) {
        const uint32_t S = sbase + buf * BUFSZ;
        #pragma unroll
        for (int k16 = 0; k16 < 2; k16++) {
            const uint32_t kb = (uint32_t)(k16 * 32);
            uint32_t af[2][4][4];
            #pragma unroll
            for (int term = 0; term < 2; term++) {
                uint32_t base = S + (term ? OFF_AL : OFF_AH);
                #pragma unroll
                for (int mt = 0; mt < 4; mt++) {
                    uint32_t addr = base
                        + (uint32_t)((wm * 64 + mt * 16 + (lane & 15)) * 80)
                        + kb + (uint32_t)((lane >> 4) * 16);
                    ldsm4(af[term][mt], addr);
                }
            }
            uint32_t bf[2][2][4];
            #pragma unroll
            for (int term = 0; term < 2; term++) {
                uint32_t base = S + (term ? OFF_BL : OFF_BH);
                #pragma unroll
                for (int np = 0; np < 2; np++) {
                    uint32_t nrow = (uint32_t)(wn * 32 + np * 16 + ((lane >> 4) * 8) + (lane & 7));
                    uint32_t addr = base + nrow * 80 + kb + (uint32_t)(((lane >> 3) & 1) * 16);
                    ldsm4(bf[term][np], addr);
                }
            }
            #pragma unroll
            for (int mt = 0; mt < 4; mt++) {
                #pragma unroll
                for (int nt = 0; nt < 4; nt++) {
                    float* d = acc[mt][nt];
                    const uint32_t* bh_ = &bf[0][nt >> 1][(nt & 1) * 2];
                    const uint32_t* bl_ = &bf[1][nt >> 1][(nt & 1) * 2];
                    mma16816(d, af[0][mt], bh_);
                    mma16816(d, af[0][mt], bl_);
                    mma16816(d, af[1][mt], bh_);
                }
            }
        }
    };

    // 2-stage pipeline (round-5 exact)
    load_chunk(0, 0);
    #pragma unroll 1
    for (int c = 0; c < 32; c++) {
        if (c + 1 < 32) {
            load_chunk(c + 1, (c + 1) & 1);
            CP_WAIT(1);
        } else {
            CP_WAIT(0);
        }
        __syncthreads();
        compute_chunk(c & 1);
        __syncthreads();
    }

    #pragma unroll
    for (int mt = 0; mt < 4; mt++) {
        #pragma unroll
        for (int nt = 0; nt < 4; nt++) {
            int c = n0 + wn * 32 + nt * 8 + (lane & 3) * 2;
            float b0 = bias[c], b1 = bias[c + 1];
            #pragma unroll
            for (int half = 0; half < 2; half++) {
                int r = m0 + wm * 64 + mt * 16 + (lane >> 2) + half * 8;
                float vx = acc[mt][nt][half * 2 + 0] + b0;
                float vy = acc[mt][nt][half * 2 + 1] + b1;
                if (mode == 3) {
                    float2 t = {vx, vy};
                    *(float2*)&outp[(size_t)r * 1024 + c] = t;
                } else {
                    __nv_bfloat16* dh = (z == 0) ? g_qh : ((z == 1) ? g_kh : g_vh);
                    __nv_bfloat16* dl = (z == 0) ? g_ql : ((z == 1) ? g_kl : g_vl);
                    int b = r >> 12, l = r & 4095;
                    int h = c >> 6, d = c & 63;
                    size_t o = (((size_t)(b * 16 + h) * 4096) + l) * 64 + d;
                    __nv_bfloat16 hp[2], lp[2];
                    split_bf16(vx, hp[0], lp[0]);
                    split_bf16(vy, hp[1], lp[1]);
                    *(uint32_t*)&dh[o] = *(uint32_t*)hp;
                    *(uint32_t*)&dl[o] = *(uint32_t*)lp;
                }
            }
        }
    }
}

// =====================================================================
// landmark pooling from split q/k; writes fp32 + split landmarks
// =====================================================================
__global__ void pool_kernel()
{
    int idx = blockIdx.x * blockDim.x + threadIdx.x;   // BH*M*D
    int d  = idx & 63;
    int m  = (idx >> 6) & 127;
    int bh = idx >> 13;
    size_t base = ((size_t)bh * L_ + m * SEG_) * D_ + d;
    float sq = 0.f, sk = 0.f;
    #pragma unroll
    for (int s = 0; s < SEG_; s++) {
        sq += __bfloat162float(g_qh[base + s * D_]) + __bfloat162float(g_ql[base + s * D_]);
        sk += __bfloat162float(g_kh[base + s * D_]) + __bfloat162float(g_kl[base + s * D_]);
    }
    float mq = sq * (1.f / SEG_), mk = sk * (1.f / SEG_);
    g_Ql[idx] = mq; g_Kl[idx] = mk;
    __nv_bfloat16 h, l;
    split_bf16(mq, h, l); g_Qlh[idx] = h; g_Qll[idx] = l;
    split_bf16(mk, h, l); g_Klh[idx] = h; g_Kll[idx] = l;
}

// =====================================================================
// k1: C[128 tok][128 lm] = q_blk @ Kl^T (split mma) + fused softmax -> split bf16
// =====================================================================
__global__ __launch_bounds__(256) void k1_mma_kernel()
{
    char* sm = dynsm;
    const uint32_t sb = smem_to_u32(sm);
    int bh = blockIdx.y, l0 = blockIdx.x * 128, tid = threadIdx.x;
    int lane = tid & 31, w = tid >> 5;

    {
        const __nv_bfloat16* qh = g_qh + ((size_t)bh * L_ + l0) * D_;
        const __nv_bfloat16* ql = g_ql + ((size_t)bh * L_ + l0) * D_;
        const __nv_bfloat16* kh = g_Klh + bh * (M_ * D_);
        const __nv_bfloat16* kl = g_Kll + bh * (M_ * D_);
        #pragma unroll
        for (int i = 0; i < 4; i++) {
            int q = tid + i * 256;
            int row = q >> 3, c8 = q & 7;
            uint32_t so = (uint32_t)(row * 144 + c8 * 16);
            size_t go = (size_t)row * 64 + c8 * 8;
            *(uint4*)(sm + 0     + so) = *(const uint4*)&qh[go];
            *(uint4*)(sm + 18432 + so) = *(const uint4*)&ql[go];
            *(uint4*)(sm + 36864 + so) = *(const uint4*)&kh[go];
            *(uint4*)(sm + 55296 + so) = *(const uint4*)&kl[go];
        }
    }
    __syncthreads();

    int wm = w >> 2, wn = w & 3;
    float acc[4][4][4];
    #pragma unroll
    for (int i = 0; i < 4; i++)
        #pragma unroll
        for (int j = 0; j < 4; j++)
            #pragma unroll
            for (int t = 0; t < 4; t++) acc[i][j][t] = 0.f;

    #pragma unroll
    for (int k16 = 0; k16 < 4; k16++) {
        uint32_t af[2][4][4];
        #pragma unroll
        for (int term = 0; term < 2; term++)
            #pragma unroll
            for (int mt = 0; mt < 4; mt++) {
                uint32_t addr = sb + term * 18432
                    + (uint32_t)((wm * 64 + mt * 16 + (lane & 15)) * 144)
                    + (uint32_t)(k16 * 32) + (uint32_t)((lane >> 4) * 16);
                ldsm4(af[term][mt], addr);
            }
        uint32_t bf[2][2][4];
        #pragma unroll
        for (int term = 0; term < 2; term++)
            #pragma unroll
            for (int np = 0; np < 2; np++) {
                uint32_t nrow = (uint32_t)(wn * 32 + np * 16 + ((lane >> 4) * 8) + (lane & 7));
                uint32_t addr = sb + 36864 + term * 18432 + nrow * 144
                    + (uint32_t)(k16 * 32) + (uint32_t)(((lane >> 3) & 1) * 16);
                ldsm4(bf[term][np], addr);
            }
        #pragma unroll
        for (int mt = 0; mt < 4; mt++)
            #pragma unroll
            for (int nt = 0; nt < 4; nt++) {
                float* d = acc[mt][nt];
                const uint32_t* bh_ = &bf[0][nt >> 1][(nt & 1) * 2];
                const uint32_t* bl_ = &bf[1][nt >> 1][(nt & 1) * 2];
                mma16816(d, af[0][mt], bh_);
                mma16816(d, af[0][mt], bl_);
                mma16816(d, af[1][mt], bh_);
            }
    }
    __syncthreads();

    float* S = (float*)sm;
    #pragma unroll
    for (int mt = 0; mt < 4; mt++)
        #pragma unroll
        for (int nt = 0; nt < 4; nt++)
            #pragma unroll
            for (int half = 0; half < 2; half++) {
                int row = wm * 64 + mt * 16 + (lane >> 2) + half * 8;
                int col = wn * 32 + nt * 8 + (lane & 3) * 2;
                S[row * 128 + col]     = acc[mt][nt][half * 2 + 0];
                S[row * 128 + col + 1] = acc[mt][nt][half * 2 + 1];
            }
    __syncthreads();

    for (int rr = 0; rr < 16; rr++) {
        int row = w * 16 + rr;
        float x0 = S[row * 128 + lane],      x1 = S[row * 128 + lane + 32];
        float x2 = S[row * 128 + lane + 64], x3 = S[row * 128 + lane + 96];
        float mx = fmaxf(fmaxf(x0, x1), fmaxf(x2, x3));
        #pragma unroll
        for (int o = 16; o; o >>= 1) mx = fmaxf(mx, __shfl_xor_sync(0xffffffffu, mx, o));
        float e0 = __expf(x0 - mx), e1 = __expf(x1 - mx);
        float e2 = __expf(x2 - mx), e3 = __expf(x3 - mx);
        float s = e0 + e1 + e2 + e3;
        #pragma unroll
        for (int o = 16; o; o >>= 1) s += __shfl_xor_sync(0xffffffffu, s, o);
        float inv = 1.f / s;
        size_t ob = ((size_t)bh * L_ + l0 + row) * 128;
        float vv[4] = {e0 * inv, e1 * inv, e2 * inv, e3 * inv};
        #pragma unroll
        for (int j = 0; j < 4; j++) {
            __nv_bfloat16 h, l; split_bf16(vv[j], h, l);
            g_k1h[ob + lane + 32 * j] = h;
            g_k1l[ob + lane + 32 * j] = l;
        }
    }
}

// =====================================================================
// k3 scores: C[m=128][l=128 blk] = Ql @ k_blk^T (split mma) -> raw fp32 g_k3
// =====================================================================
__global__ __launch_bounds__(256) void k3score_mma_kernel()
{
    char* sm = dynsm;
    const uint32_t sb = smem_to_u32(sm);
    int bh = blockIdx.y, l0 = blockIdx.x * 128, tid = threadIdx.x;
    int lane = tid & 31, w = tid >> 5;

    {
        const __nv_bfloat16* ah = g_Qlh + bh * (M_ * D_);
        const __nv_bfloat16* al = g_Qll + bh * (M_ * D_);
        const __nv_bfloat16* bhp = g_kh + ((size_t)bh * L_ + l0) * D_;
        const __nv_bfloat16* blp = g_kl + ((size_t)bh * L_ + l0) * D_;
        #pragma unroll
        for (int i = 0; i < 4; i++) {
            int q = tid + i * 256;
            int row = q >> 3, c8 = q & 7;
            uint32_t so = (uint32_t)(row * 144 + c8 * 16);
            size_t go = (size_t)row * 64 + c8 * 8;
            *(uint4*)(sm + 0     + so) = *(const uint4*)&ah[go];
            *(uint4*)(sm + 18432 + so) = *(const uint4*)&al[go];
            *(uint4*)(sm + 36864 + so) = *(const uint4*)&bhp[go];
            *(uint4*)(sm + 55296 + so) = *(const uint4*)&blp[go];
        }
    }
    __syncthreads();

    int wm = w >> 2, wn = w & 3;
    float acc[4][4][4];
    #pragma unroll
    for (int i = 0; i < 4; i++)
        #pragma unroll
        for (int j = 0; j < 4; j++)
            #pragma unroll
            for (int t = 0; t < 4; t++) acc[i][j][t] = 0.f;

    #pragma unroll
    for (int k16 = 0; k16 < 4; k16++) {
        uint32_t af[2][4][4];
        #pragma unroll
        for (int term = 0; term < 2; term++)
            #pragma unroll
            for (int mt = 0; mt < 4; mt++) {
                uint32_t addr = sb + term * 18432
                    + (uint32_t)((wm * 64 + mt * 16 + (lane & 15)) * 144)
                    + (uint32_t)(k16 * 32) + (uint32_t)((lane >> 4) * 16);
                ldsm4(af[term][mt], addr);
            }
        uint32_t bf[2][2][4];
        #pragma unroll
        for (int term = 0; term < 2; term++)
            #pragma unroll
            for (int np = 0; np < 2; np++) {
                uint32_t nrow = (uint32_t)(wn * 32 + np * 16 + ((lane >> 4) * 8) + (lane & 7));
                uint32_t addr = sb + 36864 + term * 18432 + nrow * 144
                    + (uint32_t)(k16 * 32) + (uint32_t)(((lane >> 3) & 1) * 16);
                ldsm4(bf[term][np], addr);
            }
        #pragma unroll
        for (int mt = 0; mt < 4; mt++)
            #pragma unroll
            for (int nt = 0; nt < 4; nt++) {
                float* d = acc[mt][nt];
                const uint32_t* bh_ = &bf[0][nt >> 1][(nt & 1) * 2];
                const uint32_t* bl_ = &bf[1][nt >> 1][(nt & 1) * 2];
                mma16816(d, af[0][mt], bh_);
                mma16816(d, af[0][mt], bl_);
                mma16816(d, af[1][mt], bh_);
            }
    }

    float* o = g_k3 + (size_t)bh * M_ * L_;
    #pragma unroll
    for (int mt = 0; mt < 4; mt++)
        #pragma unroll
        for (int nt = 0; nt < 4; nt++)
            #pragma unroll
            for (int half = 0; half < 2; half++) {
                int m_r = wm * 64 + mt * 16 + (lane >> 2) + half * 8;
                int l_c = l0 + wn * 32 + nt * 8 + (lane & 3) * 2;
                float2 t = {acc[mt][nt][half * 2 + 0], acc[mt][nt][half * 2 + 1]};
                *(float2*)&o[(size_t)m_r * L_ + l_c] = t;
            }
}

// =====================================================================
// row softmax over 4096; reads fp32 g_k3, writes split bf16 g_s3
// =====================================================================
__global__ __launch_bounds__(256) void softmax4096_kernel()
{
    size_t row = blockIdx.x;
    const float* p = g_k3 + row * 4096;
    int tid = threadIdx.x;
    float v[16];
    float mx = -1e30f;
    #pragma unroll
    for (int i = 0; i < 4; i++) {
        float4 t = *(const float4*)&p[i * 1024 + tid * 4];
        v[i * 4 + 0] = t.x; v[i * 4 + 1] = t.y; v[i * 4 + 2] = t.z; v[i * 4 + 3] = t.w;
        mx = fmaxf(mx, fmaxf(fmaxf(t.x, t.y), fmaxf(t.z, t.w)));
    }
    __shared__ float smx[8], ssm[8], sres;
    #pragma unroll
    for (int o = 16; o; o >>= 1) mx = fmaxf(mx, __shfl_xor_sync(0xffffffffu, mx, o));
    if ((tid & 31) == 0) smx[tid >> 5] = mx;
    __syncthreads();
    if (tid == 0) {
        float m = smx[0];
        #pragma unroll
        for (int i = 1; i < 8; i++) m = fmaxf(m, smx[i]);
        sres = m;
    }
    __syncthreads();
    float MX = sres;
    float s = 0.f;
    #pragma unroll
    for (int i = 0; i < 16; i++) { v[i] = __expf(v[i] - MX); s += v[i]; }
    #pragma unroll
    for (int o = 16; o; o >>= 1) s += __shfl_xor_sync(0xffffffffu, s, o);
    if ((tid & 31) == 0) ssm[tid >> 5] = s;
    __syncthreads();
    if (tid == 0) {
        float t = 0.f;
        #pragma unroll
        for (int i = 0; i < 8; i++) t += ssm[i];
        sres = 1.f / t;
    }
    __syncthreads();
    float inv = sres;
    #pragma unroll
    for (int i = 0; i < 4; i++) {
        __nv_bfloat16 hh[4], ll[4];
        #pragma unroll
        for (int t = 0; t < 4; t++) split_bf16(v[i * 4 + t] * inv, hh[t], ll[t]);
        *(uint2*)&g_s3h[row * 4096 + i * 1024 + tid * 4] = *(uint2*)hh;
        *(uint2*)&g_s3l[row * 4096 + i * 1024 + tid * 4] = *(uint2*)ll;
    }
}

// =====================================================================
// kernel_2 = softmax(Q_l @ K_l^T) fused (fp32, tiny). block per head.
// =====================================================================
__global__ __launch_bounds__(256) void k2_kernel()
{
    float* sm = (float*)dynsm;
    float* Qlt = sm;
    float* Klt = sm + 8192;
    float* S   = sm + 16384;
    int bh = blockIdx.x, tid = threadIdx.x;

    const float* Ql = g_Ql + bh * 8192;
    const float* Kl = g_Kl + bh * 8192;
    #pragma unroll
    for (int i = 0; i < 8; i++) {
        int f = i * 1024 + tid * 4; int m = f >> 6, d0 = f & 63;
        float4 tq = *(const float4*)&Ql[f];
        float4 tk = *(const float4*)&Kl[f];
        Qlt[(d0 + 0) * 128 + m] = tq.x; Qlt[(d0 + 1) * 128 + m] = tq.y;
        Qlt[(d0 + 2) * 128 + m] = tq.z; Qlt[(d0 + 3) * 128 + m] = tq.w;
        Klt[(d0 + 0) * 128 + m] = tk.x; Klt[(d0 + 1) * 128 + m] = tk.y;
        Klt[(d0 + 2) * 128 + m] = tk.z; Klt[(d0 + 3) * 128 + m] = tk.w;
    }
    __syncthreads();

    int tm = tid >> 4, tn = tid & 15;
    float acc[8][8] = {};
    for (int d = 0; d < 64; d++) {
        float4 a0 = *(const float4*)&Qlt[d * 128 + tm * 8];
        float4 a1 = *(const float4*)&Qlt[d * 128 + tm * 8 + 4];
        float4 b0 = *(const float4*)&Klt[d * 128 + tn * 8];
        float4 b1 = *(const float4*)&Klt[d * 128 + tn * 8 + 4];
        float av[8] = {a0.x, a0.y, a0.z, a0.w, a1.x, a1.y, a1.z, a1.w};
        float bv[8] = {b0.x, b0.y, b0.z, b0.w, b1.x, b1.y, b1.z, b1.w};
        #pragma unroll
        for (int i = 0; i < 8; i++)
            #pragma unroll
            for (int j = 0; j < 8; j++) acc[i][j] += av[i] * bv[j];
    }
    #pragma unroll
    for (int i = 0; i < 8; i++)
        #pragma unroll
        for (int j = 0; j < 8; j++) S[(tm * 8 + i) * 128 + tn * 8 + j] = acc[i][j];
    __syncthreads();

    int lane = tid & 31, w = tid >> 5;
    for (int rr = 0; rr < 16; rr++) {
        int row = w * 16 + rr;
        float x0 = S[row * 128 + lane],      x1 = S[row * 128 + lane + 32];
        float x2 = S[row * 128 + lane + 64], x3 = S[row * 128 + lane + 96];
        float mx = fmaxf(fmaxf(x0, x1), fmaxf(x2, x3));
        #pragma unroll
        for (int o = 16; o; o >>= 1) mx = fmaxf(mx, __shfl_xor_sync(0xffffffffu, mx, o));
        float e0 = __expf(x0 - mx), e1 = __expf(x1 - mx);
        float e2 = __expf(x2 - mx), e3 = __expf(x3 - mx);
        float s = e0 + e1 + e2 + e3;
        #pragma unroll
        for (int o = 16; o; o >>= 1) s += __shfl_xor_sync(0xffffffffu, s, o);
        float inv = 1.f / s;
        float* o = g_k2 + bh * 16384 + row * 128;
        o[lane] = e0 * inv; o[lane + 32] = e1 * inv; o[lane + 64] = e2 * inv; o[lane + 96] = e3 * inv;
    }
}

// =====================================================================
// V0 = K^T / max(colsum(K))
// =====================================================================
__global__ __launch_bounds__(256) void vinit_kernel()
{
    int bh = blockIdx.x, tid = threadIdx.x;
    const float* K = g_k2 + bh * 16384;
    __shared__ float cs[128];
    __shared__ float sscale;
    if (tid < 128) {
        float s = 0.f;
        for (int r = 0; r < 128; r++) s += K[r * 128 + tid];
        cs[tid] = s;
    }
    __syncthreads();
    if (tid == 0) {
        float m = cs[0];
        for (int i = 1; i < 128; i++) m = fmaxf(m, cs[i]);
        sscale = 1.f / m;
    }
    __syncthreads();
    float scale = sscale;
    for (int f = tid; f < 16384; f += 256) {
        int i = f >> 7, j = f & 127;
        g_Va[bh * 16384 + f] = scale * K[j * 128 + i];
    }
}

// =====================================================================
// batched 128x128 bmm for Newton-Schulz (fp32)
// =====================================================================
__device__ __forceinline__ float* bufsel(int s)
{
    switch (s) {
        case 0: return g_k2; case 1: return g_P; case 2: return g_M1;
        case 3: return g_M2; case 4: return g_Va; default: return g_Vb;
    }
}

__global__ __launch_bounds__(256) void bmm_kernel(int as, int bs, int cs2, int os,
                                                  float alpha, float beta)
{
    float* sm = (float*)dynsm;
    float* Bs = sm;
    float* At = sm + 16384;
    int bh = blockIdx.y, r0 = blockIdx.x * 32, tid = threadIdx.x;
    const float* A  = bufsel(as)  + bh * 16384;
    const float* Bm = bufsel(bs)  + bh * 16384;
    const float* C  = bufsel(cs2) + bh * 16384;
    float* O        = bufsel(os)  + bh * 16384;

    #pragma unroll
    for (int i = 0; i < 16; i++) {
        int f = i * 1024 + tid * 4;
        *(float4*)&Bs[f] = *(const float4*)&Bm[f];
    }
    #pragma unroll
    for (int i = 0; i < 4; i++) {
        int f = i * 1024 + tid * 4; int r = f >> 7, k0 = f & 127;
        float4 t = *(const float4*)&A[(r0 + r) * 128 + k0];
        At[(k0 + 0) * 32 + r] = t.x; At[(k0 + 1) * 32 + r] = t.y;
        At[(k0 + 2) * 32 + r] = t.z; At[(k0 + 3) * 32 + r] = t.w;
    }
    __syncthreads();

    int rb = (tid >> 5) * 4, cb = (tid & 31) * 4;
    float acc[4][4] = {};
    for (int k = 0; k < 128; k++) {
        float a0 = At[k * 32 + rb + 0], a1 = At[k * 32 + rb + 1];
        float a2 = At[k * 32 + rb + 2], a3 = At[k * 32 + rb + 3];
        float4 b = *(const float4*)&Bs[k * 128 + cb];
        acc[0][0] += a0 * b.x; acc[0][1] += a0 * b.y; acc[0][2] += a0 * b.z; acc[0][3] += a0 * b.w;
        acc[1][0] += a1 * b.x; acc[1][1] += a1 * b.y; acc[1][2] += a1 * b.z; acc[1][3] += a1 * b.w;
        acc[2][0] += a2 * b.x; acc[2][1] += a2 * b.y; acc[2][2] += a2 * b.z; acc[2][3] += a2 * b.w;
        acc[3][0] += a3 * b.x; acc[3][1] += a3 * b.y; acc[3][2] += a3 * b.z; acc[3][3] += a3 * b.w;
    }
    #pragma unroll
    for (int i = 0; i < 4; i++)
        #pragma unroll
        for (int j = 0; j < 4; j++) {
            int idx = (r0 + rb + i) * 128 + cb + j;
            O[idx] = alpha * acc[i][j] + beta * C[idx];
        }
}

// =====================================================================
// k3v: partial C[m=128][d=64] = softmax(k3)_split @ v_split (mma, split-K 4)
// 2-stage pipeline. dyn smem 110592
// =====================================================================
#define KV_STG 55296

__global__ __launch_bounds__(256) void k3v_mma_kernel()
{
    char* sm = dynsm;
    const uint32_t sb = smem_to_u32(sm);
    int s = blockIdx.x, bh = blockIdx.y, tid = threadIdx.x;
    int lane = tid & 31, w = tid >> 5;
    int wm = w >> 1, wn = w & 1;
    const size_t abase = (size_t)bh * M_ * L_;
    const size_t vbase = (size_t)bh * L_ * D_;

    float acc[2][4][4];
    #pragma unroll
    for (int i = 0; i < 2; i++)
        #pragma unroll
        for (int j = 0; j < 4; j++)
            #pragma unroll
            for (int t = 0; t < 4; t++) acc[i][j][t] = 0.f;

    auto load = [&](int ck, int buf) {
        int k0 = s * 1024 + ck * 64;
        uint32_t S = sb + buf * KV_STG;
        #pragma unroll
        for (int i = 0; i < 8; i++) {
            int q = tid + i * 256;
            int arr = q >> 10, row = (q >> 3) & 127, c8 = q & 7;
            uint32_t dst = S + arr * 18432 + (uint32_t)(row * 144 + c8 * 16);
            const __nv_bfloat16* src = (arr ? g_s3l : g_s3h) + abase + (size_t)row * L_ + k0 + c8 * 8;
            CP_ASYNC16(dst, src);
        }
        #pragma unroll
        for (int i = 0; i < 4; i++) {
            int q = tid + i * 256;
            int arr = q >> 9, row = (q >> 3) & 63, c8 = q & 7;
            uint32_t dst = S + 36864 + arr * 9216 + (uint32_t)(row * 144 + c8 * 16);
            const __nv_bfloat16* src = (arr ? g_vl : g_vh) + vbase + (size_t)(k0 + row) * D_ + c8 * 8;
            CP_ASYNC16(dst, src);
        }
        CP_COMMIT();
    };

    auto compute = [&](int buf) {
        uint32_t S = sb + buf * KV_STG;
        #pragma unroll
        for (int k16 = 0; k16 < 4; k16++) {
            uint32_t af[2][2][4];
            #pragma unroll
            for (int term = 0; term < 2; term++)
                #pragma unroll
                for (int mt = 0; mt < 2; mt++) {
                    uint32_t addr = S + term * 18432
                        + (uint32_t)((wm * 32 + mt * 16 + (lane & 15)) * 144)
                        + (uint32_t)(k16 * 32) + (uint32_t)((lane >> 4) * 16);
                    ldsm4(af[term][mt], addr);
                }
            uint32_t bf[2][2][4];
            #pragma unroll
            for (int term = 0; term < 2; term++)
                #pragma unroll
                for (int np = 0; np < 2; np++) {
                    uint32_t addr = S + 36864 + term * 9216
                        + (uint32_t)((k16 * 16 + (lane & 15)) * 144)
                        + (uint32_t)((wn * 32 + np * 16 + (lane >> 4) * 8) * 2);
                    ldsm4t(bf[term][np], addr);
                }
            #pragma unroll
            for (int mt = 0; mt < 2; mt++)
                #pragma unroll
                for (int nt = 0; nt < 4; nt++) {
                    float* d = acc[mt][nt];
                    const uint32_t* bh_ = &bf[0][nt >> 1][(nt & 1) * 2];
                    const uint32_t* bl_ = &bf[1][nt >> 1][(nt & 1) * 2];
                    mma16816(d, af[0][mt], bh_);
                    mma16816(d, af[0][mt], bl_);
                    mma16816(d, af[1][mt], bh_);
                }
        }
    };

    load(0, 0);
    #pragma unroll 1
    for (int ck = 0; ck < 16; ck++) {
        if (ck + 1 < 16) {
            load(ck + 1, (ck + 1) & 1);
            CP_WAIT(1);
        } else {
            CP_WAIT(0);
        }
        __syncthreads();
        compute(ck & 1);
        __syncthreads();
    }

    #pragma unroll
    for (int mt = 0; mt < 2; mt++)
        #pragma unroll
        for (int nt = 0; nt < 4; nt++)
            #pragma unroll
            for (int half = 0; half < 2; half++) {
                int m_r = wm * 32 + mt * 16 + (lane >> 2) + half * 8;
                int d_c = wn * 32 + nt * 8 + (lane & 3) * 2;
                float2 t = {acc[mt][nt][half * 2 + 0], acc[mt][nt][half * 2 + 1]};
                *(float2*)&g_k3v_part[((size_t)(s * 64 + bh) * 128 + m_r) * 64 + d_c] = t;
            }
}

__global__ void k3v_reduce_kernel()
{
    int idx = blockIdx.x * blockDim.x + threadIdx.x;  // 524288
    float s = 0.f;
    #pragma unroll
    for (int p = 0; p < 4; p++) s += g_k3v_part[(size_t)p * 524288 + idx];
    g_k3v[idx] = s;
}

// =====================================================================
// y2 = inv(g_Va) @ k3v per head (fp32); epilogue emits y2^T split bf16
// =====================================================================
__global__ __launch_bounds__(256) void y2_kernel()
{
    float* sm = (float*)dynsm;
    float* At = sm;
    float* Bs = sm + 16384;
    int bh = blockIdx.x, tid = threadIdx.x;
    const float* inv = g_Va + bh * 16384;
    const float* kv  = g_k3v + bh * 8192;

    #pragma unroll
    for (int i = 0; i < 16; i++) {
        int f = i * 1024 + tid * 4; int r = f >> 7, k0 = f & 127;
        float4 t = *(const float4*)&inv[f];
        At[(k0 + 0) * 128 + r] = t.x; At[(k0 + 1) * 128 + r] = t.y;
        At[(k0 + 2) * 128 + r] = t.z; At[(k0 + 3) * 128 + r] = t.w;
    }
    #pragma unroll
    for (int i = 0; i < 8; i++) {
        int f = i * 1024 + tid * 4;
        *(float4*)&Bs[f] = *(const float4*)&kv[f];
    }
    __syncthreads();

    int rt = tid >> 4, ct = tid & 15;
    float acc[8][4] = {};
    for (int k = 0; k < 128; k++) {
        float4 a0 = *(const float4*)&At[k * 128 + rt * 8];
        float4 a1 = *(const float4*)&At[k * 128 + rt * 8 + 4];
        float4 b  = *(const float4*)&Bs[k * 64 + ct * 4];
        float av[8] = {a0.x, a0.y, a0.z, a0.w, a1.x, a1.y, a1.z, a1.w};
        #pragma unroll
        for (int i = 0; i < 8; i++) {
            acc[i][0] += av[i] * b.x; acc[i][1] += av[i] * b.y;
            acc[i][2] += av[i] * b.z; acc[i][3] += av[i] * b.w;
        }
    }
    #pragma unroll
    for (int i = 0; i < 8; i++)
        #pragma unroll
        for (int j = 0; j < 4; j++) {
            __nv_bfloat16 h, l; split_bf16(acc[i][j], h, l);
            size_t o = (size_t)bh * 8192 + (ct * 4 + j) * 128 + rt * 8 + i;
            g_y2th[o] = h;
            g_y2tl[o] = l;
        }
}

// =====================================================================
// x1: C[l=128][d=64] = kernel1_split @ y2t_split (mma) -> g_ah/g_al slot 0
// =====================================================================
__global__ __launch_bounds__(256) void x1_mma_kernel()
{
    char* sm = dynsm;
    const uint32_t sb = smem_to_u32(sm);
    int bh = blockIdx.y, l0 = blockIdx.x * 128, tid = threadIdx.x;
    int lane = tid & 31, w = tid >> 5;
    int wm = w >> 1, wn = w & 1;

    {
        const __nv_bfloat16* ah = g_k1h + ((size_t)bh * L_ + l0) * 128;
        const __nv_bfloat16* al = g_k1l + ((size_t)bh * L_ + l0) * 128;
        #pragma unroll
        for (int i = 0; i < 16; i++) {
            int q = tid + i * 256;
            int arr = q >> 11, row = (q >> 4) & 127, c16 = q & 15;
            uint32_t so = (uint32_t)(arr * 34816 + row * 272 + c16 * 16);
            const __nv_bfloat16* src = (arr ? al : ah) + (size_t)row * 128 + c16 * 8;
            *(uint4*)(sm + so) = *(const uint4*)src;
        }
        const __nv_bfloat16* bhp = g_y2th + (size_t)bh * 8192;
        const __nv_bfloat16* blp = g_y2tl + (size_t)bh * 8192;
        #pragma unroll
        for (int i = 0; i < 8; i++) {
            int q = tid + i * 256;
            int arr = q >> 10, row = (q >> 4) & 63, c16 = q & 15;
            uint32_t so = (uint32_t)(69632 + arr * 17408 + row * 272 + c16 * 16);
            const __nv_bfloat16* src = (arr ? blp : bhp) + (size_t)row * 128 + c16 * 8;
            *(uint4*)(sm + so) = *(const uint4*)src;
        }
    }
    __syncthreads();

    float acc[2][4][4];
    #pragma unroll
    for (int i = 0; i < 2; i++)
        #pragma unroll
        for (int j = 0; j < 4; j++)
            #pragma unroll
            for (int t = 0; t < 4; t++) acc[i][j][t] = 0.f;

    #pragma unroll
    for (int k16 = 0; k16 < 8; k16++) {
        uint32_t af[2][2][4];
        #pragma unroll
        for (int term = 0; term < 2; term++)
            #pragma unroll
            for (int mt = 0; mt < 2; mt++) {
                uint32_t addr = sb + term * 34816
                    + (uint32_t)((wm * 32 + mt * 16 + (lane & 15)) * 272)
                    + (uint32_t)(k16 * 32) + (uint32_t)((lane >> 4) * 16);
                ldsm4(af[term][mt], addr);
            }
        uint32_t bf[2][2][4];
        #pragma unroll
        for (int term = 0; term < 2; term++)
            #pragma unroll
            for (int np = 0; np < 2; np++) {
                uint32_t nrow = (uint32_t)(wn * 32 + np * 16 + ((lane >> 4) * 8) + (lane & 7));
                uint32_t addr = sb + 69632 + term * 17408 + nrow * 272
                    + (uint32_t)(k16 * 32) + (uint32_t)(((lane >> 3) & 1) * 16);
                ldsm4(bf[term][np], addr);
            }
        #pragma unroll
        for (int mt = 0; mt < 2; mt++)
            #pragma unroll
            for (int nt = 0; nt < 4; nt++) {
                float* d = acc[mt][nt];
                const uint32_t* bh_ = &bf[0][nt >> 1][(nt & 1) * 2];
                const uint32_t* bl_ = &bf[1][nt >> 1][(nt & 1) * 2];
                mma16816(d, af[0][mt], bh_);
                mma16816(d, af[0][mt], bl_);
                mma16816(d, af[1][mt], bh_);
            }
    }

    int b = bh >> 4, h = bh & 15;
    #pragma unroll
    for (int mt = 0; mt < 2; mt++)
        #pragma unroll
        for (int nt = 0; nt < 4; nt++)
            #pragma unroll
            for (int half = 0; half < 2; half++) {
                int l = l0 + wm * 32 + mt * 16 + (lane >> 2) + half * 8;
                int d_c = wn * 32 + nt * 8 + (lane & 3) * 2;
                size_t o = ((size_t)(b * L_ + l)) * DM_ + h * 64 + d_c;
                __nv_bfloat16 hp[2], lp[2];
                split_bf16(acc[mt][nt][half * 2 + 0], hp[0], lp[0]);
                split_bf16(acc[mt][nt][half * 2 + 1], hp[1], lp[1]);
                *(uint32_t*)&g_ah[o] = *(uint32_t*)hp;
                *(uint32_t*)&g_al[o] = *(uint32_t*)lp;
            }
}

// =====================================================================
// launch — forks the Newton-Schulz chain onto a second stream
// =====================================================================
extern "C" void kernel_launch(void* const* d_in, const int* in_sizes, int n_in,
                              void* d_out, int out_size)
{
    const float* queries = (const float*)d_in[0];
    const float* keys    = (const float*)d_in[1];
    const float* values  = (const float*)d_in[2];
    const float* Wq = (const float*)d_in[3];
    const float* bq = (const float*)d_in[4];
    const float* Wk = (const float*)d_in[5];
    const float* bk = (const float*)d_in[6];
    const float* Wv = (const float*)d_in[7];
    const float* bv = (const float*)d_in[8];
    const float* Wo = (const float*)d_in[9];
    const float* bo = (const float*)d_in[10];
    float* out = (float*)d_out;

    cudaFuncSetAttribute(gemm_mma_kernel,    cudaFuncAttributeMaxDynamicSharedMemorySize, 81920);
    cudaFuncSetAttribute(k1_mma_kernel,      cudaFuncAttributeMaxDynamicSharedMemorySize, 73728);
    cudaFuncSetAttribute(k3score_mma_kernel, cudaFuncAttributeMaxDynamicSharedMemorySize, 73728);
    cudaFuncSetAttribute(k3v_mma_kernel,     cudaFuncAttributeMaxDynamicSharedMemorySize, 110592);
    cudaFuncSetAttribute(x1_mma_kernel,      cudaFuncAttributeMaxDynamicSharedMemorySize, 104448);
    cudaFuncSetAttribute(k2_kernel,          cudaFuncAttributeMaxDynamicSharedMemorySize, 131072);
    cudaFuncSetAttribute(bmm_kernel,         cudaFuncAttributeMaxDynamicSharedMemorySize, 81920);
    cudaFuncSetAttribute(y2_kernel,          cudaFuncAttributeMaxDynamicSharedMemorySize, 98304);

    // side stream + fork/join events (created once; graph-capture safe)
    static cudaStream_t s_b = nullptr;
    static cudaEvent_t ev_fork = nullptr, ev_join = nullptr;
    if (!s_b) {
        cudaStreamCreateWithFlags(&s_b, cudaStreamNonBlocking);
        cudaEventCreateWithFlags(&ev_fork, cudaEventDisableTiming);
        cudaEventCreateWithFlags(&ev_join, cudaEventDisableTiming);
    }

    dim3 wt_grid(32, 32), wt_blk(32, 8);

    // weight splits (4 slots incl. Wo) + activation splits, fused QKV GEMM
    conv_wt_kernel<<<wt_grid, wt_blk>>>(Wq, 0);
    conv_wt_kernel<<<wt_grid, wt_blk>>>(Wk, 1);
    conv_wt_kernel<<<wt_grid, wt_blk>>>(Wv, 2);
    conv_wt_kernel<<<wt_grid, wt_blk>>>(Wo, 3);
    conv_act3_kernel<<<dim3(16384, 3), 256>>>(queries, keys, values);
    gemm_mma_kernel<<<dim3(8, 128, 3), 256, 81920>>>(bq, bk, bv, nullptr, -1);

    // landmarks (both branches depend on this)
    pool_kernel<<<2048, 256>>>();

    // ---- fork: Newton-Schulz chain on side stream ----
    cudaEventRecord(ev_fork, 0);
    cudaStreamWaitEvent(s_b, ev_fork, 0);
    k2_kernel<<<64, 256, 131072, s_b>>>();
    vinit_kernel<<<64, 256, 0, s_b>>>();
    {
        int cur = 4, nxt = 5;
        for (int it = 0; it < 6; it++) {
            bmm_kernel<<<dim3(4, 64), 256, 81920, s_b>>>(0,   cur, 0,   1,   1.0f,  0.0f);
            bmm_kernel<<<dim3(4, 64), 256, 81920, s_b>>>(1,   1,   1,   2,  -1.0f,  7.0f);
            bmm_kernel<<<dim3(4, 64), 256, 81920, s_b>>>(1,   2,   1,   3,  -1.0f, 15.0f);
            bmm_kernel<<<dim3(4, 64), 256, 81920, s_b>>>(cur, 3,   cur, nxt, -0.25f, 3.25f);
            int t = cur; cur = nxt; nxt = t;
        }
        // after 6 iterations g_Va (cur==4) holds the pseudo-inverse
    }
    cudaEventRecord(ev_join, s_b);

    // ---- main stream: big attention chain ----
    k1_mma_kernel<<<dim3(32, 64), 256, 73728>>>();
    k3score_mma_kernel<<<dim3(32, 64), 256, 73728>>>();
    softmax4096_kernel<<<8192, 256>>>();
    k3v_mma_kernel<<<dim3(4, 64), 256, 110592>>>();
    k3v_reduce_kernel<<<2048, 256>>>();

    // ---- join: y2 needs g_Va (side) + g_k3v (main) ----
    cudaStreamWaitEvent(0, ev_join, 0);
    y2_kernel<<<64, 256, 98304>>>();
    x1_mma_kernel<<<dim3(32, 64), 256, 104448>>>();

    // output projection (A slot 0, W slot 3)
    gemm_mma_kernel<<<dim3(8, 128, 1), 256, 81920>>>(bo, nullptr, nullptr, out, 3);
}

// round 10
// speedup vs baseline: 1.3568x; 1.2043x over previous
#include <cuda_runtime.h>
#include <cuda_bf16.h>
#include <cstdint>

// ---------------- problem constants ----------------
#define B_    4
#define L_    4096
#define DM_   1024
#define H_    16
#define D_    64
#define M_    128
#define BH_   64          // B*H
#define SEG_  32          // L/M
#define NTOK_ 16384       // B*L

// single dynamic-smem symbol for the whole TU
extern __shared__ char dynsm[];

// ---------------- scratch (device globals; no allocations allowed) ----------------
__device__ float g_Ql[BH_ * M_ * D_];          // fp32 landmarks (for k2)
__device__ float g_Kl[BH_ * M_ * D_];
__device__ float g_k3[(size_t)BH_ * M_ * L_];  // raw scores fp32
__device__ float g_k2[BH_ * M_ * M_];
__device__ float g_P [BH_ * M_ * M_];
__device__ float g_M1[BH_ * M_ * M_];
__device__ float g_M2[BH_ * M_ * M_];
__device__ float g_Va[BH_ * M_ * M_];
__device__ float g_Vb[BH_ * M_ * M_];
__device__ float g_k3v_part[4 * BH_ * M_ * D_];

// tf32 operand buffers for the 4 big GEMMs (values pre-rounded with cvt.rna.tf32)
__device__ __align__(16) float g_af[(size_t)3 * NTOK_ * DM_];  // A slots (slot 0 reused by x1)
__device__ __align__(16) float g_wf[4 * DM_ * DM_];            // W^T slots (3 = Wo)

// bf16 split buffers for the attention-side GEMMs
__device__ __align__(16) __nv_bfloat16 g_qh[(size_t)BH_ * L_ * D_]; // q split [bh][l][d]
__device__ __align__(16) __nv_bfloat16 g_ql[(size_t)BH_ * L_ * D_];
__device__ __align__(16) __nv_bfloat16 g_kh[(size_t)BH_ * L_ * D_];
__device__ __align__(16) __nv_bfloat16 g_kl[(size_t)BH_ * L_ * D_];
__device__ __align__(16) __nv_bfloat16 g_vh[(size_t)BH_ * L_ * D_];
__device__ __align__(16) __nv_bfloat16 g_vl[(size_t)BH_ * L_ * D_];
__device__ __align__(16) __nv_bfloat16 g_Qlh[BH_ * M_ * D_];
__device__ __align__(16) __nv_bfloat16 g_Qll[BH_ * M_ * D_];
__device__ __align__(16) __nv_bfloat16 g_Klh[BH_ * M_ * D_];
__device__ __align__(16) __nv_bfloat16 g_Kll[BH_ * M_ * D_];
__device__ __align__(16) __nv_bfloat16 g_k1h[(size_t)BH_ * L_ * M_]; // kernel_1 split
__device__ __align__(16) __nv_bfloat16 g_k1l[(size_t)BH_ * L_ * M_];
__device__ __align__(16) __nv_bfloat16 g_s3h[(size_t)BH_ * M_ * L_]; // softmaxed k3 split
__device__ __align__(16) __nv_bfloat16 g_s3l[(size_t)BH_ * M_ * L_];
__device__ __align__(16) __nv_bfloat16 g_y2th[BH_ * D_ * M_];        // y2^T split [bh][d][m]
__device__ __align__(16) __nv_bfloat16 g_y2tl[BH_ * D_ * M_];

// =====================================================================
// PTX helpers (baseline set only: mma.sync / ldmatrix / cp.async / cvt)
// =====================================================================
__device__ __forceinline__ uint32_t smem_to_u32(const void* p) {
    uint32_t a;
    asm("{ .reg .u64 t; cvta.to.shared.u64 t, %1; cvt.u32.u64 %0, t; }" : "=r"(a) : "l"(p));
    return a;
}
__device__ __forceinline__ void ldsm4(uint32_t* r, uint32_t addr) {
    asm volatile("ldmatrix.sync.aligned.m8n8.x4.shared.b16 {%0,%1,%2,%3}, [%4];"
        : "=r"(r[0]), "=r"(r[1]), "=r"(r[2]), "=r"(r[3]) : "r"(addr));
}
__device__ __forceinline__ void ldsm4t(uint32_t* r, uint32_t addr) {
    asm volatile("ldmatrix.sync.aligned.m8n8.x4.trans.shared.b16 {%0,%1,%2,%3}, [%4];"
        : "=r"(r[0]), "=r"(r[1]), "=r"(r[2]), "=r"(r[3]) : "r"(addr));
}
__device__ __forceinline__ void mma16816(float* d, const uint32_t* a, const uint32_t* b) {
    asm volatile("mma.sync.aligned.m16n8k16.row.col.f32.bf16.bf16.f32 "
        "{%0,%1,%2,%3}, {%4,%5,%6,%7}, {%8,%9}, {%0,%1,%2,%3};"
        : "+f"(d[0]), "+f"(d[1]), "+f"(d[2]), "+f"(d[3])
        : "r"(a[0]), "r"(a[1]), "r"(a[2]), "r"(a[3]), "r"(b[0]), "r"(b[1]));
}
__device__ __forceinline__ void mma_tf32(float* d, const uint32_t* a, const uint32_t* b) {
    asm volatile("mma.sync.aligned.m16n8k8.row.col.f32.tf32.tf32.f32 "
        "{%0,%1,%2,%3}, {%4,%5,%6,%7}, {%8,%9}, {%0,%1,%2,%3};"
        : "+f"(d[0]), "+f"(d[1]), "+f"(d[2]), "+f"(d[3])
        : "r"(a[0]), "r"(a[1]), "r"(a[2]), "r"(a[3]), "r"(b[0]), "r"(b[1]));
}
__device__ __forceinline__ uint32_t f2tf32(float v) {
    uint32_t r;
    asm("cvt.rna.tf32.f32 %0, %1;" : "=r"(r) : "f"(v));
    return r;
}
#define CP_ASYNC16(dst, src) \
    asm volatile("cp.async.cg.shared.global [%0], [%1], 16;" :: "r"(dst), "l"(src))
#define CP_COMMIT()  asm volatile("cp.async.commit_group;" ::: "memory")
#define CP_WAIT(n)   asm volatile("cp.async.wait_group %0;" :: "n"(n) : "memory")

__device__ __forceinline__ void split_bf16(float v, __nv_bfloat16& h, __nv_bfloat16& l) {
    h = __float2bfloat16(v);
    l = __float2bfloat16(v - __bfloat162float(h));
}

// =====================================================================
// conversion kernels (fp32 -> tf32-rounded fp32)
// =====================================================================
__global__ void conv_act3_kernel(const float* __restrict__ s0,
                                 const float* __restrict__ s1,
                                 const float* __restrict__ s2)
{
    int z = blockIdx.y;
    const float* src = (z == 0) ? s0 : ((z == 1) ? s1 : s2);
    size_t i4 = (size_t)blockIdx.x * 256 + threadIdx.x;
    float4 v = *(const float4*)&src[i4 * 4];
    uint4 o;
    o.x = f2tf32(v.x); o.y = f2tf32(v.y); o.z = f2tf32(v.z); o.w = f2tf32(v.w);
    *(uint4*)&g_af[(size_t)z * NTOK_ * DM_ + i4 * 4] = o;
}

__global__ void conv_wt_kernel(const float* __restrict__ W, int slot)
{
    __shared__ float t[32][33];
    int x = blockIdx.x * 32 + threadIdx.x;
    int y = blockIdx.y * 32 + threadIdx.y;
    #pragma unroll
    for (int j = 0; j < 32; j += 8) t[threadIdx.y + j][threadIdx.x] = W[(size_t)(y + j) * 1024 + x];
    __syncthreads();
    int xo = blockIdx.y * 32 + threadIdx.x;
    int yo = blockIdx.x * 32 + threadIdx.y;
    size_t base = (size_t)slot * DM_ * DM_;
    #pragma unroll
    for (int j = 0; j < 32; j += 8) {
        float v = t[threadIdx.x][threadIdx.y + j];
        *(uint32_t*)&g_wf[base + (size_t)(yo + j) * 1024 + xo] = f2tf32(v);
    }
}

// =====================================================================
// projection GEMM — 1-term TF32, BK=32, 2-stage cp.async, 73728 B smem.
// mode = -1: fused QKV (z = blockIdx.z selects A slot z, W slot z, dest q/k/v)
// mode =  3: output projection (A slot 0, W slot 3, fp32 out, bias = b0p)
// smem row pitch 144 B (32 tf32 + 16B pad); stage = A(18432) + B(18432)
// =====================================================================
#define GT_TS   18432
#define GT_STG  (2 * GT_TS)     // 36864 per stage
#define GT_SM   (2 * GT_STG)    // 73728 total

__global__ __launch_bounds__(256) void gemm_tf32_kernel(
    const float* __restrict__ b0p, const float* __restrict__ b1p,
    const float* __restrict__ b2p, float* __restrict__ outp, int mode)
{
    const uint32_t sbase = smem_to_u32(dynsm);

    const int z  = (mode == 3) ? 0 : blockIdx.z;
    const int wz = (mode == 3) ? 3 : z;
    const float* bias = (mode == 3) ? b0p : ((z == 0) ? b0p : ((z == 1) ? b1p : b2p));
    const float* Af = g_af + (size_t)z * NTOK_ * DM_;
    const float* Wf = g_wf + (size_t)wz * DM_ * DM_;

    const int tid  = threadIdx.x;
    const int lane = tid & 31;
    const int w    = tid >> 5;
    const int wm   = w >> 2;
    const int wn   = w & 3;
    const int n0 = blockIdx.x * 128;
    const int m0 = blockIdx.y * 128;

    float acc[4][4][4];
    #pragma unroll
    for (int i = 0; i < 4; i++)
        #pragma unroll
        for (int j = 0; j < 4; j++)
            #pragma unroll
            for (int t = 0; t < 4; t++) acc[i][j][t] = 0.f;

    auto load_chunk = [&](int c, int buf) {
        const int k0 = c * 32;
        const uint32_t sb = sbase + buf * GT_STG;
        #pragma unroll
        for (int i = 0; i < 4; i++) {                  // A: 128 rows x 128 B
            int q = tid + i * 256;                     // 0..1023
            int row = q >> 3, c8 = q & 7;
            uint32_t dst = sb + (uint32_t)(row * 144 + c8 * 16);
            CP_ASYNC16(dst, &Af[(size_t)(m0 + row) * 1024 + k0 + c8 * 4]);
        }
        #pragma unroll
        for (int i = 0; i < 4; i++) {                  // B: 128 rows x 128 B
            int q = tid + i * 256;
            int row = q >> 3, c8 = q & 7;
            uint32_t dst = sb + GT_TS + (uint32_t)(row * 144 + c8 * 16);
            CP_ASYNC16(dst, &Wf[(size_t)(n0 + row) * 1024 + k0 + c8 * 4]);
        }
        CP_COMMIT();
    };

    auto compute_chunk = [&](int buf) {
        const uint32_t S = sbase + buf * GT_STG;
        #pragma unroll
        for (int k8 = 0; k8 < 4; k8++) {
            const uint32_t kb = (uint32_t)(k8 * 32);   // byte offset of this k8 in row
            uint32_t af[4][4];
            #pragma unroll
            for (int mt = 0; mt < 4; mt++) {
                uint32_t addr = S
                    + (uint32_t)((wm * 64 + mt * 16 + (lane & 15)) * 144)
                    + kb + (uint32_t)((lane >> 4) * 16);
                ldsm4(af[mt], addr);
            }
            uint32_t bf[2][4];
            #pragma unroll
            for (int np = 0; np < 2; np++) {
                uint32_t nrow = (uint32_t)(wn * 32 + np * 16 + ((lane >> 4) * 8) + (lane & 7));
                uint32_t addr = S + GT_TS + nrow * 144 + kb
                    + (uint32_t)(((lane >> 3) & 1) * 16);
                ldsm4(bf[np], addr);
            }
            #pragma unroll
            for (int mt = 0; mt < 4; mt++)
                #pragma unroll
                for (int nt = 0; nt < 4; nt++)
                    mma_tf32(acc[mt][nt], af[mt], &bf[nt >> 1][(nt & 1) * 2]);
        }
    };

    // 2-stage pipeline
    load_chunk(0, 0);
    #pragma unroll 1
    for (int c = 0; c < 32; c++) {
        if (c + 1 < 32) {
            load_chunk(c + 1, (c + 1) & 1);
            CP_WAIT(1);
        } else {
            CP_WAIT(0);
        }
        __syncthreads();
        compute_chunk(c & 1);
        __syncthreads();
    }

    #pragma unroll
    for (int mt = 0; mt < 4; mt++) {
        #pragma unroll
        for (int nt = 0; nt < 4; nt++) {
            int c = n0 + wn * 32 + nt * 8 + (lane & 3) * 2;
            float b0 = bias[c], b1 = bias[c + 1];
            #pragma unroll
            for (int half = 0; half < 2; half++) {
                int r = m0 + wm * 64 + mt * 16 + (lane >> 2) + half * 8;
                float vx = acc[mt][nt][half * 2 + 0] + b0;
                float vy = acc[mt][nt][half * 2 + 1] + b1;
                if (mode == 3) {
                    float2 t = {vx, vy};
                    *(float2*)&outp[(size_t)r * 1024 + c] = t;
                } else {
                    __nv_bfloat16* dh = (z == 0) ? g_qh : ((z == 1) ? g_kh : g_vh);
                    __nv_bfloat16* dl = (z == 0) ? g_ql : ((z == 1) ? g_kl : g_vl);
                    int b = r >> 12, l = r & 4095;
                    int h = c >> 6, d = c & 63;
                    size_t o = (((size_t)(b * 16 + h) * 4096) + l) * 64 + d;
                    __nv_bfloat16 hp[2], lp[2];
                    split_bf16(vx, hp[0], lp[0]);
                    split_bf16(vy, hp[1], lp[1]);
                    *(uint32_t*)&dh[o] = *(uint32_t*)hp;
                    *(uint32_t*)&dl[o] = *(uint32_t*)lp;
                }
            }
        }
    }
}

// =====================================================================
// landmark pooling from split q/k; writes fp32 + split landmarks
// =====================================================================
__global__ void pool_kernel()
{
    int idx = blockIdx.x * blockDim.x + threadIdx.x;   // BH*M*D
    int d  = idx & 63;
    int m  = (idx >> 6) & 127;
    int bh = idx >> 13;
    size_t base = ((size_t)bh * L_ + m * SEG_) * D_ + d;
    float sq = 0.f, sk = 0.f;
    #pragma unroll
    for (int s = 0; s < SEG_; s++) {
        sq += __bfloat162float(g_qh[base + s * D_]) + __bfloat162float(g_ql[base + s * D_]);
        sk += __bfloat162float(g_kh[base + s * D_]) + __bfloat162float(g_kl[base + s * D_]);
    }
    float mq = sq * (1.f / SEG_), mk = sk * (1.f / SEG_);
    g_Ql[idx] = mq; g_Kl[idx] = mk;
    __nv_bfloat16 h, l;
    split_bf16(mq, h, l); g_Qlh[idx] = h; g_Qll[idx] = l;
    split_bf16(mk, h, l); g_Klh[idx] = h; g_Kll[idx] = l;
}

// =====================================================================
// k1: C[128 tok][128 lm] = q_blk @ Kl^T (split mma) + fused softmax -> split bf16
// =====================================================================
__global__ __launch_bounds__(256) void k1_mma_kernel()
{
    char* sm = dynsm;
    const uint32_t sb = smem_to_u32(sm);
    int bh = blockIdx.y, l0 = blockIdx.x * 128, tid = threadIdx.x;
    int lane = tid & 31, w = tid >> 5;

    {
        const __nv_bfloat16* qh = g_qh + ((size_t)bh * L_ + l0) * D_;
        const __nv_bfloat16* ql = g_ql + ((size_t)bh * L_ + l0) * D_;
        const __nv_bfloat16* kh = g_Klh + bh * (M_ * D_);
        const __nv_bfloat16* kl = g_Kll + bh * (M_ * D_);
        #pragma unroll
        for (int i = 0; i < 4; i++) {
            int q = tid + i * 256;
            int row = q >> 3, c8 = q & 7;
            uint32_t so = (uint32_t)(row * 144 + c8 * 16);
            size_t go = (size_t)row * 64 + c8 * 8;
            *(uint4*)(sm + 0     + so) = *(const uint4*)&qh[go];
            *(uint4*)(sm + 18432 + so) = *(const uint4*)&ql[go];
            *(uint4*)(sm + 36864 + so) = *(const uint4*)&kh[go];
            *(uint4*)(sm + 55296 + so) = *(const uint4*)&kl[go];
        }
    }
    __syncthreads();

    int wm = w >> 2, wn = w & 3;
    float acc[4][4][4];
    #pragma unroll
    for (int i = 0; i < 4; i++)
        #pragma unroll
        for (int j = 0; j < 4; j++)
            #pragma unroll
            for (int t = 0; t < 4; t++) acc[i][j][t] = 0.f;

    #pragma unroll
    for (int k16 = 0; k16 < 4; k16++) {
        uint32_t af[2][4][4];
        #pragma unroll
        for (int term = 0; term < 2; term++)
            #pragma unroll
            for (int mt = 0; mt < 4; mt++) {
                uint32_t addr = sb + term * 18432
                    + (uint32_t)((wm * 64 + mt * 16 + (lane & 15)) * 144)
                    + (uint32_t)(k16 * 32) + (uint32_t)((lane >> 4) * 16);
                ldsm4(af[term][mt], addr);
            }
        uint32_t bf[2][2][4];
        #pragma unroll
        for (int term = 0; term < 2; term++)
            #pragma unroll
            for (int np = 0; np < 2; np++) {
                uint32_t nrow = (uint32_t)(wn * 32 + np * 16 + ((lane >> 4) * 8) + (lane & 7));
                uint32_t addr = sb + 36864 + term * 18432 + nrow * 144
                    + (uint32_t)(k16 * 32) + (uint32_t)(((lane >> 3) & 1) * 16);
                ldsm4(bf[term][np], addr);
            }
        #pragma unroll
        for (int mt = 0; mt < 4; mt++)
            #pragma unroll
            for (int nt = 0; nt < 4; nt++) {
                float* d = acc[mt][nt];
                const uint32_t* bh_ = &bf[0][nt >> 1][(nt & 1) * 2];
                const uint32_t* bl_ = &bf[1][nt >> 1][(nt & 1) * 2];
                mma16816(d, af[0][mt], bh_);
                mma16816(d, af[0][mt], bl_);
                mma16816(d, af[1][mt], bh_);
            }
    }
    __syncthreads();

    float* S = (float*)sm;
    #pragma unroll
    for (int mt = 0; mt < 4; mt++)
        #pragma unroll
        for (int nt = 0; nt < 4; nt++)
            #pragma unroll
            for (int half = 0; half < 2; half++) {
                int row = wm * 64 + mt * 16 + (lane >> 2) + half * 8;
                int col = wn * 32 + nt * 8 + (lane & 3) * 2;
                S[row * 128 + col]     = acc[mt][nt][half * 2 + 0];
                S[row * 128 + col + 1] = acc[mt][nt][half * 2 + 1];
            }
    __syncthreads();

    for (int rr = 0; rr < 16; rr++) {
        int row = w * 16 + rr;
        float x0 = S[row * 128 + lane],      x1 = S[row * 128 + lane + 32];
        float x2 = S[row * 128 + lane + 64], x3 = S[row * 128 + lane + 96];
        float mx = fmaxf(fmaxf(x0, x1), fmaxf(x2, x3));
        #pragma unroll
        for (int o = 16; o; o >>= 1) mx = fmaxf(mx, __shfl_xor_sync(0xffffffffu, mx, o));
        float e0 = __expf(x0 - mx), e1 = __expf(x1 - mx);
        float e2 = __expf(x2 - mx), e3 = __expf(x3 - mx);
        float s = e0 + e1 + e2 + e3;
        #pragma unroll
        for (int o = 16; o; o >>= 1) s += __shfl_xor_sync(0xffffffffu, s, o);
        float inv = 1.f / s;
        size_t ob = ((size_t)bh * L_ + l0 + row) * 128;
        float vv[4] = {e0 * inv, e1 * inv, e2 * inv, e3 * inv};
        #pragma unroll
        for (int j = 0; j < 4; j++) {
            __nv_bfloat16 h, l; split_bf16(vv[j], h, l);
            g_k1h[ob + lane + 32 * j] = h;
            g_k1l[ob + lane + 32 * j] = l;
        }
    }
}

// =====================================================================
// k3 scores: C[m=128][l=128 blk] = Ql @ k_blk^T (split mma) -> raw fp32 g_k3
// =====================================================================
__global__ __launch_bounds__(256) void k3score_mma_kernel()
{
    char* sm = dynsm;
    const uint32_t sb = smem_to_u32(sm);
    int bh = blockIdx.y, l0 = blockIdx.x * 128, tid = threadIdx.x;
    int lane = tid & 31, w = tid >> 5;

    {
        const __nv_bfloat16* ah = g_Qlh + bh * (M_ * D_);
        const __nv_bfloat16* al = g_Qll + bh * (M_ * D_);
        const __nv_bfloat16* bhp = g_kh + ((size_t)bh * L_ + l0) * D_;
        const __nv_bfloat16* blp = g_kl + ((size_t)bh * L_ + l0) * D_;
        #pragma unroll
        for (int i = 0; i < 4; i++) {
            int q = tid + i * 256;
            int row = q >> 3, c8 = q & 7;
            uint32_t so = (uint32_t)(row * 144 + c8 * 16);
            size_t go = (size_t)row * 64 + c8 * 8;
            *(uint4*)(sm + 0     + so) = *(const uint4*)&ah[go];
            *(uint4*)(sm + 18432 + so) = *(const uint4*)&al[go];
            *(uint4*)(sm + 36864 + so) = *(const uint4*)&bhp[go];
            *(uint4*)(sm + 55296 + so) = *(const uint4*)&blp[go];
        }
    }
    __syncthreads();

    int wm = w >> 2, wn = w & 3;
    float acc[4][4][4];
    #pragma unroll
    for (int i = 0; i < 4; i++)
        #pragma unroll
        for (int j = 0; j < 4; j++)
            #pragma unroll
            for (int t = 0; t < 4; t++) acc[i][j][t] = 0.f;

    #pragma unroll
    for (int k16 = 0; k16 < 4; k16++) {
        uint32_t af[2][4][4];
        #pragma unroll
        for (int term = 0; term < 2; term++)
            #pragma unroll
            for (int mt = 0; mt < 4; mt++) {
                uint32_t addr = sb + term * 18432
                    + (uint32_t)((wm * 64 + mt * 16 + (lane & 15)) * 144)
                    + (uint32_t)(k16 * 32) + (uint32_t)((lane >> 4) * 16);
                ldsm4(af[term][mt], addr);
            }
        uint32_t bf[2][2][4];
        #pragma unroll
        for (int term = 0; term < 2; term++)
            #pragma unroll
            for (int np = 0; np < 2; np++) {
                uint32_t nrow = (uint32_t)(wn * 32 + np * 16 + ((lane >> 4) * 8) + (lane & 7));
                uint32_t addr = sb + 36864 + term * 18432 + nrow * 144
                    + (uint32_t)(k16 * 32) + (uint32_t)(((lane >> 3) & 1) * 16);
                ldsm4(bf[term][np], addr);
            }
        #pragma unroll
        for (int mt = 0; mt < 4; mt++)
            #pragma unroll
            for (int nt = 0; nt < 4; nt++) {
                float* d = acc[mt][nt];
                const uint32_t* bh_ = &bf[0][nt >> 1][(nt & 1) * 2];
                const uint32_t* bl_ = &bf[1][nt >> 1][(nt & 1) * 2];
                mma16816(d, af[0][mt], bh_);
                mma16816(d, af[0][mt], bl_);
                mma16816(d, af[1][mt], bh_);
            }
    }

    float* o = g_k3 + (size_t)bh * M_ * L_;
    #pragma unroll
    for (int mt = 0; mt < 4; mt++)
        #pragma unroll
        for (int nt = 0; nt < 4; nt++)
            #pragma unroll
            for (int half = 0; half < 2; half++) {
                int m_r = wm * 64 + mt * 16 + (lane >> 2) + half * 8;
                int l_c = l0 + wn * 32 + nt * 8 + (lane & 3) * 2;
                float2 t = {acc[mt][nt][half * 2 + 0], acc[mt][nt][half * 2 + 1]};
                *(float2*)&o[(size_t)m_r * L_ + l_c] = t;
            }
}

// =====================================================================
// row softmax over 4096; reads fp32 g_k3, writes split bf16 g_s3
// =====================================================================
__global__ __launch_bounds__(256) void softmax4096_kernel()
{
    size_t row = blockIdx.x;
    const float* p = g_k3 + row * 4096;
    int tid = threadIdx.x;
    float v[16];
    float mx = -1e30f;
    #pragma unroll
    for (int i = 0; i < 4; i++) {
        float4 t = *(const float4*)&p[i * 1024 + tid * 4];
        v[i * 4 + 0] = t.x; v[i * 4 + 1] = t.y; v[i * 4 + 2] = t.z; v[i * 4 + 3] = t.w;
        mx = fmaxf(mx, fmaxf(fmaxf(t.x, t.y), fmaxf(t.z, t.w)));
    }
    __shared__ float smx[8], ssm[8], sres;
    #pragma unroll
    for (int o = 16; o; o >>= 1) mx = fmaxf(mx, __shfl_xor_sync(0xffffffffu, mx, o));
    if ((tid & 31) == 0) smx[tid >> 5] = mx;
    __syncthreads();
    if (tid == 0) {
        float m = smx[0];
        #pragma unroll
        for (int i = 1; i < 8; i++) m = fmaxf(m, smx[i]);
        sres = m;
    }
    __syncthreads();
    float MX = sres;
    float s = 0.f;
    #pragma unroll
    for (int i = 0; i < 16; i++) { v[i] = __expf(v[i] - MX); s += v[i]; }
    #pragma unroll
    for (int o = 16; o; o >>= 1) s += __shfl_xor_sync(0xffffffffu, s, o);
    if ((tid & 31) == 0) ssm[tid >> 5] = s;
    __syncthreads();
    if (tid == 0) {
        float t = 0.f;
        #pragma unroll
        for (int i = 0; i < 8; i++) t += ssm[i];
        sres = 1.f / t;
    }
    __syncthreads();
    float inv = sres;
    #pragma unroll
    for (int i = 0; i < 4; i++) {
        __nv_bfloat16 hh[4], ll[4];
        #pragma unroll
        for (int t = 0; t < 4; t++) split_bf16(v[i * 4 + t] * inv, hh[t], ll[t]);
        *(uint2*)&g_s3h[row * 4096 + i * 1024 + tid * 4] = *(uint2*)hh;
        *(uint2*)&g_s3l[row * 4096 + i * 1024 + tid * 4] = *(uint2*)ll;
    }
}

// =====================================================================
// kernel_2 = softmax(Q_l @ K_l^T) fused (fp32, tiny). block per head.
// =====================================================================
__global__ __launch_bounds__(256) void k2_kernel()
{
    float* sm = (float*)dynsm;
    float* Qlt = sm;
    float* Klt = sm + 8192;
    float* S   = sm + 16384;
    int bh = blockIdx.x, tid = threadIdx.x;

    const float* Ql = g_Ql + bh * 8192;
    const float* Kl = g_Kl + bh * 8192;
    #pragma unroll
    for (int i = 0; i < 8; i++) {
        int f = i * 1024 + tid * 4; int m = f >> 6, d0 = f & 63;
        float4 tq = *(const float4*)&Ql[f];
        float4 tk = *(const float4*)&Kl[f];
        Qlt[(d0 + 0) * 128 + m] = tq.x; Qlt[(d0 + 1) * 128 + m] = tq.y;
        Qlt[(d0 + 2) * 128 + m] = tq.z; Qlt[(d0 + 3) * 128 + m] = tq.w;
        Klt[(d0 + 0) * 128 + m] = tk.x; Klt[(d0 + 1) * 128 + m] = tk.y;
        Klt[(d0 + 2) * 128 + m] = tk.z; Klt[(d0 + 3) * 128 + m] = tk.w;
    }
    __syncthreads();

    int tm = tid >> 4, tn = tid & 15;
    float acc[8][8] = {};
    for (int d = 0; d < 64; d++) {
        float4 a0 = *(const float4*)&Qlt[d * 128 + tm * 8];
        float4 a1 = *(const float4*)&Qlt[d * 128 + tm * 8 + 4];
        float4 b0 = *(const float4*)&Klt[d * 128 + tn * 8];
        float4 b1 = *(const float4*)&Klt[d * 128 + tn * 8 + 4];
        float av[8] = {a0.x, a0.y, a0.z, a0.w, a1.x, a1.y, a1.z, a1.w};
        float bv[8] = {b0.x, b0.y, b0.z, b0.w, b1.x, b1.y, b1.z, b1.w};
        #pragma unroll
        for (int i = 0; i < 8; i++)
            #pragma unroll
            for (int j = 0; j < 8; j++) acc[i][j] += av[i] * bv[j];
    }
    #pragma unroll
    for (int i = 0; i < 8; i++)
        #pragma unroll
        for (int j = 0; j < 8; j++) S[(tm * 8 + i) * 128 + tn * 8 + j] = acc[i][j];
    __syncthreads();

    int lane = tid & 31, w = tid >> 5;
    for (int rr = 0; rr < 16; rr++) {
        int row = w * 16 + rr;
        float x0 = S[row * 128 + lane],      x1 = S[row * 128 + lane + 32];
        float x2 = S[row * 128 + lane + 64], x3 = S[row * 128 + lane + 96];
        float mx = fmaxf(fmaxf(x0, x1), fmaxf(x2, x3));
        #pragma unroll
        for (int o = 16; o; o >>= 1) mx = fmaxf(mx, __shfl_xor_sync(0xffffffffu, mx, o));
        float e0 = __expf(x0 - mx), e1 = __expf(x1 - mx);
        float e2 = __expf(x2 - mx), e3 = __expf(x3 - mx);
        float s = e0 + e1 + e2 + e3;
        #pragma unroll
        for (int o = 16; o; o >>= 1) s += __shfl_xor_sync(0xffffffffu, s, o);
        float inv = 1.f / s;
        float* o = g_k2 + bh * 16384 + row * 128;
        o[lane] = e0 * inv; o[lane + 32] = e1 * inv; o[lane + 64] = e2 * inv; o[lane + 96] = e3 * inv;
    }
}

// =====================================================================
// V0 = K^T / max(colsum(K))
// =====================================================================
__global__ __launch_bounds__(256) void vinit_kernel()
{
    int bh = blockIdx.x, tid = threadIdx.x;
    const float* K = g_k2 + bh * 16384;
    __shared__ float cs[128];
    __shared__ float sscale;
    if (tid < 128) {
        float s = 0.f;
        for (int r = 0; r < 128; r++) s += K[r * 128 + tid];
        cs[tid] = s;
    }
    __syncthreads();
    if (tid == 0) {
        float m = cs[0];
        for (int i = 1; i < 128; i++) m = fmaxf(m, cs[i]);
        sscale = 1.f / m;
    }
    __syncthreads();
    float scale = sscale;
    for (int f = tid; f < 16384; f += 256) {
        int i = f >> 7, j = f & 127;
        g_Va[bh * 16384 + f] = scale * K[j * 128 + i];
    }
}

// =====================================================================
// batched 128x128 bmm for Newton-Schulz (fp32)
// =====================================================================
__device__ __forceinline__ float* bufsel(int s)
{
    switch (s) {
        case 0: return g_k2; case 1: return g_P; case 2: return g_M1;
        case 3: return g_M2; case 4: return g_Va; default: return g_Vb;
    }
}

__global__ __launch_bounds__(256) void bmm_kernel(int as, int bs, int cs2, int os,
                                                  float alpha, float beta)
{
    float* sm = (float*)dynsm;
    float* Bs = sm;
    float* At = sm + 16384;
    int bh = blockIdx.y, r0 = blockIdx.x * 32, tid = threadIdx.x;
    const float* A  = bufsel(as)  + bh * 16384;
    const float* Bm = bufsel(bs)  + bh * 16384;
    const float* C  = bufsel(cs2) + bh * 16384;
    float* O        = bufsel(os)  + bh * 16384;

    #pragma unroll
    for (int i = 0; i < 16; i++) {
        int f = i * 1024 + tid * 4;
        *(float4*)&Bs[f] = *(const float4*)&Bm[f];
    }
    #pragma unroll
    for (int i = 0; i < 4; i++) {
        int f = i * 1024 + tid * 4; int r = f >> 7, k0 = f & 127;
        float4 t = *(const float4*)&A[(r0 + r) * 128 + k0];
        At[(k0 + 0) * 32 + r] = t.x; At[(k0 + 1) * 32 + r] = t.y;
        At[(k0 + 2) * 32 + r] = t.z; At[(k0 + 3) * 32 + r] = t.w;
    }
    __syncthreads();

    int rb = (tid >> 5) * 4, cb = (tid & 31) * 4;
    float acc[4][4] = {};
    for (int k = 0; k < 128; k++) {
        float a0 = At[k * 32 + rb + 0], a1 = At[k * 32 + rb + 1];
        float a2 = At[k * 32 + rb + 2], a3 = At[k * 32 + rb + 3];
        float4 b = *(const float4*)&Bs[k * 128 + cb];
        acc[0][0] += a0 * b.x; acc[0][1] += a0 * b.y; acc[0][2] += a0 * b.z; acc[0][3] += a0 * b.w;
        acc[1][0] += a1 * b.x; acc[1][1] += a1 * b.y; acc[1][2] += a1 * b.z; acc[1][3] += a1 * b.w;
        acc[2][0] += a2 * b.x; acc[2][1] += a2 * b.y; acc[2][2] += a2 * b.z; acc[2][3] += a2 * b.w;
        acc[3][0] += a3 * b.x; acc[3][1] += a3 * b.y; acc[3][2] += a3 * b.z; acc[3][3] += a3 * b.w;
    }
    #pragma unroll
    for (int i = 0; i < 4; i++)
        #pragma unroll
        for (int j = 0; j < 4; j++) {
            int idx = (r0 + rb + i) * 128 + cb + j;
            O[idx] = alpha * acc[i][j] + beta * C[idx];
        }
}

// =====================================================================
// k3v: partial C[m=128][d=64] = softmax(k3)_split @ v_split (mma, split-K 4)
// 2-stage pipeline. dyn smem 110592
// =====================================================================
#define KV_STG 55296

__global__ __launch_bounds__(256) void k3v_mma_kernel()
{
    char* sm = dynsm;
    const uint32_t sb = smem_to_u32(sm);
    int s = blockIdx.x, bh = blockIdx.y, tid = threadIdx.x;
    int lane = tid & 31, w = tid >> 5;
    int wm = w >> 1, wn = w & 1;
    const size_t abase = (size_t)bh * M_ * L_;
    const size_t vbase = (size_t)bh * L_ * D_;

    float acc[2][4][4];
    #pragma unroll
    for (int i = 0; i < 2; i++)
        #pragma unroll
        for (int j = 0; j < 4; j++)
            #pragma unroll
            for (int t = 0; t < 4; t++) acc[i][j][t] = 0.f;

    auto load = [&](int ck, int buf) {
        int k0 = s * 1024 + ck * 64;
        uint32_t S = sb + buf * KV_STG;
        #pragma unroll
        for (int i = 0; i < 8; i++) {
            int q = tid + i * 256;
            int arr = q >> 10, row = (q >> 3) & 127, c8 = q & 7;
            uint32_t dst = S + arr * 18432 + (uint32_t)(row * 144 + c8 * 16);
            const __nv_bfloat16* src = (arr ? g_s3l : g_s3h) + abase + (size_t)row * L_ + k0 + c8 * 8;
            CP_ASYNC16(dst, src);
        }
        #pragma unroll
        for (int i = 0; i < 4; i++) {
            int q = tid + i * 256;
            int arr = q >> 9, row = (q >> 3) & 63, c8 = q & 7;
            uint32_t dst = S + 36864 + arr * 9216 + (uint32_t)(row * 144 + c8 * 16);
            const __nv_bfloat16* src = (arr ? g_vl : g_vh) + vbase + (size_t)(k0 + row) * D_ + c8 * 8;
            CP_ASYNC16(dst, src);
        }
        CP_COMMIT();
    };

    auto compute = [&](int buf) {
        uint32_t S = sb + buf * KV_STG;
        #pragma unroll
        for (int k16 = 0; k16 < 4; k16++) {
            uint32_t af[2][2][4];
            #pragma unroll
            for (int term = 0; term < 2; term++)
                #pragma unroll
                for (int mt = 0; mt < 2; mt++) {
                    uint32_t addr = S + term * 18432
                        + (uint32_t)((wm * 32 + mt * 16 + (lane & 15)) * 144)
                        + (uint32_t)(k16 * 32) + (uint32_t)((lane >> 4) * 16);
                    ldsm4(af[term][mt], addr);
                }
            uint32_t bf[2][2][4];
            #pragma unroll
            for (int term = 0; term < 2; term++)
                #pragma unroll
                for (int np = 0; np < 2; np++) {
                    uint32_t addr = S + 36864 + term * 9216
                        + (uint32_t)((k16 * 16 + (lane & 15)) * 144)
                        + (uint32_t)((wn * 32 + np * 16 + (lane >> 4) * 8) * 2);
                    ldsm4t(bf[term][np], addr);
                }
            #pragma unroll
            for (int mt = 0; mt < 2; mt++)
                #pragma unroll
                for (int nt = 0; nt < 4; nt++) {
                    float* d = acc[mt][nt];
                    const uint32_t* bh_ = &bf[0][nt >> 1][(nt & 1) * 2];
                    const uint32_t* bl_ = &bf[1][nt >> 1][(nt & 1) * 2];
                    mma16816(d, af[0][mt], bh_);
                    mma16816(d, af[0][mt], bl_);
                    mma16816(d, af[1][mt], bh_);
                }
        }
    };

    load(0, 0);
    #pragma unroll 1
    for (int ck = 0; ck < 16; ck++) {
        if (ck + 1 < 16) {
            load(ck + 1, (ck + 1) & 1);
            CP_WAIT(1);
        } else {
            CP_WAIT(0);
        }
        __syncthreads();
        compute(ck & 1);
        __syncthreads();
    }

    #pragma unroll
    for (int mt = 0; mt < 2; mt++)
        #pragma unroll
        for (int nt = 0; nt < 4; nt++)
            #pragma unroll
            for (int half = 0; half < 2; half++) {
                int m_r = wm * 32 + mt * 16 + (lane >> 2) + half * 8;
                int d_c = wn * 32 + nt * 8 + (lane & 3) * 2;
                float2 t = {acc[mt][nt][half * 2 + 0], acc[mt][nt][half * 2 + 1]};
                *(float2*)&g_k3v_part[((size_t)(s * 64 + bh) * 128 + m_r) * 64 + d_c] = t;
            }
}

// =====================================================================
// y2 = inv(g_Va) @ sum(k3v parts) per head (fp32); emits y2^T split bf16
// =====================================================================
__global__ __launch_bounds__(256) void y2_kernel()
{
    float* sm = (float*)dynsm;
    float* At = sm;
    float* Bs = sm + 16384;
    int bh = blockIdx.x, tid = threadIdx.x;
    const float* inv = g_Va + bh * 16384;

    #pragma unroll
    for (int i = 0; i < 16; i++) {
        int f = i * 1024 + tid * 4; int r = f >> 7, k0 = f & 127;
        float4 t = *(const float4*)&inv[f];
        At[(k0 + 0) * 128 + r] = t.x; At[(k0 + 1) * 128 + r] = t.y;
        At[(k0 + 2) * 128 + r] = t.z; At[(k0 + 3) * 128 + r] = t.w;
    }
    #pragma unroll
    for (int i = 0; i < 8; i++) {
        int f = i * 1024 + tid * 4;
        size_t o = (size_t)bh * 8192 + f;
        float4 a = *(const float4*)&g_k3v_part[o];
        float4 b = *(const float4*)&g_k3v_part[o + 524288];
        float4 c = *(const float4*)&g_k3v_part[o + 2 * 524288];
        float4 d = *(const float4*)&g_k3v_part[o + 3 * 524288];
        float4 t = {a.x + b.x + c.x + d.x, a.y + b.y + c.y + d.y,
                    a.z + b.z + c.z + d.z, a.w + b.w + c.w + d.w};
        *(float4*)&Bs[f] = t;
    }
    __syncthreads();

    int rt = tid >> 4, ct = tid & 15;
    float acc[8][4] = {};
    for (int k = 0; k < 128; k++) {
        float4 a0 = *(const float4*)&At[k * 128 + rt * 8];
        float4 a1 = *(const float4*)&At[k * 128 + rt * 8 + 4];
        float4 b  = *(const float4*)&Bs[k * 64 + ct * 4];
        float av[8] = {a0.x, a0.y, a0.z, a0.w, a1.x, a1.y, a1.z, a1.w};
        #pragma unroll
        for (int i = 0; i < 8; i++) {
            acc[i][0] += av[i] * b.x; acc[i][1] += av[i] * b.y;
            acc[i][2] += av[i] * b.z; acc[i][3] += av[i] * b.w;
        }
    }
    #pragma unroll
    for (int i = 0; i < 8; i++)
        #pragma unroll
        for (int j = 0; j < 4; j++) {
            __nv_bfloat16 h, l; split_bf16(acc[i][j], h, l);
            size_t o = (size_t)bh * 8192 + (ct * 4 + j) * 128 + rt * 8 + i;
            g_y2th[o] = h;
            g_y2tl[o] = l;
        }
}

// =====================================================================
// x1: C[l=128][d=64] = kernel1_split @ y2t_split (mma) -> g_af slot 0 (tf32)
// =====================================================================
__global__ __launch_bounds__(256) void x1_mma_kernel()
{
    char* sm = dynsm;
    const uint32_t sb = smem_to_u32(sm);
    int bh = blockIdx.y, l0 = blockIdx.x * 128, tid = threadIdx.x;
    int lane = tid & 31, w = tid >> 5;
    int wm = w >> 1, wn = w & 1;

    {
        const __nv_bfloat16* ah = g_k1h + ((size_t)bh * L_ + l0) * 128;
        const __nv_bfloat16* al = g_k1l + ((size_t)bh * L_ + l0) * 128;
        #pragma unroll
        for (int i = 0; i < 16; i++) {
            int q = tid + i * 256;
            int arr = q >> 11, row = (q >> 4) & 127, c16 = q & 15;
            uint32_t so = (uint32_t)(arr * 34816 + row * 272 + c16 * 16);
            const __nv_bfloat16* src = (arr ? al : ah) + (size_t)row * 128 + c16 * 8;
            *(uint4*)(sm + so) = *(const uint4*)src;
        }
        const __nv_bfloat16* bhp = g_y2th + (size_t)bh * 8192;
        const __nv_bfloat16* blp = g_y2tl + (size_t)bh * 8192;
        #pragma unroll
        for (int i = 0; i < 8; i++) {
            int q = tid + i * 256;
            int arr = q >> 10, row = (q >> 4) & 63, c16 = q & 15;
            uint32_t so = (uint32_t)(69632 + arr * 17408 + row * 272 + c16 * 16);
            const __nv_bfloat16* src = (arr ? blp : bhp) + (size_t)row * 128 + c16 * 8;
            *(uint4*)(sm + so) = *(const uint4*)src;
        }
    }
    __syncthreads();

    float acc[2][4][4];
    #pragma unroll
    for (int i = 0; i < 2; i++)
        #pragma unroll
        for (int j = 0; j < 4; j++)
            #pragma unroll
            for (int t = 0; t < 4; t++) acc[i][j][t] = 0.f;

    #pragma unroll
    for (int k16 = 0; k16 < 8; k16++) {
        uint32_t af[2][2][4];
        #pragma unroll
        for (int term = 0; term < 2; term++)
            #pragma unroll
            for (int mt = 0; mt < 2; mt++) {
                uint32_t addr = sb + term * 34816
                    + (uint32_t)((wm * 32 + mt * 16 + (lane & 15)) * 272)
                    + (uint32_t)(k16 * 32) + (uint32_t)((lane >> 4) * 16);
                ldsm4(af[term][mt], addr);
            }
        uint32_t bf[2][2][4];
        #pragma unroll
        for (int term = 0; term < 2; term++)
            #pragma unroll
            for (int np = 0; np < 2; np++) {
                uint32_t nrow = (uint32_t)(wn * 32 + np * 16 + ((lane >> 4) * 8) + (lane & 7));
                uint32_t addr = sb + 69632 + term * 17408 + nrow * 272
                    + (uint32_t)(k16 * 32) + (uint32_t)(((lane >> 3) & 1) * 16);
                ldsm4(bf[term][np], addr);
            }
        #pragma unroll
        for (int mt = 0; mt < 2; mt++)
            #pragma unroll
            for (int nt = 0; nt < 4; nt++) {
                float* d = acc[mt][nt];
                const uint32_t* bh_ = &bf[0][nt >> 1][(nt & 1) * 2];
                const uint32_t* bl_ = &bf[1][nt >> 1][(nt & 1) * 2];
                mma16816(d, af[0][mt], bh_);
                mma16816(d, af[0][mt], bl_);
                mma16816(d, af[1][mt], bh_);
            }
    }

    int b = bh >> 4, h = bh & 15;
    #pragma unroll
    for (int mt = 0; mt < 2; mt++)
        #pragma unroll
        for (int nt = 0; nt < 4; nt++)
            #pragma unroll
            for (int half = 0; half < 2; half++) {
                int l = l0 + wm * 32 + mt * 16 + (lane >> 2) + half * 8;
                int d_c = wn * 32 + nt * 8 + (lane & 3) * 2;
                size_t o = ((size_t)(b * L_ + l)) * DM_ + h * 64 + d_c;
                uint2 t;
                t.x = f2tf32(acc[mt][nt][half * 2 + 0]);
                t.y = f2tf32(acc[mt][nt][half * 2 + 1]);
                *(uint2*)&g_af[o] = t;
            }
}

// =====================================================================
// launch — capture-legal fork/join: side stream always enters capture via
// an event recorded on the origin stream FIRST.
// =====================================================================
extern "C" void kernel_launch(void* const* d_in, const int* in_sizes, int n_in,
                              void* d_out, int out_size)
{
    const float* queries = (const float*)d_in[0];
    const float* keys    = (const float*)d_in[1];
    const float* values  = (const float*)d_in[2];
    const float* Wq = (const float*)d_in[3];
    const float* bq = (const float*)d_in[4];
    const float* Wk = (const float*)d_in[5];
    const float* bk = (const float*)d_in[6];
    const float* Wv = (const float*)d_in[7];
    const float* bv = (const float*)d_in[8];
    const float* Wo = (const float*)d_in[9];
    const float* bo = (const float*)d_in[10];
    float* out = (float*)d_out;

    cudaFuncSetAttribute(gemm_tf32_kernel,   cudaFuncAttributeMaxDynamicSharedMemorySize, GT_SM);
    cudaFuncSetAttribute(k1_mma_kernel,      cudaFuncAttributeMaxDynamicSharedMemorySize, 73728);
    cudaFuncSetAttribute(k3score_mma_kernel, cudaFuncAttributeMaxDynamicSharedMemorySize, 73728);
    cudaFuncSetAttribute(k3v_mma_kernel,     cudaFuncAttributeMaxDynamicSharedMemorySize, 110592);
    cudaFuncSetAttribute(x1_mma_kernel,      cudaFuncAttributeMaxDynamicSharedMemorySize, 104448);
    cudaFuncSetAttribute(k2_kernel,          cudaFuncAttributeMaxDynamicSharedMemorySize, 131072);
    cudaFuncSetAttribute(bmm_kernel,         cudaFuncAttributeMaxDynamicSharedMemorySize, 81920);
    cudaFuncSetAttribute(y2_kernel,          cudaFuncAttributeMaxDynamicSharedMemorySize, 98304);

    static cudaStream_t s_b = nullptr;
    static cudaEvent_t ev_start = nullptr, ev_wt = nullptr, ev_fork = nullptr, ev_join = nullptr;
    if (!s_b) {
        cudaStreamCreateWithFlags(&s_b, cudaStreamNonBlocking);
        cudaEventCreateWithFlags(&ev_start, cudaEventDisableTiming);
        cudaEventCreateWithFlags(&ev_wt,    cudaEventDisableTiming);
        cudaEventCreateWithFlags(&ev_fork,  cudaEventDisableTiming);
        cudaEventCreateWithFlags(&ev_join,  cudaEventDisableTiming);
    }

    dim3 wt_grid(32, 32), wt_blk(32, 8);

    // fork side stream INTO the capture before any s_b work
    cudaEventRecord(ev_start, 0);
    cudaStreamWaitEvent(s_b, ev_start, 0);

    // weight conversions on side stream, activation conversion on main
    conv_wt_kernel<<<wt_grid, wt_blk, 0, s_b>>>(Wq, 0);
    conv_wt_kernel<<<wt_grid, wt_blk, 0, s_b>>>(Wk, 1);
    conv_wt_kernel<<<wt_grid, wt_blk, 0, s_b>>>(Wv, 2);
    conv_wt_kernel<<<wt_grid, wt_blk, 0, s_b>>>(Wo, 3);
    cudaEventRecord(ev_wt, s_b);
    conv_act3_kernel<<<dim3(16384, 3), 256>>>(queries, keys, values);
    cudaStreamWaitEvent(0, ev_wt, 0);

    // fused QKV projection (tf32 1-term)
    gemm_tf32_kernel<<<dim3(8, 128, 3), 256, GT_SM>>>(bq, bk, bv, nullptr, -1);

    // landmarks (both branches depend on this)
    pool_kernel<<<2048, 256>>>();

    // ---- fork: Newton-Schulz chain on side stream ----
    cudaEventRecord(ev_fork, 0);
    cudaStreamWaitEvent(s_b, ev_fork, 0);
    k2_kernel<<<64, 256, 131072, s_b>>>();
    vinit_kernel<<<64, 256, 0, s_b>>>();
    {
        int cur = 4, nxt = 5;
        for (int it = 0; it < 6; it++) {
            bmm_kernel<<<dim3(4, 64), 256, 81920, s_b>>>(0,   cur, 0,   1,   1.0f,  0.0f);
            bmm_kernel<<<dim3(4, 64), 256, 81920, s_b>>>(1,   1,   1,   2,  -1.0f,  7.0f);
            bmm_kernel<<<dim3(4, 64), 256, 81920, s_b>>>(1,   2,   1,   3,  -1.0f, 15.0f);
            bmm_kernel<<<dim3(4, 64), 256, 81920, s_b>>>(cur, 3,   cur, nxt, -0.25f, 3.25f);
            int t = cur; cur = nxt; nxt = t;
        }
    }
    cudaEventRecord(ev_join, s_b);

    // ---- main stream: big attention chain ----
    k1_mma_kernel<<<dim3(32, 64), 256, 73728>>>();
    k3score_mma_kernel<<<dim3(32, 64), 256, 73728>>>();
    softmax4096_kernel<<<8192, 256>>>();
    k3v_mma_kernel<<<dim3(4, 64), 256, 110592>>>();

    // ---- join: y2 needs g_Va (side) + k3v parts (main) ----
    cudaStreamWaitEvent(0, ev_join, 0);
    y2_kernel<<<64, 256, 98304>>>();
    x1_mma_kernel<<<dim3(32, 64), 256, 104448>>>();

    // output projection (A slot 0, W slot 3)
    gemm_tf32_kernel<<<dim3(8, 128, 1), 256, GT_SM>>>(bo, nullptr, nullptr, out, 3);
}

// round 11
// speedup vs baseline: 1.6830x; 1.2405x over previous
#include <cuda_runtime.h>
#include <cuda_bf16.h>
#include <cuda_fp16.h>
#include <cstdint>

// ---------------- problem constants ----------------
#define B_    4
#define L_    4096
#define DM_   1024
#define H_    16
#define D_    64
#define M_    128
#define BH_   64          // B*H
#define SEG_  32          // L/M
#define NTOK_ 16384       // B*L

// single dynamic-smem symbol for the whole TU
extern __shared__ char dynsm[];

// ---------------- scratch (device globals; no allocations allowed) ----------------
__device__ float g_Ql[BH_ * M_ * D_];          // fp32 landmarks (for k2)
__device__ float g_Kl[BH_ * M_ * D_];
__device__ float g_k3[(size_t)BH_ * M_ * L_];  // raw scores fp32
__device__ float g_k2[BH_ * M_ * M_];
__device__ float g_P [BH_ * M_ * M_];
__device__ float g_M1[BH_ * M_ * M_];
__device__ float g_M2[BH_ * M_ * M_];
__device__ float g_Va[BH_ * M_ * M_];
__device__ float g_Vb[BH_ * M_ * M_];
__device__ float g_k3v_part[4 * BH_ * M_ * D_];

// fp16 operand buffers for the 4 big GEMMs (1-term, RN-rounded)
__device__ __align__(16) __half g_a16[(size_t)3 * NTOK_ * DM_];  // A slots (slot 0 reused by x1)
__device__ __align__(16) __half g_w16[4 * DM_ * DM_];            // W^T slots (3 = Wo)

// bf16 split buffers for the attention-side GEMMs
__device__ __align__(16) __nv_bfloat16 g_qh[(size_t)BH_ * L_ * D_]; // q split [bh][l][d]
__device__ __align__(16) __nv_bfloat16 g_ql[(size_t)BH_ * L_ * D_];
__device__ __align__(16) __nv_bfloat16 g_kh[(size_t)BH_ * L_ * D_];
__device__ __align__(16) __nv_bfloat16 g_kl[(size_t)BH_ * L_ * D_];
__device__ __align__(16) __nv_bfloat16 g_vh[(size_t)BH_ * L_ * D_];
__device__ __align__(16) __nv_bfloat16 g_vl[(size_t)BH_ * L_ * D_];
__device__ __align__(16) __nv_bfloat16 g_Qlh[BH_ * M_ * D_];
__device__ __align__(16) __nv_bfloat16 g_Qll[BH_ * M_ * D_];
__device__ __align__(16) __nv_bfloat16 g_Klh[BH_ * M_ * D_];
__device__ __align__(16) __nv_bfloat16 g_Kll[BH_ * M_ * D_];
__device__ __align__(16) __nv_bfloat16 g_k1h[(size_t)BH_ * L_ * M_]; // kernel_1 split
__device__ __align__(16) __nv_bfloat16 g_k1l[(size_t)BH_ * L_ * M_];
__device__ __align__(16) __nv_bfloat16 g_s3h[(size_t)BH_ * M_ * L_]; // softmaxed k3 split
__device__ __align__(16) __nv_bfloat16 g_s3l[(size_t)BH_ * M_ * L_];
__device__ __align__(16) __nv_bfloat16 g_y2th[BH_ * D_ * M_];        // y2^T split [bh][d][m]
__device__ __align__(16) __nv_bfloat16 g_y2tl[BH_ * D_ * M_];

// =====================================================================
// PTX helpers (baseline set only: mma.sync / ldmatrix / cp.async / cvt)
// =====================================================================
__device__ __forceinline__ uint32_t smem_to_u32(const void* p) {
    uint32_t a;
    asm("{ .reg .u64 t; cvta.to.shared.u64 t, %1; cvt.u32.u64 %0, t; }" : "=r"(a) : "l"(p));
    return a;
}
__device__ __forceinline__ void ldsm4(uint32_t* r, uint32_t addr) {
    asm volatile("ldmatrix.sync.aligned.m8n8.x4.shared.b16 {%0,%1,%2,%3}, [%4];"
        : "=r"(r[0]), "=r"(r[1]), "=r"(r[2]), "=r"(r[3]) : "r"(addr));
}
__device__ __forceinline__ void ldsm4t(uint32_t* r, uint32_t addr) {
    asm volatile("ldmatrix.sync.aligned.m8n8.x4.trans.shared.b16 {%0,%1,%2,%3}, [%4];"
        : "=r"(r[0]), "=r"(r[1]), "=r"(r[2]), "=r"(r[3]) : "r"(addr));
}
__device__ __forceinline__ void mma16816(float* d, const uint32_t* a, const uint32_t* b) {
    asm volatile("mma.sync.aligned.m16n8k16.row.col.f32.bf16.bf16.f32 "
        "{%0,%1,%2,%3}, {%4,%5,%6,%7}, {%8,%9}, {%0,%1,%2,%3};"
        : "+f"(d[0]), "+f"(d[1]), "+f"(d[2]), "+f"(d[3])
        : "r"(a[0]), "r"(a[1]), "r"(a[2]), "r"(a[3]), "r"(b[0]), "r"(b[1]));
}
__device__ __forceinline__ void mma16816h(float* d, const uint32_t* a, const uint32_t* b) {
    asm volatile("mma.sync.aligned.m16n8k16.row.col.f32.f16.f16.f32 "
        "{%0,%1,%2,%3}, {%4,%5,%6,%7}, {%8,%9}, {%0,%1,%2,%3};"
        : "+f"(d[0]), "+f"(d[1]), "+f"(d[2]), "+f"(d[3])
        : "r"(a[0]), "r"(a[1]), "r"(a[2]), "r"(a[3]), "r"(b[0]), "r"(b[1]));
}
#define CP_ASYNC16(dst, src) \
    asm volatile("cp.async.cg.shared.global [%0], [%1], 16;" :: "r"(dst), "l"(src))
#define CP_COMMIT()  asm volatile("cp.async.commit_group;" ::: "memory")
#define CP_WAIT(n)   asm volatile("cp.async.wait_group %0;" :: "n"(n) : "memory")

__device__ __forceinline__ void split_bf16(float v, __nv_bfloat16& h, __nv_bfloat16& l) {
    h = __float2bfloat16(v);
    l = __float2bfloat16(v - __bfloat162float(h));
}

// =====================================================================
// conversion kernels (fp32 -> fp16 RN)
// =====================================================================
__global__ void conv_act3_kernel(const float* __restrict__ s0,
                                 const float* __restrict__ s1,
                                 const float* __restrict__ s2)
{
    int z = blockIdx.y;
    const float* src = (z == 0) ? s0 : ((z == 1) ? s1 : s2);
    size_t i4 = (size_t)blockIdx.x * 256 + threadIdx.x;
    float4 v = *(const float4*)&src[i4 * 4];
    __half h[4];
    h[0] = __float2half_rn(v.x); h[1] = __float2half_rn(v.y);
    h[2] = __float2half_rn(v.z); h[3] = __float2half_rn(v.w);
    *(uint2*)&g_a16[(size_t)z * NTOK_ * DM_ + i4 * 4] = *(uint2*)h;
}

__global__ void conv_wt_kernel(const float* __restrict__ W, int slot)
{
    __shared__ float t[32][33];
    int x = blockIdx.x * 32 + threadIdx.x;
    int y = blockIdx.y * 32 + threadIdx.y;
    #pragma unroll
    for (int j = 0; j < 32; j += 8) t[threadIdx.y + j][threadIdx.x] = W[(size_t)(y + j) * 1024 + x];
    __syncthreads();
    int xo = blockIdx.y * 32 + threadIdx.x;
    int yo = blockIdx.x * 32 + threadIdx.y;
    size_t base = (size_t)slot * DM_ * DM_;
    #pragma unroll
    for (int j = 0; j < 32; j += 8)
        g_w16[base + (size_t)(yo + j) * 1024 + xo] = __float2half_rn(t[threadIdx.x][threadIdx.y + j]);
}

// =====================================================================
// projection GEMM — 1-term FP16, BK=32, 2-stage cp.async, 40960 B smem.
// mode = -1: fused QKV (z = blockIdx.z selects A slot z, W slot z, dest q/k/v)
// mode =  3: output projection (A slot 0, W slot 3, fp32 out, bias = b0p)
// per-array tile: 128 rows x 80 B pitch (32 fp16 + 16 B pad) = 10240 B
// =====================================================================
#define H_TSZ   10240
#define H_STG   (2 * H_TSZ)     // A + B per stage = 20480
#define H_SM    (2 * H_STG)     // 40960 total

__global__ __launch_bounds__(256) void gemm_fp16_kernel(
    const float* __restrict__ b0p, const float* __restrict__ b1p,
    const float* __restrict__ b2p, float* __restrict__ outp, int mode)
{
    const uint32_t sbase = smem_to_u32(dynsm);

    const int z  = (mode == 3) ? 0 : blockIdx.z;
    const int wz = (mode == 3) ? 3 : z;
    const float* bias = (mode == 3) ? b0p : ((z == 0) ? b0p : ((z == 1) ? b1p : b2p));
    const __half* Ah = g_a16 + (size_t)z * NTOK_ * DM_;
    const __half* Wh = g_w16 + (size_t)wz * DM_ * DM_;

    const int tid  = threadIdx.x;
    const int lane = tid & 31;
    const int w    = tid >> 5;
    const int wm   = w >> 2;
    const int wn   = w & 3;
    const int n0 = blockIdx.x * 128;
    const int m0 = blockIdx.y * 128;

    float acc[4][4][4];
    #pragma unroll
    for (int i = 0; i < 4; i++)
        #pragma unroll
        for (int j = 0; j < 4; j++)
            #pragma unroll
            for (int t = 0; t < 4; t++) acc[i][j][t] = 0.f;

    auto load_chunk = [&](int c, int buf) {
        const int k0 = c * 32;
        const uint32_t sb = sbase + buf * H_STG;
        #pragma unroll
        for (int i = 0; i < 4; i++) {
            int q = tid + i * 256;           // 0..1023
            int arr = q >> 9;                // 0 = A, 1 = B
            int r   = (q >> 2) & 127;
            int c4  = q & 3;
            uint32_t dst = sb + arr * H_TSZ + r * 80 + c4 * 16;
            const __half* src = (arr == 0)
                ? &Ah[(size_t)(m0 + r) * 1024 + k0 + c4 * 8]
                : &Wh[(size_t)(n0 + r) * 1024 + k0 + c4 * 8];
            CP_ASYNC16(dst, src);
        }
        CP_COMMIT();
    };

    auto compute_chunk = [&](int buf) {
        const uint32_t S = sbase + buf * H_STG;
        #pragma unroll
        for (int k16 = 0; k16 < 2; k16++) {
            const uint32_t kb = (uint32_t)(k16 * 32);
            uint32_t af[4][4];
            #pragma unroll
            for (int mt = 0; mt < 4; mt++) {
                uint32_t addr = S
                    + (uint32_t)((wm * 64 + mt * 16 + (lane & 15)) * 80)
                    + kb + (uint32_t)((lane >> 4) * 16);
                ldsm4(af[mt], addr);
            }
            uint32_t bf[2][4];
            #pragma unroll
            for (int np = 0; np < 2; np++) {
                uint32_t nrow = (uint32_t)(wn * 32 + np * 16 + ((lane >> 4) * 8) + (lane & 7));
                uint32_t addr = S + H_TSZ + nrow * 80 + kb + (uint32_t)(((lane >> 3) & 1) * 16);
                ldsm4(bf[np], addr);
            }
            #pragma unroll
            for (int mt = 0; mt < 4; mt++)
                #pragma unroll
                for (int nt = 0; nt < 4; nt++)
                    mma16816h(acc[mt][nt], af[mt], &bf[nt >> 1][(nt & 1) * 2]);
        }
    };

    // 2-stage pipeline
    load_chunk(0, 0);
    #pragma unroll 1
    for (int c = 0; c < 32; c++) {
        if (c + 1 < 32) {
            load_chunk(c + 1, (c + 1) & 1);
            CP_WAIT(1);
        } else {
            CP_WAIT(0);
        }
        __syncthreads();
        compute_chunk(c & 1);
        __syncthreads();
    }

    #pragma unroll
    for (int mt = 0; mt < 4; mt++) {
        #pragma unroll
        for (int nt = 0; nt < 4; nt++) {
            int c = n0 + wn * 32 + nt * 8 + (lane & 3) * 2;
            float b0 = bias[c], b1 = bias[c + 1];
            #pragma unroll
            for (int half = 0; half < 2; half++) {
                int r = m0 + wm * 64 + mt * 16 + (lane >> 2) + half * 8;
                float vx = acc[mt][nt][half * 2 + 0] + b0;
                float vy = acc[mt][nt][half * 2 + 1] + b1;
                if (mode == 3) {
                    float2 t = {vx, vy};
                    *(float2*)&outp[(size_t)r * 1024 + c] = t;
                } else {
                    __nv_bfloat16* dh = (z == 0) ? g_qh : ((z == 1) ? g_kh : g_vh);
                    __nv_bfloat16* dl = (z == 0) ? g_ql : ((z == 1) ? g_kl : g_vl);
                    int b = r >> 12, l = r & 4095;
                    int h = c >> 6, d = c & 63;
                    size_t o = (((size_t)(b * 16 + h) * 4096) + l) * 64 + d;
                    __nv_bfloat16 hp[2], lp[2];
                    split_bf16(vx, hp[0], lp[0]);
                    split_bf16(vy, hp[1], lp[1]);
                    *(uint32_t*)&dh[o] = *(uint32_t*)hp;
                    *(uint32_t*)&dl[o] = *(uint32_t*)lp;
                }
            }
        }
    }
}

// =====================================================================
// landmark pooling from split q/k; writes fp32 + split landmarks
// =====================================================================
__global__ void pool_kernel()
{
    int idx = blockIdx.x * blockDim.x + threadIdx.x;   // BH*M*D
    int d  = idx & 63;
    int m  = (idx >> 6) & 127;
    int bh = idx >> 13;
    size_t base = ((size_t)bh * L_ + m * SEG_) * D_ + d;
    float sq = 0.f, sk = 0.f;
    #pragma unroll
    for (int s = 0; s < SEG_; s++) {
        sq += __bfloat162float(g_qh[base + s * D_]) + __bfloat162float(g_ql[base + s * D_]);
        sk += __bfloat162float(g_kh[base + s * D_]) + __bfloat162float(g_kl[base + s * D_]);
    }
    float mq = sq * (1.f / SEG_), mk = sk * (1.f / SEG_);
    g_Ql[idx] = mq; g_Kl[idx] = mk;
    __nv_bfloat16 h, l;
    split_bf16(mq, h, l); g_Qlh[idx] = h; g_Qll[idx] = l;
    split_bf16(mk, h, l); g_Klh[idx] = h; g_Kll[idx] = l;
}

// =====================================================================
// k1: C[128 tok][128 lm] = q_blk @ Kl^T (split mma) + fused softmax -> split bf16
// =====================================================================
__global__ __launch_bounds__(256) void k1_mma_kernel()
{
    char* sm = dynsm;
    const uint32_t sb = smem_to_u32(sm);
    int bh = blockIdx.y, l0 = blockIdx.x * 128, tid = threadIdx.x;
    int lane = tid & 31, w = tid >> 5;

    {
        const __nv_bfloat16* qh = g_qh + ((size_t)bh * L_ + l0) * D_;
        const __nv_bfloat16* ql = g_ql + ((size_t)bh * L_ + l0) * D_;
        const __nv_bfloat16* kh = g_Klh + bh * (M_ * D_);
        const __nv_bfloat16* kl = g_Kll + bh * (M_ * D_);
        #pragma unroll
        for (int i = 0; i < 4; i++) {
            int q = tid + i * 256;
            int row = q >> 3, c8 = q & 7;
            uint32_t so = (uint32_t)(row * 144 + c8 * 16);
            size_t go = (size_t)row * 64 + c8 * 8;
            *(uint4*)(sm + 0     + so) = *(const uint4*)&qh[go];
            *(uint4*)(sm + 18432 + so) = *(const uint4*)&ql[go];
            *(uint4*)(sm + 36864 + so) = *(const uint4*)&kh[go];
            *(uint4*)(sm + 55296 + so) = *(const uint4*)&kl[go];
        }
    }
    __syncthreads();

    int wm = w >> 2, wn = w & 3;
    float acc[4][4][4];
    #pragma unroll
    for (int i = 0; i < 4; i++)
        #pragma unroll
        for (int j = 0; j < 4; j++)
            #pragma unroll
            for (int t = 0; t < 4; t++) acc[i][j][t] = 0.f;

    #pragma unroll
    for (int k16 = 0; k16 < 4; k16++) {
        uint32_t af[2][4][4];
        #pragma unroll
        for (int term = 0; term < 2; term++)
            #pragma unroll
            for (int mt = 0; mt < 4; mt++) {
                uint32_t addr = sb + term * 18432
                    + (uint32_t)((wm * 64 + mt * 16 + (lane & 15)) * 144)
                    + (uint32_t)(k16 * 32) + (uint32_t)((lane >> 4) * 16);
                ldsm4(af[term][mt], addr);
            }
        uint32_t bf[2][2][4];
        #pragma unroll
        for (int term = 0; term < 2; term++)
            #pragma unroll
            for (int np = 0; np < 2; np++) {
                uint32_t nrow = (uint32_t)(wn * 32 + np * 16 + ((lane >> 4) * 8) + (lane & 7));
                uint32_t addr = sb + 36864 + term * 18432 + nrow * 144
                    + (uint32_t)(k16 * 32) + (uint32_t)(((lane >> 3) & 1) * 16);
                ldsm4(bf[term][np], addr);
            }
        #pragma unroll
        for (int mt = 0; mt < 4; mt++)
            #pragma unroll
            for (int nt = 0; nt < 4; nt++) {
                float* d = acc[mt][nt];
                const uint32_t* bh_ = &bf[0][nt >> 1][(nt & 1) * 2];
                const uint32_t* bl_ = &bf[1][nt >> 1][(nt & 1) * 2];
                mma16816(d, af[0][mt], bh_);
                mma16816(d, af[0][mt], bl_);
                mma16816(d, af[1][mt], bh_);
            }
    }
    __syncthreads();

    float* S = (float*)sm;
    #pragma unroll
    for (int mt = 0; mt < 4; mt++)
        #pragma unroll
        for (int nt = 0; nt < 4; nt++)
            #pragma unroll
            for (int half = 0; half < 2; half++) {
                int row = wm * 64 + mt * 16 + (lane >> 2) + half * 8;
                int col = wn * 32 + nt * 8 + (lane & 3) * 2;
                S[row * 128 + col]     = acc[mt][nt][half * 2 + 0];
                S[row * 128 + col + 1] = acc[mt][nt][half * 2 + 1];
            }
    __syncthreads();

    for (int rr = 0; rr < 16; rr++) {
        int row = w * 16 + rr;
        float x0 = S[row * 128 + lane],      x1 = S[row * 128 + lane + 32];
        float x2 = S[row * 128 + lane + 64], x3 = S[row * 128 + lane + 96];
        float mx = fmaxf(fmaxf(x0, x1), fmaxf(x2, x3));
        #pragma unroll
        for (int o = 16; o; o >>= 1) mx = fmaxf(mx, __shfl_xor_sync(0xffffffffu, mx, o));
        float e0 = __expf(x0 - mx), e1 = __expf(x1 - mx);
        float e2 = __expf(x2 - mx), e3 = __expf(x3 - mx);
        float s = e0 + e1 + e2 + e3;
        #pragma unroll
        for (int o = 16; o; o >>= 1) s += __shfl_xor_sync(0xffffffffu, s, o);
        float inv = 1.f / s;
        size_t ob = ((size_t)bh * L_ + l0 + row) * 128;
        float vv[4] = {e0 * inv, e1 * inv, e2 * inv, e3 * inv};
        #pragma unroll
        for (int j = 0; j < 4; j++) {
            __nv_bfloat16 h, l; split_bf16(vv[j], h, l);
            g_k1h[ob + lane + 32 * j] = h;
            g_k1l[ob + lane + 32 * j] = l;
        }
    }
}

// =====================================================================
// k3 scores: C[m=128][l=128 blk] = Ql @ k_blk^T (split mma) -> raw fp32 g_k3
// =====================================================================
__global__ __launch_bounds__(256) void k3score_mma_kernel()
{
    char* sm = dynsm;
    const uint32_t sb = smem_to_u32(sm);
    int bh = blockIdx.y, l0 = blockIdx.x * 128, tid = threadIdx.x;
    int lane = tid & 31, w = tid >> 5;

    {
        const __nv_bfloat16* ah = g_Qlh + bh * (M_ * D_);
        const __nv_bfloat16* al = g_Qll + bh * (M_ * D_);
        const __nv_bfloat16* bhp = g_kh + ((size_t)bh * L_ + l0) * D_;
        const __nv_bfloat16* blp = g_kl + ((size_t)bh * L_ + l0) * D_;
        #pragma unroll
        for (int i = 0; i < 4; i++) {
            int q = tid + i * 256;
            int row = q >> 3, c8 = q & 7;
            uint32_t so = (uint32_t)(row * 144 + c8 * 16);
            size_t go = (size_t)row * 64 + c8 * 8;
            *(uint4*)(sm + 0     + so) = *(const uint4*)&ah[go];
            *(uint4*)(sm + 18432 + so) = *(const uint4*)&al[go];
            *(uint4*)(sm + 36864 + so) = *(const uint4*)&bhp[go];
            *(uint4*)(sm + 55296 + so) = *(const uint4*)&blp[go];
        }
    }
    __syncthreads();

    int wm = w >> 2, wn = w & 3;
    float acc[4][4][4];
    #pragma unroll
    for (int i = 0; i < 4; i++)
        #pragma unroll
        for (int j = 0; j < 4; j++)
            #pragma unroll
            for (int t = 0; t < 4; t++) acc[i][j][t] = 0.f;

    #pragma unroll
    for (int k16 = 0; k16 < 4; k16++) {
        uint32_t af[2][4][4];
        #pragma unroll
        for (int term = 0; term < 2; term++)
            #pragma unroll
            for (int mt = 0; mt < 4; mt++) {
                uint32_t addr = sb + term * 18432
                    + (uint32_t)((wm * 64 + mt * 16 + (lane & 15)) * 144)
                    + (uint32_t)(k16 * 32) + (uint32_t)((lane >> 4) * 16);
                ldsm4(af[term][mt], addr);
            }
        uint32_t bf[2][2][4];
        #pragma unroll
        for (int term = 0; term < 2; term++)
            #pragma unroll
            for (int np = 0; np < 2; np++) {
                uint32_t nrow = (uint32_t)(wn * 32 + np * 16 + ((lane >> 4) * 8) + (lane & 7));
                uint32_t addr = sb + 36864 + term * 18432 + nrow * 144
                    + (uint32_t)(k16 * 32) + (uint32_t)(((lane >> 3) & 1) * 16);
                ldsm4(bf[term][np], addr);
            }
        #pragma unroll
        for (int mt = 0; mt < 4; mt++)
            #pragma unroll
            for (int nt = 0; nt < 4; nt++) {
                float* d = acc[mt][nt];
                const uint32_t* bh_ = &bf[0][nt >> 1][(nt & 1) * 2];
                const uint32_t* bl_ = &bf[1][nt >> 1][(nt & 1) * 2];
                mma16816(d, af[0][mt], bh_);
                mma16816(d, af[0][mt], bl_);
                mma16816(d, af[1][mt], bh_);
            }
    }

    float* o = g_k3 + (size_t)bh * M_ * L_;
    #pragma unroll
    for (int mt = 0; mt < 4; mt++)
        #pragma unroll
        for (int nt = 0; nt < 4; nt++)
            #pragma unroll
            for (int half = 0; half < 2; half++) {
                int m_r = wm * 64 + mt * 16 + (lane >> 2) + half * 8;
                int l_c = l0 + wn * 32 + nt * 8 + (lane & 3) * 2;
                float2 t = {acc[mt][nt][half * 2 + 0], acc[mt][nt][half * 2 + 1]};
                *(float2*)&o[(size_t)m_r * L_ + l_c] = t;
            }
}

// =====================================================================
// row softmax over 4096; reads fp32 g_k3, writes split bf16 g_s3
// =====================================================================
__global__ __launch_bounds__(256) void softmax4096_kernel()
{
    size_t row = blockIdx.x;
    const float* p = g_k3 + row * 4096;
    int tid = threadIdx.x;
    float v[16];
    float mx = -1e30f;
    #pragma unroll
    for (int i = 0; i < 4; i++) {
        float4 t = *(const float4*)&p[i * 1024 + tid * 4];
        v[i * 4 + 0] = t.x; v[i * 4 + 1] = t.y; v[i * 4 + 2] = t.z; v[i * 4 + 3] = t.w;
        mx = fmaxf(mx, fmaxf(fmaxf(t.x, t.y), fmaxf(t.z, t.w)));
    }
    __shared__ float smx[8], ssm[8], sres;
    #pragma unroll
    for (int o = 16; o; o >>= 1) mx = fmaxf(mx, __shfl_xor_sync(0xffffffffu, mx, o));
    if ((tid & 31) == 0) smx[tid >> 5] = mx;
    __syncthreads();
    if (tid == 0) {
        float m = smx[0];
        #pragma unroll
        for (int i = 1; i < 8; i++) m = fmaxf(m, smx[i]);
        sres = m;
    }
    __syncthreads();
    float MX = sres;
    float s = 0.f;
    #pragma unroll
    for (int i = 0; i < 16; i++) { v[i] = __expf(v[i] - MX); s += v[i]; }
    #pragma unroll
    for (int o = 16; o; o >>= 1) s += __shfl_xor_sync(0xffffffffu, s, o);
    if ((tid & 31) == 0) ssm[tid >> 5] = s;
    __syncthreads();
    if (tid == 0) {
        float t = 0.f;
        #pragma unroll
        for (int i = 0; i < 8; i++) t += ssm[i];
        sres = 1.f / t;
    }
    __syncthreads();
    float inv = sres;
    #pragma unroll
    for (int i = 0; i < 4; i++) {
        __nv_bfloat16 hh[4], ll[4];
        #pragma unroll
        for (int t = 0; t < 4; t++) split_bf16(v[i * 4 + t] * inv, hh[t], ll[t]);
        *(uint2*)&g_s3h[row * 4096 + i * 1024 + tid * 4] = *(uint2*)hh;
        *(uint2*)&g_s3l[row * 4096 + i * 1024 + tid * 4] = *(uint2*)ll;
    }
}

// =====================================================================
// kernel_2 = softmax(Q_l @ K_l^T) fused (fp32, tiny). block per head.
// =====================================================================
__global__ __launch_bounds__(256) void k2_kernel()
{
    float* sm = (float*)dynsm;
    float* Qlt = sm;
    float* Klt = sm + 8192;
    float* S   = sm + 16384;
    int bh = blockIdx.x, tid = threadIdx.x;

    const float* Ql = g_Ql + bh * 8192;
    const float* Kl = g_Kl + bh * 8192;
    #pragma unroll
    for (int i = 0; i < 8; i++) {
        int f = i * 1024 + tid * 4; int m = f >> 6, d0 = f & 63;
        float4 tq = *(const float4*)&Ql[f];
        float4 tk = *(const float4*)&Kl[f];
        Qlt[(d0 + 0) * 128 + m] = tq.x; Qlt[(d0 + 1) * 128 + m] = tq.y;
        Qlt[(d0 + 2) * 128 + m] = tq.z; Qlt[(d0 + 3) * 128 + m] = tq.w;
        Klt[(d0 + 0) * 128 + m] = tk.x; Klt[(d0 + 1) * 128 + m] = tk.y;
        Klt[(d0 + 2) * 128 + m] = tk.z; Klt[(d0 + 3) * 128 + m] = tk.w;
    }
    __syncthreads();

    int tm = tid >> 4, tn = tid & 15;
    float acc[8][8] = {};
    for (int d = 0; d < 64; d++) {
        float4 a0 = *(const float4*)&Qlt[d * 128 + tm * 8];
        float4 a1 = *(const float4*)&Qlt[d * 128 + tm * 8 + 4];
        float4 b0 = *(const float4*)&Klt[d * 128 + tn * 8];
        float4 b1 = *(const float4*)&Klt[d * 128 + tn * 8 + 4];
        float av[8] = {a0.x, a0.y, a0.z, a0.w, a1.x, a1.y, a1.z, a1.w};
        float bv[8] = {b0.x, b0.y, b0.z, b0.w, b1.x, b1.y, b1.z, b1.w};
        #pragma unroll
        for (int i = 0; i < 8; i++)
            #pragma unroll
            for (int j = 0; j < 8; j++) acc[i][j] += av[i] * bv[j];
    }
    #pragma unroll
    for (int i = 0; i < 8; i++)
        #pragma unroll
        for (int j = 0; j < 8; j++) S[(tm * 8 + i) * 128 + tn * 8 + j] = acc[i][j];
    __syncthreads();

    int lane = tid & 31, w = tid >> 5;
    for (int rr = 0; rr < 16; rr++) {
        int row = w * 16 + rr;
        float x0 = S[row * 128 + lane],      x1 = S[row * 128 + lane + 32];
        float x2 = S[row * 128 + lane + 64], x3 = S[row * 128 + lane + 96];
        float mx = fmaxf(fmaxf(x0, x1), fmaxf(x2, x3));
        #pragma unroll
        for (int o = 16; o; o >>= 1) mx = fmaxf(mx, __shfl_xor_sync(0xffffffffu, mx, o));
        float e0 = __expf(x0 - mx), e1 = __expf(x1 - mx);
        float e2 = __expf(x2 - mx), e3 = __expf(x3 - mx);
        float s = e0 + e1 + e2 + e3;
        #pragma unroll
        for (int o = 16; o; o >>= 1) s += __shfl_xor_sync(0xffffffffu, s, o);
        float inv = 1.f / s;
        float* o = g_k2 + bh * 16384 + row * 128;
        o[lane] = e0 * inv; o[lane + 32] = e1 * inv; o[lane + 64] = e2 * inv; o[lane + 96] = e3 * inv;
    }
}

// =====================================================================
// V0 = K^T / max(colsum(K))
// =====================================================================
__global__ __launch_bounds__(256) void vinit_kernel()
{
    int bh = blockIdx.x, tid = threadIdx.x;
    const float* K = g_k2 + bh * 16384;
    __shared__ float cs[128];
    __shared__ float sscale;
    if (tid < 128) {
        float s = 0.f;
        for (int r = 0; r < 128; r++) s += K[r * 128 + tid];
        cs[tid] = s;
    }
    __syncthreads();
    if (tid == 0) {
        float m = cs[0];
        for (int i = 1; i < 128; i++) m = fmaxf(m, cs[i]);
        sscale = 1.f / m;
    }
    __syncthreads();
    float scale = sscale;
    for (int f = tid; f < 16384; f += 256) {
        int i = f >> 7, j = f & 127;
        g_Va[bh * 16384 + f] = scale * K[j * 128 + i];
    }
}

// =====================================================================
// batched 128x128 bmm for Newton-Schulz (fp32)
// =====================================================================
__device__ __forceinline__ float* bufsel(int s)
{
    switch (s) {
        case 0: return g_k2; case 1: return g_P; case 2: return g_M1;
        case 3: return g_M2; case 4: return g_Va; default: return g_Vb;
    }
}

__global__ __launch_bounds__(256) void bmm_kernel(int as, int bs, int cs2, int os,
                                                  float alpha, float beta)
{
    float* sm = (float*)dynsm;
    float* Bs = sm;
    float* At = sm + 16384;
    int bh = blockIdx.y, r0 = blockIdx.x * 32, tid = threadIdx.x;
    const float* A  = bufsel(as)  + bh * 16384;
    const float* Bm = bufsel(bs)  + bh * 16384;
    const float* C  = bufsel(cs2) + bh * 16384;
    float* O        = bufsel(os)  + bh * 16384;

    #pragma unroll
    for (int i = 0; i < 16; i++) {
        int f = i * 1024 + tid * 4;
        *(float4*)&Bs[f] = *(const float4*)&Bm[f];
    }
    #pragma unroll
    for (int i = 0; i < 4; i++) {
        int f = i * 1024 + tid * 4; int r = f >> 7, k0 = f & 127;
        float4 t = *(const float4*)&A[(r0 + r) * 128 + k0];
        At[(k0 + 0) * 32 + r] = t.x; At[(k0 + 1) * 32 + r] = t.y;
        At[(k0 + 2) * 32 + r] = t.z; At[(k0 + 3) * 32 + r] = t.w;
    }
    __syncthreads();

    int rb = (tid >> 5) * 4, cb = (tid & 31) * 4;
    float acc[4][4] = {};
    for (int k = 0; k < 128; k++) {
        float a0 = At[k * 32 + rb + 0], a1 = At[k * 32 + rb + 1];
        float a2 = At[k * 32 + rb + 2], a3 = At[k * 32 + rb + 3];
        float4 b = *(const float4*)&Bs[k * 128 + cb];
        acc[0][0] += a0 * b.x; acc[0][1] += a0 * b.y; acc[0][2] += a0 * b.z; acc[0][3] += a0 * b.w;
        acc[1][0] += a1 * b.x; acc[1][1] += a1 * b.y; acc[1][2] += a1 * b.z; acc[1][3] += a1 * b.w;
        acc[2][0] += a2 * b.x; acc[2][1] += a2 * b.y; acc[2][2] += a2 * b.z; acc[2][3] += a2 * b.w;
        acc[3][0] += a3 * b.x; acc[3][1] += a3 * b.y; acc[3][2] += a3 * b.z; acc[3][3] += a3 * b.w;
    }
    #pragma unroll
    for (int i = 0; i < 4; i++)
        #pragma unroll
        for (int j = 0; j < 4; j++) {
            int idx = (r0 + rb + i) * 128 + cb + j;
            O[idx] = alpha * acc[i][j] + beta * C[idx];
        }
}

// =====================================================================
// k3v: partial C[m=128][d=64] = softmax(k3)_split @ v_split (mma, split-K 4)
// 2-stage pipeline. dyn smem 110592
// =====================================================================
#define KV_STG 55296

__global__ __launch_bounds__(256) void k3v_mma_kernel()
{
    char* sm = dynsm;
    const uint32_t sb = smem_to_u32(sm);
    int s = blockIdx.x, bh = blockIdx.y, tid = threadIdx.x;
    int lane = tid & 31, w = tid >> 5;
    int wm = w >> 1, wn = w & 1;
    const size_t abase = (size_t)bh * M_ * L_;
    const size_t vbase = (size_t)bh * L_ * D_;

    float acc[2][4][4];
    #pragma unroll
    for (int i = 0; i < 2; i++)
        #pragma unroll
        for (int j = 0; j < 4; j++)
            #pragma unroll
            for (int t = 0; t < 4; t++) acc[i][j][t] = 0.f;

    auto load = [&](int ck, int buf) {
        int k0 = s * 1024 + ck * 64;
        uint32_t S = sb + buf * KV_STG;
        #pragma unroll
        for (int i = 0; i < 8; i++) {
            int q = tid + i * 256;
            int arr = q >> 10, row = (q >> 3) & 127, c8 = q & 7;
            uint32_t dst = S + arr * 18432 + (uint32_t)(row * 144 + c8 * 16);
            const __nv_bfloat16* src = (arr ? g_s3l : g_s3h) + abase + (size_t)row * L_ + k0 + c8 * 8;
            CP_ASYNC16(dst, src);
        }
        #pragma unroll
        for (int i = 0; i < 4; i++) {
            int q = tid + i * 256;
            int arr = q >> 9, row = (q >> 3) & 63, c8 = q & 7;
            uint32_t dst = S + 36864 + arr * 9216 + (uint32_t)(row * 144 + c8 * 16);
            const __nv_bfloat16* src = (arr ? g_vl : g_vh) + vbase + (size_t)(k0 + row) * D_ + c8 * 8;
            CP_ASYNC16(dst, src);
        }
        CP_COMMIT();
    };

    auto compute = [&](int buf) {
        uint32_t S = sb + buf * KV_STG;
        #pragma unroll
        for (int k16 = 0; k16 < 4; k16++) {
            uint32_t af[2][2][4];
            #pragma unroll
            for (int term = 0; term < 2; term++)
                #pragma unroll
                for (int mt = 0; mt < 2; mt++) {
                    uint32_t addr = S + term * 18432
                        + (uint32_t)((wm * 32 + mt * 16 + (lane & 15)) * 144)
                        + (uint32_t)(k16 * 32) + (uint32_t)((lane >> 4) * 16);
                    ldsm4(af[term][mt], addr);
                }
            uint32_t bf[2][2][4];
            #pragma unroll
            for (int term = 0; term < 2; term++)
                #pragma unroll
                for (int np = 0; np < 2; np++) {
                    uint32_t addr = S + 36864 + term * 9216
                        + (uint32_t)((k16 * 16 + (lane & 15)) * 144)
                        + (uint32_t)((wn * 32 + np * 16 + (lane >> 4) * 8) * 2);
                    ldsm4t(bf[term][np], addr);
                }
            #pragma unroll
            for (int mt = 0; mt < 2; mt++)
                #pragma unroll
                for (int nt = 0; nt < 4; nt++) {
                    float* d = acc[mt][nt];
                    const uint32_t* bh_ = &bf[0][nt >> 1][(nt & 1) * 2];
                    const uint32_t* bl_ = &bf[1][nt >> 1][(nt & 1) * 2];
                    mma16816(d, af[0][mt], bh_);
                    mma16816(d, af[0][mt], bl_);
                    mma16816(d, af[1][mt], bh_);
                }
        }
    };

    load(0, 0);
    #pragma unroll 1
    for (int ck = 0; ck < 16; ck++) {
        if (ck + 1 < 16) {
            load(ck + 1, (ck + 1) & 1);
            CP_WAIT(1);
        } else {
            CP_WAIT(0);
        }
        __syncthreads();
        compute(ck & 1);
        __syncthreads();
    }

    #pragma unroll
    for (int mt = 0; mt < 2; mt++)
        #pragma unroll
        for (int nt = 0; nt < 4; nt++)
            #pragma unroll
            for (int half = 0; half < 2; half++) {
                int m_r = wm * 32 + mt * 16 + (lane >> 2) + half * 8;
                int d_c = wn * 32 + nt * 8 + (lane & 3) * 2;
                float2 t = {acc[mt][nt][half * 2 + 0], acc[mt][nt][half * 2 + 1]};
                *(float2*)&g_k3v_part[((size_t)(s * 64 + bh) * 128 + m_r) * 64 + d_c] = t;
            }
}

// =====================================================================
// y2 = inv(g_Va) @ sum(k3v parts) per head (fp32); emits y2^T split bf16
// =====================================================================
__global__ __launch_bounds__(256) void y2_kernel()
{
    float* sm = (float*)dynsm;
    float* At = sm;
    float* Bs = sm + 16384;
    int bh = blockIdx.x, tid = threadIdx.x;
    const float* inv = g_Va + bh * 16384;

    #pragma unroll
    for (int i = 0; i < 16; i++) {
        int f = i * 1024 + tid * 4; int r = f >> 7, k0 = f & 127;
        float4 t = *(const float4*)&inv[f];
        At[(k0 + 0) * 128 + r] = t.x; At[(k0 + 1) * 128 + r] = t.y;
        At[(k0 + 2) * 128 + r] = t.z; At[(k0 + 3) * 128 + r] = t.w;
    }
    #pragma unroll
    for (int i = 0; i < 8; i++) {
        int f = i * 1024 + tid * 4;
        size_t o = (size_t)bh * 8192 + f;
        float4 a = *(const float4*)&g_k3v_part[o];
        float4 b = *(const float4*)&g_k3v_part[o + 524288];
        float4 c = *(const float4*)&g_k3v_part[o + 2 * 524288];
        float4 d = *(const float4*)&g_k3v_part[o + 3 * 524288];
        float4 t = {a.x + b.x + c.x + d.x, a.y + b.y + c.y + d.y,
                    a.z + b.z + c.z + d.z, a.w + b.w + c.w + d.w};
        *(float4*)&Bs[f] = t;
    }
    __syncthreads();

    int rt = tid >> 4, ct = tid & 15;
    float acc[8][4] = {};
    for (int k = 0; k < 128; k++) {
        float4 a0 = *(const float4*)&At[k * 128 + rt * 8];
        float4 a1 = *(const float4*)&At[k * 128 + rt * 8 + 4];
        float4 b  = *(const float4*)&Bs[k * 64 + ct * 4];
        float av[8] = {a0.x, a0.y, a0.z, a0.w, a1.x, a1.y, a1.z, a1.w};
        #pragma unroll
        for (int i = 0; i < 8; i++) {
            acc[i][0] += av[i] * b.x; acc[i][1] += av[i] * b.y;
            acc[i][2] += av[i] * b.z; acc[i][3] += av[i] * b.w;
        }
    }
    #pragma unroll
    for (int i = 0; i < 8; i++)
        #pragma unroll
        for (int j = 0; j < 4; j++) {
            __nv_bfloat16 h, l; split_bf16(acc[i][j], h, l);
            size_t o = (size_t)bh * 8192 + (ct * 4 + j) * 128 + rt * 8 + i;
            g_y2th[o] = h;
            g_y2tl[o] = l;
        }
}

// =====================================================================
// x1: C[l=128][d=64] = kernel1_split @ y2t_split (mma) -> g_a16 slot 0 (fp16)
// =====================================================================
__global__ __launch_bounds__(256) void x1_mma_kernel()
{
    char* sm = dynsm;
    const uint32_t sb = smem_to_u32(sm);
    int bh = blockIdx.y, l0 = blockIdx.x * 128, tid = threadIdx.x;
    int lane = tid & 31, w = tid >> 5;
    int wm = w >> 1, wn = w & 1;

    {
        const __nv_bfloat16* ah = g_k1h + ((size_t)bh * L_ + l0) * 128;
        const __nv_bfloat16* al = g_k1l + ((size_t)bh * L_ + l0) * 128;
        #pragma unroll
        for (int i = 0; i < 16; i++) {
            int q = tid + i * 256;
            int arr = q >> 11, row = (q >> 4) & 127, c16 = q & 15;
            uint32_t so = (uint32_t)(arr * 34816 + row * 272 + c16 * 16);
            const __nv_bfloat16* src = (arr ? al : ah) + (size_t)row * 128 + c16 * 8;
            *(uint4*)(sm + so) = *(const uint4*)src;
        }
        const __nv_bfloat16* bhp = g_y2th + (size_t)bh * 8192;
        const __nv_bfloat16* blp = g_y2tl + (size_t)bh * 8192;
        #pragma unroll
        for (int i = 0; i < 8; i++) {
            int q = tid + i * 256;
            int arr = q >> 10, row = (q >> 4) & 63, c16 = q & 15;
            uint32_t so = (uint32_t)(69632 + arr * 17408 + row * 272 + c16 * 16);
            const __nv_bfloat16* src = (arr ? blp : bhp) + (size_t)row * 128 + c16 * 8;
            *(uint4*)(sm + so) = *(const uint4*)src;
        }
    }
    __syncthreads();

    float acc[2][4][4];
    #pragma unroll
    for (int i = 0; i < 2; i++)
        #pragma unroll
        for (int j = 0; j < 4; j++)
            #pragma unroll
            for (int t = 0; t < 4; t++) acc[i][j][t] = 0.f;

    #pragma unroll
    for (int k16 = 0; k16 < 8; k16++) {
        uint32_t af[2][2][4];
        #pragma unroll
        for (int term = 0; term < 2; term++)
            #pragma unroll
            for (int mt = 0; mt < 2; mt++) {
                uint32_t addr = sb + term * 34816
                    + (uint32_t)((wm * 32 + mt * 16 + (lane & 15)) * 272)
                    + (uint32_t)(k16 * 32) + (uint32_t)((lane >> 4) * 16);
                ldsm4(af[term][mt], addr);
            }
        uint32_t bf[2][2][4];
        #pragma unroll
        for (int term = 0; term < 2; term++)
            #pragma unroll
            for (int np = 0; np < 2; np++) {
                uint32_t nrow = (uint32_t)(wn * 32 + np * 16 + ((lane >> 4) * 8) + (lane & 7));
                uint32_t addr = sb + 69632 + term * 17408 + nrow * 272
                    + (uint32_t)(k16 * 32) + (uint32_t)(((lane >> 3) & 1) * 16);
                ldsm4(bf[term][np], addr);
            }
        #pragma unroll
        for (int mt = 0; mt < 2; mt++)
            #pragma unroll
            for (int nt = 0; nt < 4; nt++) {
                float* d = acc[mt][nt];
                const uint32_t* bh_ = &bf[0][nt >> 1][(nt & 1) * 2];
                const uint32_t* bl_ = &bf[1][nt >> 1][(nt & 1) * 2];
                mma16816(d, af[0][mt], bh_);
                mma16816(d, af[0][mt], bl_);
                mma16816(d, af[1][mt], bh_);
            }
    }

    int b = bh >> 4, h = bh & 15;
    #pragma unroll
    for (int mt = 0; mt < 2; mt++)
        #pragma unroll
        for (int nt = 0; nt < 4; nt++)
            #pragma unroll
            for (int half = 0; half < 2; half++) {
                int l = l0 + wm * 32 + mt * 16 + (lane >> 2) + half * 8;
                int d_c = wn * 32 + nt * 8 + (lane & 3) * 2;
                size_t o = ((size_t)(b * L_ + l)) * DM_ + h * 64 + d_c;
                __half hp[2];
                hp[0] = __float2half_rn(acc[mt][nt][half * 2 + 0]);
                hp[1] = __float2half_rn(acc[mt][nt][half * 2 + 1]);
                *(uint32_t*)&g_a16[o] = *(uint32_t*)hp;
            }
}

// =====================================================================
// launch — capture-legal fork/join (side stream enters capture via ev_start)
// =====================================================================
extern "C" void kernel_launch(void* const* d_in, const int* in_sizes, int n_in,
                              void* d_out, int out_size)
{
    const float* queries = (const float*)d_in[0];
    const float* keys    = (const float*)d_in[1];
    const float* values  = (const float*)d_in[2];
    const float* Wq = (const float*)d_in[3];
    const float* bq = (const float*)d_in[4];
    const float* Wk = (const float*)d_in[5];
    const float* bk = (const float*)d_in[6];
    const float* Wv = (const float*)d_in[7];
    const float* bv = (const float*)d_in[8];
    const float* Wo = (const float*)d_in[9];
    const float* bo = (const float*)d_in[10];
    float* out = (float*)d_out;

    cudaFuncSetAttribute(gemm_fp16_kernel,   cudaFuncAttributeMaxDynamicSharedMemorySize, H_SM);
    cudaFuncSetAttribute(k1_mma_kernel,      cudaFuncAttributeMaxDynamicSharedMemorySize, 73728);
    cudaFuncSetAttribute(k3score_mma_kernel, cudaFuncAttributeMaxDynamicSharedMemorySize, 73728);
    cudaFuncSetAttribute(k3v_mma_kernel,     cudaFuncAttributeMaxDynamicSharedMemorySize, 110592);
    cudaFuncSetAttribute(x1_mma_kernel,      cudaFuncAttributeMaxDynamicSharedMemorySize, 104448);
    cudaFuncSetAttribute(k2_kernel,          cudaFuncAttributeMaxDynamicSharedMemorySize, 131072);
    cudaFuncSetAttribute(bmm_kernel,         cudaFuncAttributeMaxDynamicSharedMemorySize, 81920);
    cudaFuncSetAttribute(y2_kernel,          cudaFuncAttributeMaxDynamicSharedMemorySize, 98304);

    static cudaStream_t s_b = nullptr;
    static cudaEvent_t ev_start = nullptr, ev_wt = nullptr, ev_fork = nullptr, ev_join = nullptr;
    if (!s_b) {
        cudaStreamCreateWithFlags(&s_b, cudaStreamNonBlocking);
        cudaEventCreateWithFlags(&ev_start, cudaEventDisableTiming);
        cudaEventCreateWithFlags(&ev_wt,    cudaEventDisableTiming);
        cudaEventCreateWithFlags(&ev_fork,  cudaEventDisableTiming);
        cudaEventCreateWithFlags(&ev_join,  cudaEventDisableTiming);
    }

    dim3 wt_grid(32, 32), wt_blk(32, 8);

    // fork side stream INTO the capture before any s_b work
    cudaEventRecord(ev_start, 0);
    cudaStreamWaitEvent(s_b, ev_start, 0);

    // weight conversions on side stream, activation conversion on main
    conv_wt_kernel<<<wt_grid, wt_blk, 0, s_b>>>(Wq, 0);
    conv_wt_kernel<<<wt_grid, wt_blk, 0, s_b>>>(Wk, 1);
    conv_wt_kernel<<<wt_grid, wt_blk, 0, s_b>>>(Wv, 2);
    conv_wt_kernel<<<wt_grid, wt_blk, 0, s_b>>>(Wo, 3);
    cudaEventRecord(ev_wt, s_b);
    conv_act3_kernel<<<dim3(16384, 3), 256>>>(queries, keys, values);
    cudaStreamWaitEvent(0, ev_wt, 0);

    // fused QKV projection (fp16 1-term)
    gemm_fp16_kernel<<<dim3(8, 128, 3), 256, H_SM>>>(bq, bk, bv, nullptr, -1);

    // landmarks (both branches depend on this)
    pool_kernel<<<2048, 256>>>();

    // ---- fork: Newton-Schulz chain on side stream ----
    cudaEventRecord(ev_fork, 0);
    cudaStreamWaitEvent(s_b, ev_fork, 0);
    k2_kernel<<<64, 256, 131072, s_b>>>();
    vinit_kernel<<<64, 256, 0, s_b>>>();
    {
        int cur = 4, nxt = 5;
        for (int it = 0; it < 6; it++) {
            bmm_kernel<<<dim3(4, 64), 256, 81920, s_b>>>(0,   cur, 0,   1,   1.0f,  0.0f);
            bmm_kernel<<<dim3(4, 64), 256, 81920, s_b>>>(1,   1,   1,   2,  -1.0f,  7.0f);
            bmm_kernel<<<dim3(4, 64), 256, 81920, s_b>>>(1,   2,   1,   3,  -1.0f, 15.0f);
            bmm_kernel<<<dim3(4, 64), 256, 81920, s_b>>>(cur, 3,   cur, nxt, -0.25f, 3.25f);
            int t = cur; cur = nxt; nxt = t;
        }
    }
    cudaEventRecord(ev_join, s_b);

    // ---- main stream: big attention chain ----
    k1_mma_kernel<<<dim3(32, 64), 256, 73728>>>();
    k3score_mma_kernel<<<dim3(32, 64), 256, 73728>>>();
    softmax4096_kernel<<<8192, 256>>>();
    k3v_mma_kernel<<<dim3(4, 64), 256, 110592>>>();

    // ---- join: y2 needs g_Va (side) + k3v parts (main) ----
    cudaStreamWaitEvent(0, ev_join, 0);
    y2_kernel<<<64, 256, 98304>>>();
    x1_mma_kernel<<<dim3(32, 64), 256, 104448>>>();

    // output projection (A slot 0, W slot 3)
    gemm_fp16_kernel<<<dim3(8, 128, 1), 256, H_SM>>>(bo, nullptr, nullptr, out, 3);
}

// round 12
// speedup vs baseline: 1.7914x; 1.0644x over previous
#include <cuda_runtime.h>
#include <cuda_bf16.h>
#include <cuda_fp16.h>
#include <cstdint>

// ---------------- problem constants ----------------
#define B_    4
#define L_    4096
#define DM_   1024
#define H_    16
#define D_    64
#define M_    128
#define BH_   64          // B*H
#define SEG_  32          // L/M
#define NTOK_ 16384       // B*L

// single dynamic-smem symbol for the whole TU
extern __shared__ char dynsm[];

// ---------------- scratch (device globals; no allocations allowed) ----------------
__device__ float g_Ql[BH_ * M_ * D_];          // fp32 landmarks (for k2)
__device__ float g_Kl[BH_ * M_ * D_];
__device__ float g_k3[(size_t)BH_ * M_ * L_];  // raw scores fp32
__device__ float g_k2[BH_ * M_ * M_];
__device__ float g_P [BH_ * M_ * M_];
__device__ float g_M1[BH_ * M_ * M_];
__device__ float g_M2[BH_ * M_ * M_];
__device__ float g_Va[BH_ * M_ * M_];
__device__ float g_Vb[BH_ * M_ * M_];
__device__ float g_k3v_part[4 * BH_ * M_ * D_];

// fp16 operand buffers for the 4 big GEMMs (1-term, RN-rounded)
__device__ __align__(16) __half g_a16[(size_t)3 * NTOK_ * DM_];  // A slots (slot 0 reused by x1)
__device__ __align__(16) __half g_w16[4 * DM_ * DM_];            // W^T slots (3 = Wo)

// bf16 split buffers for the logit-path GEMMs (k1, k3score)
__device__ __align__(16) __nv_bfloat16 g_qh[(size_t)BH_ * L_ * D_]; // q split [bh][l][d]
__device__ __align__(16) __nv_bfloat16 g_ql[(size_t)BH_ * L_ * D_];
__device__ __align__(16) __nv_bfloat16 g_kh[(size_t)BH_ * L_ * D_];
__device__ __align__(16) __nv_bfloat16 g_kl[(size_t)BH_ * L_ * D_];
__device__ __align__(16) __nv_bfloat16 g_Qlh[BH_ * M_ * D_];
__device__ __align__(16) __nv_bfloat16 g_Qll[BH_ * M_ * D_];
__device__ __align__(16) __nv_bfloat16 g_Klh[BH_ * M_ * D_];
__device__ __align__(16) __nv_bfloat16 g_Kll[BH_ * M_ * D_];

// single-fp16 buffers for the probability-path GEMMs (k3v, x1)
__device__ __align__(16) __half g_v16 [(size_t)BH_ * L_ * D_];   // v [bh][l][d]
__device__ __align__(16) __half g_k116[(size_t)BH_ * L_ * M_];   // kernel_1 probs [bh][l][m]
__device__ __align__(16) __half g_s316[(size_t)BH_ * M_ * L_];   // softmaxed k3 [bh][m][l]
__device__ __align__(16) __half g_y2t16[BH_ * D_ * M_];          // y2^T [bh][d][m]

// =====================================================================
// PTX helpers (baseline set only: mma.sync / ldmatrix / cp.async / cvt)
// =====================================================================
__device__ __forceinline__ uint32_t smem_to_u32(const void* p) {
    uint32_t a;
    asm("{ .reg .u64 t; cvta.to.shared.u64 t, %1; cvt.u32.u64 %0, t; }" : "=r"(a) : "l"(p));
    return a;
}
__device__ __forceinline__ void ldsm4(uint32_t* r, uint32_t addr) {
    asm volatile("ldmatrix.sync.aligned.m8n8.x4.shared.b16 {%0,%1,%2,%3}, [%4];"
        : "=r"(r[0]), "=r"(r[1]), "=r"(r[2]), "=r"(r[3]) : "r"(addr));
}
__device__ __forceinline__ void ldsm4t(uint32_t* r, uint32_t addr) {
    asm volatile("ldmatrix.sync.aligned.m8n8.x4.trans.shared.b16 {%0,%1,%2,%3}, [%4];"
        : "=r"(r[0]), "=r"(r[1]), "=r"(r[2]), "=r"(r[3]) : "r"(addr));
}
__device__ __forceinline__ void mma16816(float* d, const uint32_t* a, const uint32_t* b) {
    asm volatile("mma.sync.aligned.m16n8k16.row.col.f32.bf16.bf16.f32 "
        "{%0,%1,%2,%3}, {%4,%5,%6,%7}, {%8,%9}, {%0,%1,%2,%3};"
        : "+f"(d[0]), "+f"(d[1]), "+f"(d[2]), "+f"(d[3])
        : "r"(a[0]), "r"(a[1]), "r"(a[2]), "r"(a[3]), "r"(b[0]), "r"(b[1]));
}
__device__ __forceinline__ void mma16816h(float* d, const uint32_t* a, const uint32_t* b) {
    asm volatile("mma.sync.aligned.m16n8k16.row.col.f32.f16.f16.f32 "
        "{%0,%1,%2,%3}, {%4,%5,%6,%7}, {%8,%9}, {%0,%1,%2,%3};"
        : "+f"(d[0]), "+f"(d[1]), "+f"(d[2]), "+f"(d[3])
        : "r"(a[0]), "r"(a[1]), "r"(a[2]), "r"(a[3]), "r"(b[0]), "r"(b[1]));
}
#define CP_ASYNC16(dst, src) \
    asm volatile("cp.async.cg.shared.global [%0], [%1], 16;" :: "r"(dst), "l"(src))
#define CP_COMMIT()  asm volatile("cp.async.commit_group;" ::: "memory")
#define CP_WAIT(n)   asm volatile("cp.async.wait_group %0;" :: "n"(n) : "memory")

__device__ __forceinline__ void split_bf16(float v, __nv_bfloat16& h, __nv_bfloat16& l) {
    h = __float2bfloat16(v);
    l = __float2bfloat16(v - __bfloat162float(h));
}

// =====================================================================
// conversion kernels (fp32 -> fp16 RN)
// =====================================================================
__global__ void conv_act3_kernel(const float* __restrict__ s0,
                                 const float* __restrict__ s1,
                                 const float* __restrict__ s2)
{
    int z = blockIdx.y;
    const float* src = (z == 0) ? s0 : ((z == 1) ? s1 : s2);
    size_t i4 = (size_t)blockIdx.x * 256 + threadIdx.x;
    float4 v = *(const float4*)&src[i4 * 4];
    __half h[4];
    h[0] = __float2half_rn(v.x); h[1] = __float2half_rn(v.y);
    h[2] = __float2half_rn(v.z); h[3] = __float2half_rn(v.w);
    *(uint2*)&g_a16[(size_t)z * NTOK_ * DM_ + i4 * 4] = *(uint2*)h;
}

__global__ void conv_wt_kernel(const float* __restrict__ W, int slot)
{
    __shared__ float t[32][33];
    int x = blockIdx.x * 32 + threadIdx.x;
    int y = blockIdx.y * 32 + threadIdx.y;
    #pragma unroll
    for (int j = 0; j < 32; j += 8) t[threadIdx.y + j][threadIdx.x] = W[(size_t)(y + j) * 1024 + x];
    __syncthreads();
    int xo = blockIdx.y * 32 + threadIdx.x;
    int yo = blockIdx.x * 32 + threadIdx.y;
    size_t base = (size_t)slot * DM_ * DM_;
    #pragma unroll
    for (int j = 0; j < 32; j += 8)
        g_w16[base + (size_t)(yo + j) * 1024 + xo] = __float2half_rn(t[threadIdx.x][threadIdx.y + j]);
}

// =====================================================================
// projection GEMM — 1-term FP16, BK=32, 2-stage cp.async, 40960 B smem.
// mode = -1: fused QKV (z selects A/W slot; q,k -> split bf16, v -> fp16)
// mode =  3: output projection (A slot 0, W slot 3, fp32 out, bias = b0p)
// =====================================================================
#define H_TSZ   10240
#define H_STG   (2 * H_TSZ)     // 20480
#define H_SM    (2 * H_STG)     // 40960

__global__ __launch_bounds__(256) void gemm_fp16_kernel(
    const float* __restrict__ b0p, const float* __restrict__ b1p,
    const float* __restrict__ b2p, float* __restrict__ outp, int mode)
{
    const uint32_t sbase = smem_to_u32(dynsm);

    const int z  = (mode == 3) ? 0 : blockIdx.z;
    const int wz = (mode == 3) ? 3 : z;
    const float* bias = (mode == 3) ? b0p : ((z == 0) ? b0p : ((z == 1) ? b1p : b2p));
    const __half* Ah = g_a16 + (size_t)z * NTOK_ * DM_;
    const __half* Wh = g_w16 + (size_t)wz * DM_ * DM_;

    const int tid  = threadIdx.x;
    const int lane = tid & 31;
    const int w    = tid >> 5;
    const int wm   = w >> 2;
    const int wn   = w & 3;
    const int n0 = blockIdx.x * 128;
    const int m0 = blockIdx.y * 128;

    float acc[4][4][4];
    #pragma unroll
    for (int i = 0; i < 4; i++)
        #pragma unroll
        for (int j = 0; j < 4; j++)
            #pragma unroll
            for (int t = 0; t < 4; t++) acc[i][j][t] = 0.f;

    auto load_chunk = [&](int c, int buf) {
        const int k0 = c * 32;
        const uint32_t sb = sbase + buf * H_STG;
        #pragma unroll
        for (int i = 0; i < 4; i++) {
            int q = tid + i * 256;
            int arr = q >> 9;
            int r   = (q >> 2) & 127;
            int c4  = q & 3;
            uint32_t dst = sb + arr * H_TSZ + r * 80 + c4 * 16;
            const __half* src = (arr == 0)
                ? &Ah[(size_t)(m0 + r) * 1024 + k0 + c4 * 8]
                : &Wh[(size_t)(n0 + r) * 1024 + k0 + c4 * 8];
            CP_ASYNC16(dst, src);
        }
        CP_COMMIT();
    };

    auto compute_chunk = [&](int buf) {
        const uint32_t S = sbase + buf * H_STG;
        #pragma unroll
        for (int k16 = 0; k16 < 2; k16++) {
            const uint32_t kb = (uint32_t)(k16 * 32);
            uint32_t af[4][4];
            #pragma unroll
            for (int mt = 0; mt < 4; mt++) {
                uint32_t addr = S
                    + (uint32_t)((wm * 64 + mt * 16 + (lane & 15)) * 80)
                    + kb + (uint32_t)((lane >> 4) * 16);
                ldsm4(af[mt], addr);
            }
            uint32_t bf[2][4];
            #pragma unroll
            for (int np = 0; np < 2; np++) {
                uint32_t nrow = (uint32_t)(wn * 32 + np * 16 + ((lane >> 4) * 8) + (lane & 7));
                uint32_t addr = S + H_TSZ + nrow * 80 + kb + (uint32_t)(((lane >> 3) & 1) * 16);
                ldsm4(bf[np], addr);
            }
            #pragma unroll
            for (int mt = 0; mt < 4; mt++)
                #pragma unroll
                for (int nt = 0; nt < 4; nt++)
                    mma16816h(acc[mt][nt], af[mt], &bf[nt >> 1][(nt & 1) * 2]);
        }
    };

    load_chunk(0, 0);
    #pragma unroll 1
    for (int c = 0; c < 32; c++) {
        if (c + 1 < 32) {
            load_chunk(c + 1, (c + 1) & 1);
            CP_WAIT(1);
        } else {
            CP_WAIT(0);
        }
        __syncthreads();
        compute_chunk(c & 1);
        __syncthreads();
    }

    #pragma unroll
    for (int mt = 0; mt < 4; mt++) {
        #pragma unroll
        for (int nt = 0; nt < 4; nt++) {
            int c = n0 + wn * 32 + nt * 8 + (lane & 3) * 2;
            float b0 = bias[c], b1 = bias[c + 1];
            #pragma unroll
            for (int half = 0; half < 2; half++) {
                int r = m0 + wm * 64 + mt * 16 + (lane >> 2) + half * 8;
                float vx = acc[mt][nt][half * 2 + 0] + b0;
                float vy = acc[mt][nt][half * 2 + 1] + b1;
                if (mode == 3) {
                    float2 t = {vx, vy};
                    *(float2*)&outp[(size_t)r * 1024 + c] = t;
                } else {
                    int b = r >> 12, l = r & 4095;
                    int h = c >> 6, d = c & 63;
                    size_t o = (((size_t)(b * 16 + h) * 4096) + l) * 64 + d;
                    if (z == 2) {
                        __half hp[2];
                        hp[0] = __float2half_rn(vx);
                        hp[1] = __float2half_rn(vy);
                        *(uint32_t*)&g_v16[o] = *(uint32_t*)hp;
                    } else {
                        __nv_bfloat16* dh = (z == 0) ? g_qh : g_kh;
                        __nv_bfloat16* dl = (z == 0) ? g_ql : g_kl;
                        __nv_bfloat16 hp[2], lp[2];
                        split_bf16(vx, hp[0], lp[0]);
                        split_bf16(vy, hp[1], lp[1]);
                        *(uint32_t*)&dh[o] = *(uint32_t*)hp;
                        *(uint32_t*)&dl[o] = *(uint32_t*)lp;
                    }
                }
            }
        }
    }
}

// =====================================================================
// landmark pooling from split q/k; writes fp32 + split landmarks
// =====================================================================
__global__ void pool_kernel()
{
    int idx = blockIdx.x * blockDim.x + threadIdx.x;   // BH*M*D
    int d  = idx & 63;
    int m  = (idx >> 6) & 127;
    int bh = idx >> 13;
    size_t base = ((size_t)bh * L_ + m * SEG_) * D_ + d;
    float sq = 0.f, sk = 0.f;
    #pragma unroll
    for (int s = 0; s < SEG_; s++) {
        sq += __bfloat162float(g_qh[base + s * D_]) + __bfloat162float(g_ql[base + s * D_]);
        sk += __bfloat162float(g_kh[base + s * D_]) + __bfloat162float(g_kl[base + s * D_]);
    }
    float mq = sq * (1.f / SEG_), mk = sk * (1.f / SEG_);
    g_Ql[idx] = mq; g_Kl[idx] = mk;
    __nv_bfloat16 h, l;
    split_bf16(mq, h, l); g_Qlh[idx] = h; g_Qll[idx] = l;
    split_bf16(mk, h, l); g_Klh[idx] = h; g_Kll[idx] = l;
}

// =====================================================================
// k1: C[128 tok][128 lm] = q_blk @ Kl^T (3-term split mma) + fused softmax
// -> single fp16 probs g_k116
// =====================================================================
__global__ __launch_bounds__(256) void k1_mma_kernel()
{
    char* sm = dynsm;
    const uint32_t sb = smem_to_u32(sm);
    int bh = blockIdx.y, l0 = blockIdx.x * 128, tid = threadIdx.x;
    int lane = tid & 31, w = tid >> 5;

    {
        const __nv_bfloat16* qh = g_qh + ((size_t)bh * L_ + l0) * D_;
        const __nv_bfloat16* ql = g_ql + ((size_t)bh * L_ + l0) * D_;
        const __nv_bfloat16* kh = g_Klh + bh * (M_ * D_);
        const __nv_bfloat16* kl = g_Kll + bh * (M_ * D_);
        #pragma unroll
        for (int i = 0; i < 4; i++) {
            int q = tid + i * 256;
            int row = q >> 3, c8 = q & 7;
            uint32_t so = (uint32_t)(row * 144 + c8 * 16);
            size_t go = (size_t)row * 64 + c8 * 8;
            *(uint4*)(sm + 0     + so) = *(const uint4*)&qh[go];
            *(uint4*)(sm + 18432 + so) = *(const uint4*)&ql[go];
            *(uint4*)(sm + 36864 + so) = *(const uint4*)&kh[go];
            *(uint4*)(sm + 55296 + so) = *(const uint4*)&kl[go];
        }
    }
    __syncthreads();

    int wm = w >> 2, wn = w & 3;
    float acc[4][4][4];
    #pragma unroll
    for (int i = 0; i < 4; i++)
        #pragma unroll
        for (int j = 0; j < 4; j++)
            #pragma unroll
            for (int t = 0; t < 4; t++) acc[i][j][t] = 0.f;

    #pragma unroll
    for (int k16 = 0; k16 < 4; k16++) {
        uint32_t af[2][4][4];
        #pragma unroll
        for (int term = 0; term < 2; term++)
            #pragma unroll
            for (int mt = 0; mt < 4; mt++) {
                uint32_t addr = sb + term * 18432
                    + (uint32_t)((wm * 64 + mt * 16 + (lane & 15)) * 144)
                    + (uint32_t)(k16 * 32) + (uint32_t)((lane >> 4) * 16);
                ldsm4(af[term][mt], addr);
            }
        uint32_t bf[2][2][4];
        #pragma unroll
        for (int term = 0; term < 2; term++)
            #pragma unroll
            for (int np = 0; np < 2; np++) {
                uint32_t nrow = (uint32_t)(wn * 32 + np * 16 + ((lane >> 4) * 8) + (lane & 7));
                uint32_t addr = sb + 36864 + term * 18432 + nrow * 144
                    + (uint32_t)(k16 * 32) + (uint32_t)(((lane >> 3) & 1) * 16);
                ldsm4(bf[term][np], addr);
            }
        #pragma unroll
        for (int mt = 0; mt < 4; mt++)
            #pragma unroll
            for (int nt = 0; nt < 4; nt++) {
                float* d = acc[mt][nt];
                const uint32_t* bh_ = &bf[0][nt >> 1][(nt & 1) * 2];
                const uint32_t* bl_ = &bf[1][nt >> 1][(nt & 1) * 2];
                mma16816(d, af[0][mt], bh_);
                mma16816(d, af[0][mt], bl_);
                mma16816(d, af[1][mt], bh_);
            }
    }
    __syncthreads();

    float* S = (float*)sm;
    #pragma unroll
    for (int mt = 0; mt < 4; mt++)
        #pragma unroll
        for (int nt = 0; nt < 4; nt++)
            #pragma unroll
            for (int half = 0; half < 2; half++) {
                int row = wm * 64 + mt * 16 + (lane >> 2) + half * 8;
                int col = wn * 32 + nt * 8 + (lane & 3) * 2;
                S[row * 128 + col]     = acc[mt][nt][half * 2 + 0];
                S[row * 128 + col + 1] = acc[mt][nt][half * 2 + 1];
            }
    __syncthreads();

    for (int rr = 0; rr < 16; rr++) {
        int row = w * 16 + rr;
        float x0 = S[row * 128 + lane],      x1 = S[row * 128 + lane + 32];
        float x2 = S[row * 128 + lane + 64], x3 = S[row * 128 + lane + 96];
        float mx = fmaxf(fmaxf(x0, x1), fmaxf(x2, x3));
        #pragma unroll
        for (int o = 16; o; o >>= 1) mx = fmaxf(mx, __shfl_xor_sync(0xffffffffu, mx, o));
        float e0 = __expf(x0 - mx), e1 = __expf(x1 - mx);
        float e2 = __expf(x2 - mx), e3 = __expf(x3 - mx);
        float s = e0 + e1 + e2 + e3;
        #pragma unroll
        for (int o = 16; o; o >>= 1) s += __shfl_xor_sync(0xffffffffu, s, o);
        float inv = 1.f / s;
        size_t ob = ((size_t)bh * L_ + l0 + row) * 128;
        g_k116[ob + lane]      = __float2half_rn(e0 * inv);
        g_k116[ob + lane + 32] = __float2half_rn(e1 * inv);
        g_k116[ob + lane + 64] = __float2half_rn(e2 * inv);
        g_k116[ob + lane + 96] = __float2half_rn(e3 * inv);
    }
}

// =====================================================================
// k3 scores: C[m=128][l=128 blk] = Ql @ k_blk^T (3-term split) -> fp32 g_k3
// =====================================================================
__global__ __launch_bounds__(256) void k3score_mma_kernel()
{
    char* sm = dynsm;
    const uint32_t sb = smem_to_u32(sm);
    int bh = blockIdx.y, l0 = blockIdx.x * 128, tid = threadIdx.x;
    int lane = tid & 31, w = tid >> 5;

    {
        const __nv_bfloat16* ah = g_Qlh + bh * (M_ * D_);
        const __nv_bfloat16* al = g_Qll + bh * (M_ * D_);
        const __nv_bfloat16* bhp = g_kh + ((size_t)bh * L_ + l0) * D_;
        const __nv_bfloat16* blp = g_kl + ((size_t)bh * L_ + l0) * D_;
        #pragma unroll
        for (int i = 0; i < 4; i++) {
            int q = tid + i * 256;
            int row = q >> 3, c8 = q & 7;
            uint32_t so = (uint32_t)(row * 144 + c8 * 16);
            size_t go = (size_t)row * 64 + c8 * 8;
            *(uint4*)(sm + 0     + so) = *(const uint4*)&ah[go];
            *(uint4*)(sm + 18432 + so) = *(const uint4*)&al[go];
            *(uint4*)(sm + 36864 + so) = *(const uint4*)&bhp[go];
            *(uint4*)(sm + 55296 + so) = *(const uint4*)&blp[go];
        }
    }
    __syncthreads();

    int wm = w >> 2, wn = w & 3;
    float acc[4][4][4];
    #pragma unroll
    for (int i = 0; i < 4; i++)
        #pragma unroll
        for (int j = 0; j < 4; j++)
            #pragma unroll
            for (int t = 0; t < 4; t++) acc[i][j][t] = 0.f;

    #pragma unroll
    for (int k16 = 0; k16 < 4; k16++) {
        uint32_t af[2][4][4];
        #pragma unroll
        for (int term = 0; term < 2; term++)
            #pragma unroll
            for (int mt = 0; mt < 4; mt++) {
                uint32_t addr = sb + term * 18432
                    + (uint32_t)((wm * 64 + mt * 16 + (lane & 15)) * 144)
                    + (uint32_t)(k16 * 32) + (uint32_t)((lane >> 4) * 16);
                ldsm4(af[term][mt], addr);
            }
        uint32_t bf[2][2][4];
        #pragma unroll
        for (int term = 0; term < 2; term++)
            #pragma unroll
            for (int np = 0; np < 2; np++) {
                uint32_t nrow = (uint32_t)(wn * 32 + np * 16 + ((lane >> 4) * 8) + (lane & 7));
                uint32_t addr = sb + 36864 + term * 18432 + nrow * 144
                    + (uint32_t)(k16 * 32) + (uint32_t)(((lane >> 3) & 1) * 16);
                ldsm4(bf[term][np], addr);
            }
        #pragma unroll
        for (int mt = 0; mt < 4; mt++)
            #pragma unroll
            for (int nt = 0; nt < 4; nt++) {
                float* d = acc[mt][nt];
                const uint32_t* bh_ = &bf[0][nt >> 1][(nt & 1) * 2];
                const uint32_t* bl_ = &bf[1][nt >> 1][(nt & 1) * 2];
                mma16816(d, af[0][mt], bh_);
                mma16816(d, af[0][mt], bl_);
                mma16816(d, af[1][mt], bh_);
            }
    }

    float* o = g_k3 + (size_t)bh * M_ * L_;
    #pragma unroll
    for (int mt = 0; mt < 4; mt++)
        #pragma unroll
        for (int nt = 0; nt < 4; nt++)
            #pragma unroll
            for (int half = 0; half < 2; half++) {
                int m_r = wm * 64 + mt * 16 + (lane >> 2) + half * 8;
                int l_c = l0 + wn * 32 + nt * 8 + (lane & 3) * 2;
                float2 t = {acc[mt][nt][half * 2 + 0], acc[mt][nt][half * 2 + 1]};
                *(float2*)&o[(size_t)m_r * L_ + l_c] = t;
            }
}

// =====================================================================
// row softmax over 4096; reads fp32 g_k3, writes single fp16 g_s316
// =====================================================================
__global__ __launch_bounds__(256) void softmax4096_kernel()
{
    size_t row = blockIdx.x;
    const float* p = g_k3 + row * 4096;
    int tid = threadIdx.x;
    float v[16];
    float mx = -1e30f;
    #pragma unroll
    for (int i = 0; i < 4; i++) {
        float4 t = *(const float4*)&p[i * 1024 + tid * 4];
        v[i * 4 + 0] = t.x; v[i * 4 + 1] = t.y; v[i * 4 + 2] = t.z; v[i * 4 + 3] = t.w;
        mx = fmaxf(mx, fmaxf(fmaxf(t.x, t.y), fmaxf(t.z, t.w)));
    }
    __shared__ float smx[8], ssm[8], sres;
    #pragma unroll
    for (int o = 16; o; o >>= 1) mx = fmaxf(mx, __shfl_xor_sync(0xffffffffu, mx, o));
    if ((tid & 31) == 0) smx[tid >> 5] = mx;
    __syncthreads();
    if (tid == 0) {
        float m = smx[0];
        #pragma unroll
        for (int i = 1; i < 8; i++) m = fmaxf(m, smx[i]);
        sres = m;
    }
    __syncthreads();
    float MX = sres;
    float s = 0.f;
    #pragma unroll
    for (int i = 0; i < 16; i++) { v[i] = __expf(v[i] - MX); s += v[i]; }
    #pragma unroll
    for (int o = 16; o; o >>= 1) s += __shfl_xor_sync(0xffffffffu, s, o);
    if ((tid & 31) == 0) ssm[tid >> 5] = s;
    __syncthreads();
    if (tid == 0) {
        float t = 0.f;
        #pragma unroll
        for (int i = 0; i < 8; i++) t += ssm[i];
        sres = 1.f / t;
    }
    __syncthreads();
    float inv = sres;
    #pragma unroll
    for (int i = 0; i < 4; i++) {
        __half hh[4];
        #pragma unroll
        for (int t = 0; t < 4; t++) hh[t] = __float2half_rn(v[i * 4 + t] * inv);
        *(uint2*)&g_s316[row * 4096 + i * 1024 + tid * 4] = *(uint2*)hh;
    }
}

// =====================================================================
// kernel_2 = softmax(Q_l @ K_l^T) fused (fp32, tiny). block per head.
// =====================================================================
__global__ __launch_bounds__(256) void k2_kernel()
{
    float* sm = (float*)dynsm;
    float* Qlt = sm;
    float* Klt = sm + 8192;
    float* S   = sm + 16384;
    int bh = blockIdx.x, tid = threadIdx.x;

    const float* Ql = g_Ql + bh * 8192;
    const float* Kl = g_Kl + bh * 8192;
    #pragma unroll
    for (int i = 0; i < 8; i++) {
        int f = i * 1024 + tid * 4; int m = f >> 6, d0 = f & 63;
        float4 tq = *(const float4*)&Ql[f];
        float4 tk = *(const float4*)&Kl[f];
        Qlt[(d0 + 0) * 128 + m] = tq.x; Qlt[(d0 + 1) * 128 + m] = tq.y;
        Qlt[(d0 + 2) * 128 + m] = tq.z; Qlt[(d0 + 3) * 128 + m] = tq.w;
        Klt[(d0 + 0) * 128 + m] = tk.x; Klt[(d0 + 1) * 128 + m] = tk.y;
        Klt[(d0 + 2) * 128 + m] = tk.z; Klt[(d0 + 3) * 128 + m] = tk.w;
    }
    __syncthreads();

    int tm = tid >> 4, tn = tid & 15;
    float acc[8][8] = {};
    for (int d = 0; d < 64; d++) {
        float4 a0 = *(const float4*)&Qlt[d * 128 + tm * 8];
        float4 a1 = *(const float4*)&Qlt[d * 128 + tm * 8 + 4];
        float4 b0 = *(const float4*)&Klt[d * 128 + tn * 8];
        float4 b1 = *(const float4*)&Klt[d * 128 + tn * 8 + 4];
        float av[8] = {a0.x, a0.y, a0.z, a0.w, a1.x, a1.y, a1.z, a1.w};
        float bv[8] = {b0.x, b0.y, b0.z, b0.w, b1.x, b1.y, b1.z, b1.w};
        #pragma unroll
        for (int i = 0; i < 8; i++)
            #pragma unroll
            for (int j = 0; j < 8; j++) acc[i][j] += av[i] * bv[j];
    }
    #pragma unroll
    for (int i = 0; i < 8; i++)
        #pragma unroll
        for (int j = 0; j < 8; j++) S[(tm * 8 + i) * 128 + tn * 8 + j] = acc[i][j];
    __syncthreads();

    int lane = tid & 31, w = tid >> 5;
    for (int rr = 0; rr < 16; rr++) {
        int row = w * 16 + rr;
        float x0 = S[row * 128 + lane],      x1 = S[row * 128 + lane + 32];
        float x2 = S[row * 128 + lane + 64], x3 = S[row * 128 + lane + 96];
        float mx = fmaxf(fmaxf(x0, x1), fmaxf(x2, x3));
        #pragma unroll
        for (int o = 16; o; o >>= 1) mx = fmaxf(mx, __shfl_xor_sync(0xffffffffu, mx, o));
        float e0 = __expf(x0 - mx), e1 = __expf(x1 - mx);
        float e2 = __expf(x2 - mx), e3 = __expf(x3 - mx);
        float s = e0 + e1 + e2 + e3;
        #pragma unroll
        for (int o = 16; o; o >>= 1) s += __shfl_xor_sync(0xffffffffu, s, o);
        float inv = 1.f / s;
        float* o = g_k2 + bh * 16384 + row * 128;
        o[lane] = e0 * inv; o[lane + 32] = e1 * inv; o[lane + 64] = e2 * inv; o[lane + 96] = e3 * inv;
    }
}

// =====================================================================
// V0 = K^T / max(colsum(K))
// =====================================================================
__global__ __launch_bounds__(256) void vinit_kernel()
{
    int bh = blockIdx.x, tid = threadIdx.x;
    const float* K = g_k2 + bh * 16384;
    __shared__ float cs[128];
    __shared__ float sscale;
    if (tid < 128) {
        float s = 0.f;
        for (int r = 0; r < 128; r++) s += K[r * 128 + tid];
        cs[tid] = s;
    }
    __syncthreads();
    if (tid == 0) {
        float m = cs[0];
        for (int i = 1; i < 128; i++) m = fmaxf(m, cs[i]);
        sscale = 1.f / m;
    }
    __syncthreads();
    float scale = sscale;
    for (int f = tid; f < 16384; f += 256) {
        int i = f >> 7, j = f & 127;
        g_Va[bh * 16384 + f] = scale * K[j * 128 + i];
    }
}

// =====================================================================
// batched 128x128 bmm for Newton-Schulz (fp32)
// =====================================================================
__device__ __forceinline__ float* bufsel(int s)
{
    switch (s) {
        case 0: return g_k2; case 1: return g_P; case 2: return g_M1;
        case 3: return g_M2; case 4: return g_Va; default: return g_Vb;
    }
}

__global__ __launch_bounds__(256) void bmm_kernel(int as, int bs, int cs2, int os,
                                                  float alpha, float beta)
{
    float* sm = (float*)dynsm;
    float* Bs = sm;
    float* At = sm + 16384;
    int bh = blockIdx.y, r0 = blockIdx.x * 32, tid = threadIdx.x;
    const float* A  = bufsel(as)  + bh * 16384;
    const float* Bm = bufsel(bs)  + bh * 16384;
    const float* C  = bufsel(cs2) + bh * 16384;
    float* O        = bufsel(os)  + bh * 16384;

    #pragma unroll
    for (int i = 0; i < 16; i++) {
        int f = i * 1024 + tid * 4;
        *(float4*)&Bs[f] = *(const float4*)&Bm[f];
    }
    #pragma unroll
    for (int i = 0; i < 4; i++) {
        int f = i * 1024 + tid * 4; int r = f >> 7, k0 = f & 127;
        float4 t = *(const float4*)&A[(r0 + r) * 128 + k0];
        At[(k0 + 0) * 32 + r] = t.x; At[(k0 + 1) * 32 + r] = t.y;
        At[(k0 + 2) * 32 + r] = t.z; At[(k0 + 3) * 32 + r] = t.w;
    }
    __syncthreads();

    int rb = (tid >> 5) * 4, cb = (tid & 31) * 4;
    float acc[4][4] = {};
    for (int k = 0; k < 128; k++) {
        float a0 = At[k * 32 + rb + 0], a1 = At[k * 32 + rb + 1];
        float a2 = At[k * 32 + rb + 2], a3 = At[k * 32 + rb + 3];
        float4 b = *(const float4*)&Bs[k * 128 + cb];
        acc[0][0] += a0 * b.x; acc[0][1] += a0 * b.y; acc[0][2] += a0 * b.z; acc[0][3] += a0 * b.w;
        acc[1][0] += a1 * b.x; acc[1][1] += a1 * b.y; acc[1][2] += a1 * b.z; acc[1][3] += a1 * b.w;
        acc[2][0] += a2 * b.x; acc[2][1] += a2 * b.y; acc[2][2] += a2 * b.z; acc[2][3] += a2 * b.w;
        acc[3][0] += a3 * b.x; acc[3][1] += a3 * b.y; acc[3][2] += a3 * b.z; acc[3][3] += a3 * b.w;
    }
    #pragma unroll
    for (int i = 0; i < 4; i++)
        #pragma unroll
        for (int j = 0; j < 4; j++) {
            int idx = (r0 + rb + i) * 128 + cb + j;
            O[idx] = alpha * acc[i][j] + beta * C[idx];
        }
}

// =====================================================================
// k3v: partial C[m=128][d=64] = s3_fp16 @ v_fp16 (1-term, split-K 4)
// 2-stage pipeline. stage = A(18432) + B(9216) = 27648; dyn smem 55296
// =====================================================================
#define KV_TS_A 18432
#define KV_STG  27648

__global__ __launch_bounds__(256) void k3v_mma_kernel()
{
    char* sm = dynsm;
    const uint32_t sb = smem_to_u32(sm);
    int s = blockIdx.x, bh = blockIdx.y, tid = threadIdx.x;
    int lane = tid & 31, w = tid >> 5;
    int wm = w >> 1, wn = w & 1;
    const size_t abase = (size_t)bh * M_ * L_;
    const size_t vbase = (size_t)bh * L_ * D_;

    float acc[2][4][4];
    #pragma unroll
    for (int i = 0; i < 2; i++)
        #pragma unroll
        for (int j = 0; j < 4; j++)
            #pragma unroll
            for (int t = 0; t < 4; t++) acc[i][j][t] = 0.f;

    auto load = [&](int ck, int buf) {
        int k0 = s * 1024 + ck * 64;
        uint32_t S = sb + buf * KV_STG;
        #pragma unroll
        for (int i = 0; i < 4; i++) {               // A: probs, 128 rows x 128 B
            int q = tid + i * 256;
            int row = q >> 3, c8 = q & 7;
            uint32_t dst = S + (uint32_t)(row * 144 + c8 * 16);
            CP_ASYNC16(dst, g_s316 + abase + (size_t)row * L_ + k0 + c8 * 8);
        }
        #pragma unroll
        for (int i = 0; i < 2; i++) {               // B: v, 64 rows x 128 B
            int q = tid + i * 256;
            int row = q >> 3, c8 = q & 7;
            uint32_t dst = S + KV_TS_A + (uint32_t)(row * 144 + c8 * 16);
            CP_ASYNC16(dst, g_v16 + vbase + (size_t)(k0 + row) * D_ + c8 * 8);
        }
        CP_COMMIT();
    };

    auto compute = [&](int buf) {
        uint32_t S = sb + buf * KV_STG;
        #pragma unroll
        for (int k16 = 0; k16 < 4; k16++) {
            uint32_t af[2][4];
            #pragma unroll
            for (int mt = 0; mt < 2; mt++) {
                uint32_t addr = S
                    + (uint32_t)((wm * 32 + mt * 16 + (lane & 15)) * 144)
                    + (uint32_t)(k16 * 32) + (uint32_t)((lane >> 4) * 16);
                ldsm4(af[mt], addr);
            }
            uint32_t bf[2][4];
            #pragma unroll
            for (int np = 0; np < 2; np++) {
                uint32_t addr = S + KV_TS_A
                    + (uint32_t)((k16 * 16 + (lane & 15)) * 144)
                    + (uint32_t)((wn * 32 + np * 16 + (lane >> 4) * 8) * 2);
                ldsm4t(bf[np], addr);
            }
            #pragma unroll
            for (int mt = 0; mt < 2; mt++)
                #pragma unroll
                for (int nt = 0; nt < 4; nt++)
                    mma16816h(acc[mt][nt], af[mt], &bf[nt >> 1][(nt & 1) * 2]);
        }
    };

    load(0, 0);
    #pragma unroll 1
    for (int ck = 0; ck < 16; ck++) {
        if (ck + 1 < 16) {
            load(ck + 1, (ck + 1) & 1);
            CP_WAIT(1);
        } else {
            CP_WAIT(0);
        }
        __syncthreads();
        compute(ck & 1);
        __syncthreads();
    }

    #pragma unroll
    for (int mt = 0; mt < 2; mt++)
        #pragma unroll
        for (int nt = 0; nt < 4; nt++)
            #pragma unroll
            for (int half = 0; half < 2; half++) {
                int m_r = wm * 32 + mt * 16 + (lane >> 2) + half * 8;
                int d_c = wn * 32 + nt * 8 + (lane & 3) * 2;
                float2 t = {acc[mt][nt][half * 2 + 0], acc[mt][nt][half * 2 + 1]};
                *(float2*)&g_k3v_part[((size_t)(s * 64 + bh) * 128 + m_r) * 64 + d_c] = t;
            }
}

// =====================================================================
// y2 = inv(g_Va) @ sum(k3v parts) per head (fp32); emits y2^T single fp16
// =====================================================================
__global__ __launch_bounds__(256) void y2_kernel()
{
    float* sm = (float*)dynsm;
    float* At = sm;
    float* Bs = sm + 16384;
    int bh = blockIdx.x, tid = threadIdx.x;
    const float* inv = g_Va + bh * 16384;

    #pragma unroll
    for (int i = 0; i < 16; i++) {
        int f = i * 1024 + tid * 4; int r = f >> 7, k0 = f & 127;
        float4 t = *(const float4*)&inv[f];
        At[(k0 + 0) * 128 + r] = t.x; At[(k0 + 1) * 128 + r] = t.y;
        At[(k0 + 2) * 128 + r] = t.z; At[(k0 + 3) * 128 + r] = t.w;
    }
    #pragma unroll
    for (int i = 0; i < 8; i++) {
        int f = i * 1024 + tid * 4;
        size_t o = (size_t)bh * 8192 + f;
        float4 a = *(const float4*)&g_k3v_part[o];
        float4 b = *(const float4*)&g_k3v_part[o + 524288];
        float4 c = *(const float4*)&g_k3v_part[o + 2 * 524288];
        float4 d = *(const float4*)&g_k3v_part[o + 3 * 524288];
        float4 t = {a.x + b.x + c.x + d.x, a.y + b.y + c.y + d.y,
                    a.z + b.z + c.z + d.z, a.w + b.w + c.w + d.w};
        *(float4*)&Bs[f] = t;
    }
    __syncthreads();

    int rt = tid >> 4, ct = tid & 15;
    float acc[8][4] = {};
    for (int k = 0; k < 128; k++) {
        float4 a0 = *(const float4*)&At[k * 128 + rt * 8];
        float4 a1 = *(const float4*)&At[k * 128 + rt * 8 + 4];
        float4 b  = *(const float4*)&Bs[k * 64 + ct * 4];
        float av[8] = {a0.x, a0.y, a0.z, a0.w, a1.x, a1.y, a1.z, a1.w};
        #pragma unroll
        for (int i = 0; i < 8; i++) {
            acc[i][0] += av[i] * b.x; acc[i][1] += av[i] * b.y;
            acc[i][2] += av[i] * b.z; acc[i][3] += av[i] * b.w;
        }
    }
    #pragma unroll
    for (int i = 0; i < 8; i++)
        #pragma unroll
        for (int j = 0; j < 4; j++) {
            size_t o = (size_t)bh * 8192 + (ct * 4 + j) * 128 + rt * 8 + i;
            g_y2t16[o] = __float2half_rn(acc[i][j]);
        }
}

// =====================================================================
// x1: C[l=128][d=64] = k1_fp16 @ y2t_fp16 (1-term) -> g_a16 slot 0
// smem: A 34816 | B 17408 ; dyn smem 52224 (pitch 272 B)
// =====================================================================
__global__ __launch_bounds__(256) void x1_mma_kernel()
{
    char* sm = dynsm;
    const uint32_t sb = smem_to_u32(sm);
    int bh = blockIdx.y, l0 = blockIdx.x * 128, tid = threadIdx.x;
    int lane = tid & 31, w = tid >> 5;
    int wm = w >> 1, wn = w & 1;

    {
        const __half* ap = g_k116 + ((size_t)bh * L_ + l0) * 128;
        #pragma unroll
        for (int i = 0; i < 8; i++) {
            int q = tid + i * 256;                 // 0..2047
            int row = q >> 4, c16 = q & 15;
            uint32_t so = (uint32_t)(row * 272 + c16 * 16);
            *(uint4*)(sm + so) = *(const uint4*)&ap[(size_t)row * 128 + c16 * 8];
        }
        const __half* bp = g_y2t16 + (size_t)bh * 8192;
        #pragma unroll
        for (int i = 0; i < 4; i++) {
            int q = tid + i * 256;                 // 0..1023
            int row = q >> 4, c16 = q & 15;
            uint32_t so = (uint32_t)(34816 + row * 272 + c16 * 16);
            *(uint4*)(sm + so) = *(const uint4*)&bp[(size_t)row * 128 + c16 * 8];
        }
    }
    __syncthreads();

    float acc[2][4][4];
    #pragma unroll
    for (int i = 0; i < 2; i++)
        #pragma unroll
        for (int j = 0; j < 4; j++)
            #pragma unroll
            for (int t = 0; t < 4; t++) acc[i][j][t] = 0.f;

    #pragma unroll
    for (int k16 = 0; k16 < 8; k16++) {
        uint32_t af[2][4];
        #pragma unroll
        for (int mt = 0; mt < 2; mt++) {
            uint32_t addr = sb
                + (uint32_t)((wm * 32 + mt * 16 + (lane & 15)) * 272)
                + (uint32_t)(k16 * 32) + (uint32_t)((lane >> 4) * 16);
            ldsm4(af[mt], addr);
        }
        uint32_t bf[2][4];
        #pragma unroll
        for (int np = 0; np < 2; np++) {
            uint32_t nrow = (uint32_t)(wn * 32 + np * 16 + ((lane >> 4) * 8) + (lane & 7));
            uint32_t addr = sb + 34816 + nrow * 272
                + (uint32_t)(k16 * 32) + (uint32_t)(((lane >> 3) & 1) * 16);
            ldsm4(bf[np], addr);
        }
        #pragma unroll
        for (int mt = 0; mt < 2; mt++)
            #pragma unroll
            for (int nt = 0; nt < 4; nt++)
                mma16816h(acc[mt][nt], af[mt], &bf[nt >> 1][(nt & 1) * 2]);
    }

    int b = bh >> 4, h = bh & 15;
    #pragma unroll
    for (int mt = 0; mt < 2; mt++)
        #pragma unroll
        for (int nt = 0; nt < 4; nt++)
            #pragma unroll
            for (int half = 0; half < 2; half++) {
                int l = l0 + wm * 32 + mt * 16 + (lane >> 2) + half * 8;
                int d_c = wn * 32 + nt * 8 + (lane & 3) * 2;
                size_t o = ((size_t)(b * L_ + l)) * DM_ + h * 64 + d_c;
                __half hp[2];
                hp[0] = __float2half_rn(acc[mt][nt][half * 2 + 0]);
                hp[1] = __float2half_rn(acc[mt][nt][half * 2 + 1]);
                *(uint32_t*)&g_a16[o] = *(uint32_t*)hp;
            }
}

// =====================================================================
// launch — capture-legal fork/join (side stream enters capture via ev_start)
// =====================================================================
extern "C" void kernel_launch(void* const* d_in, const int* in_sizes, int n_in,
                              void* d_out, int out_size)
{
    const float* queries = (const float*)d_in[0];
    const float* keys    = (const float*)d_in[1];
    const float* values  = (const float*)d_in[2];
    const float* Wq = (const float*)d_in[3];
    const float* bq = (const float*)d_in[4];
    const float* Wk = (const float*)d_in[5];
    const float* bk = (const float*)d_in[6];
    const float* Wv = (const float*)d_in[7];
    const float* bv = (const float*)d_in[8];
    const float* Wo = (const float*)d_in[9];
    const float* bo = (const float*)d_in[10];
    float* out = (float*)d_out;

    cudaFuncSetAttribute(gemm_fp16_kernel,   cudaFuncAttributeMaxDynamicSharedMemorySize, H_SM);
    cudaFuncSetAttribute(k1_mma_kernel,      cudaFuncAttributeMaxDynamicSharedMemorySize, 73728);
    cudaFuncSetAttribute(k3score_mma_kernel, cudaFuncAttributeMaxDynamicSharedMemorySize, 73728);
    cudaFuncSetAttribute(k3v_mma_kernel,     cudaFuncAttributeMaxDynamicSharedMemorySize, 55296);
    cudaFuncSetAttribute(x1_mma_kernel,      cudaFuncAttributeMaxDynamicSharedMemorySize, 52224);
    cudaFuncSetAttribute(k2_kernel,          cudaFuncAttributeMaxDynamicSharedMemorySize, 131072);
    cudaFuncSetAttribute(bmm_kernel,         cudaFuncAttributeMaxDynamicSharedMemorySize, 81920);
    cudaFuncSetAttribute(y2_kernel,          cudaFuncAttributeMaxDynamicSharedMemorySize, 98304);

    static cudaStream_t s_b = nullptr;
    static cudaEvent_t ev_start = nullptr, ev_wt = nullptr, ev_fork = nullptr, ev_join = nullptr;
    if (!s_b) {
        cudaStreamCreateWithFlags(&s_b, cudaStreamNonBlocking);
        cudaEventCreateWithFlags(&ev_start, cudaEventDisableTiming);
        cudaEventCreateWithFlags(&ev_wt,    cudaEventDisableTiming);
        cudaEventCreateWithFlags(&ev_fork,  cudaEventDisableTiming);
        cudaEventCreateWithFlags(&ev_join,  cudaEventDisableTiming);
    }

    dim3 wt_grid(32, 32), wt_blk(32, 8);

    // fork side stream INTO the capture before any s_b work
    cudaEventRecord(ev_start, 0);
    cudaStreamWaitEvent(s_b, ev_start, 0);

    // weight conversions on side stream, activation conversion on main
    conv_wt_kernel<<<wt_grid, wt_blk, 0, s_b>>>(Wq, 0);
    conv_wt_kernel<<<wt_grid, wt_blk, 0, s_b>>>(Wk, 1);
    conv_wt_kernel<<<wt_grid, wt_blk, 0, s_b>>>(Wv, 2);
    conv_wt_kernel<<<wt_grid, wt_blk, 0, s_b>>>(Wo, 3);
    cudaEventRecord(ev_wt, s_b);
    conv_act3_kernel<<<dim3(16384, 3), 256>>>(queries, keys, values);
    cudaStreamWaitEvent(0, ev_wt, 0);

    // fused QKV projection (fp16 1-term)
    gemm_fp16_kernel<<<dim3(8, 128, 3), 256, H_SM>>>(bq, bk, bv, nullptr, -1);

    // landmarks (both branches depend on this)
    pool_kernel<<<2048, 256>>>();

    // ---- fork: Newton-Schulz chain on side stream ----
    cudaEventRecord(ev_fork, 0);
    cudaStreamWaitEvent(s_b, ev_fork, 0);
    k2_kernel<<<64, 256, 131072, s_b>>>();
    vinit_kernel<<<64, 256, 0, s_b>>>();
    {
        int cur = 4, nxt = 5;
        for (int it = 0; it < 6; it++) {
            bmm_kernel<<<dim3(4, 64), 256, 81920, s_b>>>(0,   cur, 0,   1,   1.0f,  0.0f);
            bmm_kernel<<<dim3(4, 64), 256, 81920, s_b>>>(1,   1,   1,   2,  -1.0f,  7.0f);
            bmm_kernel<<<dim3(4, 64), 256, 81920, s_b>>>(1,   2,   1,   3,  -1.0f, 15.0f);
            bmm_kernel<<<dim3(4, 64), 256, 81920, s_b>>>(cur, 3,   cur, nxt, -0.25f, 3.25f);
            int t = cur; cur = nxt; nxt = t;
        }
    }
    cudaEventRecord(ev_join, s_b);

    // ---- main stream: big attention chain ----
    k1_mma_kernel<<<dim3(32, 64), 256, 73728>>>();
    k3score_mma_kernel<<<dim3(32, 64), 256, 73728>>>();
    softmax4096_kernel<<<8192, 256>>>();
    k3v_mma_kernel<<<dim3(4, 64), 256, 55296>>>();

    // ---- join: y2 needs g_Va (side) + k3v parts (main) ----
    cudaStreamWaitEvent(0, ev_join, 0);
    y2_kernel<<<64, 256, 98304>>>();
    x1_mma_kernel<<<dim3(32, 64), 256, 52224>>>();

    // output projection (A slot 0, W slot 3)
    gemm_fp16_kernel<<<dim3(8, 128, 1), 256, H_SM>>>(bo, nullptr, nullptr, out, 3);
}

// round 13
// speedup vs baseline: 1.8923x; 1.0563x over previous
#include <cuda_runtime.h>
#include <cuda_bf16.h>
#include <cuda_fp16.h>
#include <cstdint>

// ---------------- problem constants ----------------
#define B_    4
#define L_    4096
#define DM_   1024
#define H_    16
#define D_    64
#define M_    128
#define BH_   64          // B*H
#define SEG_  32          // L/M
#define NTOK_ 16384       // B*L

// single dynamic-smem symbol for the whole TU
extern __shared__ char dynsm[];

// ---------------- scratch (device globals; no allocations allowed) ----------------
__device__ float g_Ql[BH_ * M_ * D_];          // fp32 landmarks (for k2)
__device__ float g_Kl[BH_ * M_ * D_];
__device__ float g_k3[(size_t)BH_ * M_ * L_];  // raw scores fp32
__device__ float g_k2[BH_ * M_ * M_];
__device__ float g_P [BH_ * M_ * M_];
__device__ float g_M1[BH_ * M_ * M_];
__device__ float g_M2[BH_ * M_ * M_];
__device__ float g_Va[BH_ * M_ * M_];
__device__ float g_Vb[BH_ * M_ * M_];
__device__ float g_k3v_part[4 * BH_ * M_ * D_];

// fp16 operand buffers for the 4 big GEMMs (1-term, RN-rounded)
__device__ __align__(16) __half g_a16[(size_t)3 * NTOK_ * DM_];  // A slots (slot 0 reused by x1)
__device__ __align__(16) __half g_w16[4 * DM_ * DM_];            // W^T slots (3 = Wo)

// bf16 split buffers for the logit-path GEMMs (k1, k3score)
__device__ __align__(16) __nv_bfloat16 g_qh[(size_t)BH_ * L_ * D_]; // q split [bh][l][d]
__device__ __align__(16) __nv_bfloat16 g_ql[(size_t)BH_ * L_ * D_];
__device__ __align__(16) __nv_bfloat16 g_kh[(size_t)BH_ * L_ * D_];
__device__ __align__(16) __nv_bfloat16 g_kl[(size_t)BH_ * L_ * D_];
__device__ __align__(16) __nv_bfloat16 g_Qlh[BH_ * M_ * D_];
__device__ __align__(16) __nv_bfloat16 g_Qll[BH_ * M_ * D_];
__device__ __align__(16) __nv_bfloat16 g_Klh[BH_ * M_ * D_];
__device__ __align__(16) __nv_bfloat16 g_Kll[BH_ * M_ * D_];

// single-fp16 buffers for the probability-path GEMMs (k3v, x1)
__device__ __align__(16) __half g_v16 [(size_t)BH_ * L_ * D_];   // v [bh][l][d]
__device__ __align__(16) __half g_k116[(size_t)BH_ * L_ * M_];   // kernel_1 probs [bh][l][m]
__device__ __align__(16) __half g_s316[(size_t)BH_ * M_ * L_];   // softmaxed k3 [bh][m][l]
__device__ __align__(16) __half g_y2t16[BH_ * D_ * M_];          // y2^T [bh][d][m]

// =====================================================================
// PTX helpers (baseline set only: mma.sync / ldmatrix / cp.async / cvt)
// =====================================================================
__device__ __forceinline__ uint32_t smem_to_u32(const void* p) {
    uint32_t a;
    asm("{ .reg .u64 t; cvta.to.shared.u64 t, %1; cvt.u32.u64 %0, t; }" : "=r"(a) : "l"(p));
    return a;
}
__device__ __forceinline__ void ldsm4(uint32_t* r, uint32_t addr) {
    asm volatile("ldmatrix.sync.aligned.m8n8.x4.shared.b16 {%0,%1,%2,%3}, [%4];"
        : "=r"(r[0]), "=r"(r[1]), "=r"(r[2]), "=r"(r[3]) : "r"(addr));
}
__device__ __forceinline__ void ldsm4t(uint32_t* r, uint32_t addr) {
    asm volatile("ldmatrix.sync.aligned.m8n8.x4.trans.shared.b16 {%0,%1,%2,%3}, [%4];"
        : "=r"(r[0]), "=r"(r[1]), "=r"(r[2]), "=r"(r[3]) : "r"(addr));
}
__device__ __forceinline__ void mma16816(float* d, const uint32_t* a, const uint32_t* b) {
    asm volatile("mma.sync.aligned.m16n8k16.row.col.f32.bf16.bf16.f32 "
        "{%0,%1,%2,%3}, {%4,%5,%6,%7}, {%8,%9}, {%0,%1,%2,%3};"
        : "+f"(d[0]), "+f"(d[1]), "+f"(d[2]), "+f"(d[3])
        : "r"(a[0]), "r"(a[1]), "r"(a[2]), "r"(a[3]), "r"(b[0]), "r"(b[1]));
}
__device__ __forceinline__ void mma16816h(float* d, const uint32_t* a, const uint32_t* b) {
    asm volatile("mma.sync.aligned.m16n8k16.row.col.f32.f16.f16.f32 "
        "{%0,%1,%2,%3}, {%4,%5,%6,%7}, {%8,%9}, {%0,%1,%2,%3};"
        : "+f"(d[0]), "+f"(d[1]), "+f"(d[2]), "+f"(d[3])
        : "r"(a[0]), "r"(a[1]), "r"(a[2]), "r"(a[3]), "r"(b[0]), "r"(b[1]));
}
#define CP_ASYNC16(dst, src) \
    asm volatile("cp.async.cg.shared.global [%0], [%1], 16;" :: "r"(dst), "l"(src))
#define CP_COMMIT()  asm volatile("cp.async.commit_group;" ::: "memory")
#define CP_WAIT(n)   asm volatile("cp.async.wait_group %0;" :: "n"(n) : "memory")

__device__ __forceinline__ void split_bf16(float v, __nv_bfloat16& h, __nv_bfloat16& l) {
    h = __float2bfloat16(v);
    l = __float2bfloat16(v - __bfloat162float(h));
}

// =====================================================================
// conversion kernels (fp32 -> fp16 RN)
// =====================================================================
__global__ void conv_act3_kernel(const float* __restrict__ s0,
                                 const float* __restrict__ s1,
                                 const float* __restrict__ s2)
{
    int z = blockIdx.y;
    const float* src = (z == 0) ? s0 : ((z == 1) ? s1 : s2);
    size_t i4 = (size_t)blockIdx.x * 256 + threadIdx.x;
    float4 v = *(const float4*)&src[i4 * 4];
    __half h[4];
    h[0] = __float2half_rn(v.x); h[1] = __float2half_rn(v.y);
    h[2] = __float2half_rn(v.z); h[3] = __float2half_rn(v.w);
    *(uint2*)&g_a16[(size_t)z * NTOK_ * DM_ + i4 * 4] = *(uint2*)h;
}

__global__ void conv_wt_kernel(const float* __restrict__ W, int slot)
{
    __shared__ float t[32][33];
    int x = blockIdx.x * 32 + threadIdx.x;
    int y = blockIdx.y * 32 + threadIdx.y;
    #pragma unroll
    for (int j = 0; j < 32; j += 8) t[threadIdx.y + j][threadIdx.x] = W[(size_t)(y + j) * 1024 + x];
    __syncthreads();
    int xo = blockIdx.y * 32 + threadIdx.x;
    int yo = blockIdx.x * 32 + threadIdx.y;
    size_t base = (size_t)slot * DM_ * DM_;
    #pragma unroll
    for (int j = 0; j < 32; j += 8)
        g_w16[base + (size_t)(yo + j) * 1024 + xo] = __float2half_rn(t[threadIdx.x][threadIdx.y + j]);
}

// =====================================================================
// projection GEMM — 1-term FP16, BK=64, 3-stage cp.async, ONE sync/chunk.
// stage = A(18432) + B(18432) = 36864; total 110592 (2 CTAs/SM).
// mode = -1: fused QKV (z selects A/W slot; q,k -> split bf16, v -> fp16)
// mode =  3: output projection (A slot 0, W slot 3, fp32 out, bias = b0p)
// smem row pitch 144 B (64 fp16 + 16 B pad)
// =====================================================================
#define H_TSZ   18432
#define H_STG   (2 * H_TSZ)     // 36864
#define H_SM    (3 * H_STG)     // 110592

__global__ __launch_bounds__(256, 2) void gemm_fp16_kernel(
    const float* __restrict__ b0p, const float* __restrict__ b1p,
    const float* __restrict__ b2p, float* __restrict__ outp, int mode)
{
    const uint32_t sbase = smem_to_u32(dynsm);

    const int z  = (mode == 3) ? 0 : blockIdx.z;
    const int wz = (mode == 3) ? 3 : z;
    const float* bias = (mode == 3) ? b0p : ((z == 0) ? b0p : ((z == 1) ? b1p : b2p));
    const __half* Ah = g_a16 + (size_t)z * NTOK_ * DM_;
    const __half* Wh = g_w16 + (size_t)wz * DM_ * DM_;

    const int tid  = threadIdx.x;
    const int lane = tid & 31;
    const int w    = tid >> 5;
    const int wm   = w >> 2;
    const int wn   = w & 3;
    const int n0 = blockIdx.x * 128;
    const int m0 = blockIdx.y * 128;

    float acc[4][4][4];
    #pragma unroll
    for (int i = 0; i < 4; i++)
        #pragma unroll
        for (int j = 0; j < 4; j++)
            #pragma unroll
            for (int t = 0; t < 4; t++) acc[i][j][t] = 0.f;

    auto load_chunk = [&](int c, int buf) {
        const int k0 = c * 64;
        const uint32_t sb = sbase + buf * H_STG;
        #pragma unroll
        for (int i = 0; i < 8; i++) {
            int q = tid + i * 256;           // 0..2047
            int arr = q >> 10;               // 0 = A, 1 = B
            int r   = (q >> 3) & 127;
            int c8  = q & 7;
            uint32_t dst = sb + arr * H_TSZ + r * 144 + c8 * 16;
            const __half* src = (arr == 0)
                ? &Ah[(size_t)(m0 + r) * 1024 + k0 + c8 * 8]
                : &Wh[(size_t)(n0 + r) * 1024 + k0 + c8 * 8];
            CP_ASYNC16(dst, src);
        }
        CP_COMMIT();
    };

    auto compute_chunk = [&](int buf) {
        const uint32_t S = sbase + buf * H_STG;
        #pragma unroll
        for (int k16 = 0; k16 < 4; k16++) {
            const uint32_t kb = (uint32_t)(k16 * 32);
            uint32_t af[4][4];
            #pragma unroll
            for (int mt = 0; mt < 4; mt++) {
                uint32_t addr = S
                    + (uint32_t)((wm * 64 + mt * 16 + (lane & 15)) * 144)
                    + kb + (uint32_t)((lane >> 4) * 16);
                ldsm4(af[mt], addr);
            }
            uint32_t bf[2][4];
            #pragma unroll
            for (int np = 0; np < 2; np++) {
                uint32_t nrow = (uint32_t)(wn * 32 + np * 16 + ((lane >> 4) * 8) + (lane & 7));
                uint32_t addr = S + H_TSZ + nrow * 144 + kb + (uint32_t)(((lane >> 3) & 1) * 16);
                ldsm4(bf[np], addr);
            }
            #pragma unroll
            for (int mt = 0; mt < 4; mt++)
                #pragma unroll
                for (int nt = 0; nt < 4; nt++)
                    mma16816h(acc[mt][nt], af[mt], &bf[nt >> 1][(nt & 1) * 2]);
        }
    };

    // 3-stage pipeline: wait(1) -> sync -> load(c+2) -> compute(c)
    load_chunk(0, 0);
    load_chunk(1, 1);
    #pragma unroll 1
    for (int c = 0; c < 16; c++) {
        if (c < 15) { CP_WAIT(1); } else { CP_WAIT(0); }
        __syncthreads();
        if (c + 2 < 16) load_chunk(c + 2, (c + 2) % 3);
        compute_chunk(c % 3);
    }

    #pragma unroll
    for (int mt = 0; mt < 4; mt++) {
        #pragma unroll
        for (int nt = 0; nt < 4; nt++) {
            int c = n0 + wn * 32 + nt * 8 + (lane & 3) * 2;
            float b0 = bias[c], b1 = bias[c + 1];
            #pragma unroll
            for (int half = 0; half < 2; half++) {
                int r = m0 + wm * 64 + mt * 16 + (lane >> 2) + half * 8;
                float vx = acc[mt][nt][half * 2 + 0] + b0;
                float vy = acc[mt][nt][half * 2 + 1] + b1;
                if (mode == 3) {
                    float2 t = {vx, vy};
                    *(float2*)&outp[(size_t)r * 1024 + c] = t;
                } else {
                    int b = r >> 12, l = r & 4095;
                    int h = c >> 6, d = c & 63;
                    size_t o = (((size_t)(b * 16 + h) * 4096) + l) * 64 + d;
                    if (z == 2) {
                        __half hp[2];
                        hp[0] = __float2half_rn(vx);
                        hp[1] = __float2half_rn(vy);
                        *(uint32_t*)&g_v16[o] = *(uint32_t*)hp;
                    } else {
                        __nv_bfloat16* dh = (z == 0) ? g_qh : g_kh;
                        __nv_bfloat16* dl = (z == 0) ? g_ql : g_kl;
                        __nv_bfloat16 hp[2], lp[2];
                        split_bf16(vx, hp[0], lp[0]);
                        split_bf16(vy, hp[1], lp[1]);
                        *(uint32_t*)&dh[o] = *(uint32_t*)hp;
                        *(uint32_t*)&dl[o] = *(uint32_t*)lp;
                    }
                }
            }
        }
    }
}

// =====================================================================
// landmark pooling from split q/k; writes fp32 + split landmarks
// =====================================================================
__global__ void pool_kernel()
{
    int idx = blockIdx.x * blockDim.x + threadIdx.x;   // BH*M*D
    int d  = idx & 63;
    int m  = (idx >> 6) & 127;
    int bh = idx >> 13;
    size_t base = ((size_t)bh * L_ + m * SEG_) * D_ + d;
    float sq = 0.f, sk = 0.f;
    #pragma unroll
    for (int s = 0; s < SEG_; s++) {
        sq += __bfloat162float(g_qh[base + s * D_]) + __bfloat162float(g_ql[base + s * D_]);
        sk += __bfloat162float(g_kh[base + s * D_]) + __bfloat162float(g_kl[base + s * D_]);
    }
    float mq = sq * (1.f / SEG_), mk = sk * (1.f / SEG_);
    g_Ql[idx] = mq; g_Kl[idx] = mk;
    __nv_bfloat16 h, l;
    split_bf16(mq, h, l); g_Qlh[idx] = h; g_Qll[idx] = l;
    split_bf16(mk, h, l); g_Klh[idx] = h; g_Kll[idx] = l;
}

// =====================================================================
// k1: C[128 tok][128 lm] = q_blk @ Kl^T (3-term split mma) + fused softmax
// -> single fp16 probs g_k116
// =====================================================================
__global__ __launch_bounds__(256) void k1_mma_kernel()
{
    char* sm = dynsm;
    const uint32_t sb = smem_to_u32(sm);
    int bh = blockIdx.y, l0 = blockIdx.x * 128, tid = threadIdx.x;
    int lane = tid & 31, w = tid >> 5;

    {
        const __nv_bfloat16* qh = g_qh + ((size_t)bh * L_ + l0) * D_;
        const __nv_bfloat16* ql = g_ql + ((size_t)bh * L_ + l0) * D_;
        const __nv_bfloat16* kh = g_Klh + bh * (M_ * D_);
        const __nv_bfloat16* kl = g_Kll + bh * (M_ * D_);
        #pragma unroll
        for (int i = 0; i < 4; i++) {
            int q = tid + i * 256;
            int row = q >> 3, c8 = q & 7;
            uint32_t so = (uint32_t)(row * 144 + c8 * 16);
            size_t go = (size_t)row * 64 + c8 * 8;
            *(uint4*)(sm + 0     + so) = *(const uint4*)&qh[go];
            *(uint4*)(sm + 18432 + so) = *(const uint4*)&ql[go];
            *(uint4*)(sm + 36864 + so) = *(const uint4*)&kh[go];
            *(uint4*)(sm + 55296 + so) = *(const uint4*)&kl[go];
        }
    }
    __syncthreads();

    int wm = w >> 2, wn = w & 3;
    float acc[4][4][4];
    #pragma unroll
    for (int i = 0; i < 4; i++)
        #pragma unroll
        for (int j = 0; j < 4; j++)
            #pragma unroll
            for (int t = 0; t < 4; t++) acc[i][j][t] = 0.f;

    #pragma unroll
    for (int k16 = 0; k16 < 4; k16++) {
        uint32_t af[2][4][4];
        #pragma unroll
        for (int term = 0; term < 2; term++)
            #pragma unroll
            for (int mt = 0; mt < 4; mt++) {
                uint32_t addr = sb + term * 18432
                    + (uint32_t)((wm * 64 + mt * 16 + (lane & 15)) * 144)
                    + (uint32_t)(k16 * 32) + (uint32_t)((lane >> 4) * 16);
                ldsm4(af[term][mt], addr);
            }
        uint32_t bf[2][2][4];
        #pragma unroll
        for (int term = 0; term < 2; term++)
            #pragma unroll
            for (int np = 0; np < 2; np++) {
                uint32_t nrow = (uint32_t)(wn * 32 + np * 16 + ((lane >> 4) * 8) + (lane & 7));
                uint32_t addr = sb + 36864 + term * 18432 + nrow * 144
                    + (uint32_t)(k16 * 32) + (uint32_t)(((lane >> 3) & 1) * 16);
                ldsm4(bf[term][np], addr);
            }
        #pragma unroll
        for (int mt = 0; mt < 4; mt++)
            #pragma unroll
            for (int nt = 0; nt < 4; nt++) {
                float* d = acc[mt][nt];
                const uint32_t* bh_ = &bf[0][nt >> 1][(nt & 1) * 2];
                const uint32_t* bl_ = &bf[1][nt >> 1][(nt & 1) * 2];
                mma16816(d, af[0][mt], bh_);
                mma16816(d, af[0][mt], bl_);
                mma16816(d, af[1][mt], bh_);
            }
    }
    __syncthreads();

    float* S = (float*)sm;
    #pragma unroll
    for (int mt = 0; mt < 4; mt++)
        #pragma unroll
        for (int nt = 0; nt < 4; nt++)
            #pragma unroll
            for (int half = 0; half < 2; half++) {
                int row = wm * 64 + mt * 16 + (lane >> 2) + half * 8;
                int col = wn * 32 + nt * 8 + (lane & 3) * 2;
                S[row * 128 + col]     = acc[mt][nt][half * 2 + 0];
                S[row * 128 + col + 1] = acc[mt][nt][half * 2 + 1];
            }
    __syncthreads();

    for (int rr = 0; rr < 16; rr++) {
        int row = w * 16 + rr;
        float x0 = S[row * 128 + lane],      x1 = S[row * 128 + lane + 32];
        float x2 = S[row * 128 + lane + 64], x3 = S[row * 128 + lane + 96];
        float mx = fmaxf(fmaxf(x0, x1), fmaxf(x2, x3));
        #pragma unroll
        for (int o = 16; o; o >>= 1) mx = fmaxf(mx, __shfl_xor_sync(0xffffffffu, mx, o));
        float e0 = __expf(x0 - mx), e1 = __expf(x1 - mx);
        float e2 = __expf(x2 - mx), e3 = __expf(x3 - mx);
        float s = e0 + e1 + e2 + e3;
        #pragma unroll
        for (int o = 16; o; o >>= 1) s += __shfl_xor_sync(0xffffffffu, s, o);
        float inv = 1.f / s;
        size_t ob = ((size_t)bh * L_ + l0 + row) * 128;
        g_k116[ob + lane]      = __float2half_rn(e0 * inv);
        g_k116[ob + lane + 32] = __float2half_rn(e1 * inv);
        g_k116[ob + lane + 64] = __float2half_rn(e2 * inv);
        g_k116[ob + lane + 96] = __float2half_rn(e3 * inv);
    }
}

// =====================================================================
// k3 scores: C[m=128][l=128 blk] = Ql @ k_blk^T (3-term split) -> fp32 g_k3
// =====================================================================
__global__ __launch_bounds__(256) void k3score_mma_kernel()
{
    char* sm = dynsm;
    const uint32_t sb = smem_to_u32(sm);
    int bh = blockIdx.y, l0 = blockIdx.x * 128, tid = threadIdx.x;
    int lane = tid & 31, w = tid >> 5;

    {
        const __nv_bfloat16* ah = g_Qlh + bh * (M_ * D_);
        const __nv_bfloat16* al = g_Qll + bh * (M_ * D_);
        const __nv_bfloat16* bhp = g_kh + ((size_t)bh * L_ + l0) * D_;
        const __nv_bfloat16* blp = g_kl + ((size_t)bh * L_ + l0) * D_;
        #pragma unroll
        for (int i = 0; i < 4; i++) {
            int q = tid + i * 256;
            int row = q >> 3, c8 = q & 7;
            uint32_t so = (uint32_t)(row * 144 + c8 * 16);
            size_t go = (size_t)row * 64 + c8 * 8;
            *(uint4*)(sm + 0     + so) = *(const uint4*)&ah[go];
            *(uint4*)(sm + 18432 + so) = *(const uint4*)&al[go];
            *(uint4*)(sm + 36864 + so) = *(const uint4*)&bhp[go];
            *(uint4*)(sm + 55296 + so) = *(const uint4*)&blp[go];
        }
    }
    __syncthreads();

    int wm = w >> 2, wn = w & 3;
    float acc[4][4][4];
    #pragma unroll
    for (int i = 0; i < 4; i++)
        #pragma unroll
        for (int j = 0; j < 4; j++)
            #pragma unroll
            for (int t = 0; t < 4; t++) acc[i][j][t] = 0.f;

    #pragma unroll
    for (int k16 = 0; k16 < 4; k16++) {
        uint32_t af[2][4][4];
        #pragma unroll
        for (int term = 0; term < 2; term++)
            #pragma unroll
            for (int mt = 0; mt < 4; mt++) {
                uint32_t addr = sb + term * 18432
                    + (uint32_t)((wm * 64 + mt * 16 + (lane & 15)) * 144)
                    + (uint32_t)(k16 * 32) + (uint32_t)((lane >> 4) * 16);
                ldsm4(af[term][mt], addr);
            }
        uint32_t bf[2][2][4];
        #pragma unroll
        for (int term = 0; term < 2; term++)
            #pragma unroll
            for (int np = 0; np < 2; np++) {
                uint32_t nrow = (uint32_t)(wn * 32 + np * 16 + ((lane >> 4) * 8) + (lane & 7));
                uint32_t addr = sb + 36864 + term * 18432 + nrow * 144
                    + (uint32_t)(k16 * 32) + (uint32_t)(((lane >> 3) & 1) * 16);
                ldsm4(bf[term][np], addr);
            }
        #pragma unroll
        for (int mt = 0; mt < 4; mt++)
            #pragma unroll
            for (int nt = 0; nt < 4; nt++) {
                float* d = acc[mt][nt];
                const uint32_t* bh_ = &bf[0][nt >> 1][(nt & 1) * 2];
                const uint32_t* bl_ = &bf[1][nt >> 1][(nt & 1) * 2];
                mma16816(d, af[0][mt], bh_);
                mma16816(d, af[0][mt], bl_);
                mma16816(d, af[1][mt], bh_);
            }
    }

    float* o = g_k3 + (size_t)bh * M_ * L_;
    #pragma unroll
    for (int mt = 0; mt < 4; mt++)
        #pragma unroll
        for (int nt = 0; nt < 4; nt++)
            #pragma unroll
            for (int half = 0; half < 2; half++) {
                int m_r = wm * 64 + mt * 16 + (lane >> 2) + half * 8;
                int l_c = l0 + wn * 32 + nt * 8 + (lane & 3) * 2;
                float2 t = {acc[mt][nt][half * 2 + 0], acc[mt][nt][half * 2 + 1]};
                *(float2*)&o[(size_t)m_r * L_ + l_c] = t;
            }
}

// =====================================================================
// row softmax over 4096; reads fp32 g_k3, writes single fp16 g_s316
// =====================================================================
__global__ __launch_bounds__(256) void softmax4096_kernel()
{
    size_t row = blockIdx.x;
    const float* p = g_k3 + row * 4096;
    int tid = threadIdx.x;
    float v[16];
    float mx = -1e30f;
    #pragma unroll
    for (int i = 0; i < 4; i++) {
        float4 t = *(const float4*)&p[i * 1024 + tid * 4];
        v[i * 4 + 0] = t.x; v[i * 4 + 1] = t.y; v[i * 4 + 2] = t.z; v[i * 4 + 3] = t.w;
        mx = fmaxf(mx, fmaxf(fmaxf(t.x, t.y), fmaxf(t.z, t.w)));
    }
    __shared__ float smx[8], ssm[8], sres;
    #pragma unroll
    for (int o = 16; o; o >>= 1) mx = fmaxf(mx, __shfl_xor_sync(0xffffffffu, mx, o));
    if ((tid & 31) == 0) smx[tid >> 5] = mx;
    __syncthreads();
    if (tid == 0) {
        float m = smx[0];
        #pragma unroll
        for (int i = 1; i < 8; i++) m = fmaxf(m, smx[i]);
        sres = m;
    }
    __syncthreads();
    float MX = sres;
    float s = 0.f;
    #pragma unroll
    for (int i = 0; i < 16; i++) { v[i] = __expf(v[i] - MX); s += v[i]; }
    #pragma unroll
    for (int o = 16; o; o >>= 1) s += __shfl_xor_sync(0xffffffffu, s, o);
    if ((tid & 31) == 0) ssm[tid >> 5] = s;
    __syncthreads();
    if (tid == 0) {
        float t = 0.f;
        #pragma unroll
        for (int i = 0; i < 8; i++) t += ssm[i];
        sres = 1.f / t;
    }
    __syncthreads();
    float inv = sres;
    #pragma unroll
    for (int i = 0; i < 4; i++) {
        __half hh[4];
        #pragma unroll
        for (int t = 0; t < 4; t++) hh[t] = __float2half_rn(v[i * 4 + t] * inv);
        *(uint2*)&g_s316[row * 4096 + i * 1024 + tid * 4] = *(uint2*)hh;
    }
}

// =====================================================================
// kernel_2 = softmax(Q_l @ K_l^T) fused (fp32, tiny). block per head.
// =====================================================================
__global__ __launch_bounds__(256) void k2_kernel()
{
    float* sm = (float*)dynsm;
    float* Qlt = sm;
    float* Klt = sm + 8192;
    float* S   = sm + 16384;
    int bh = blockIdx.x, tid = threadIdx.x;

    const float* Ql = g_Ql + bh * 8192;
    const float* Kl = g_Kl + bh * 8192;
    #pragma unroll
    for (int i = 0; i < 8; i++) {
        int f = i * 1024 + tid * 4; int m = f >> 6, d0 = f & 63;
        float4 tq = *(const float4*)&Ql[f];
        float4 tk = *(const float4*)&Kl[f];
        Qlt[(d0 + 0) * 128 + m] = tq.x; Qlt[(d0 + 1) * 128 + m] = tq.y;
        Qlt[(d0 + 2) * 128 + m] = tq.z; Qlt[(d0 + 3) * 128 + m] = tq.w;
        Klt[(d0 + 0) * 128 + m] = tk.x; Klt[(d0 + 1) * 128 + m] = tk.y;
        Klt[(d0 + 2) * 128 + m] = tk.z; Klt[(d0 + 3) * 128 + m] = tk.w;
    }
    __syncthreads();

    int tm = tid >> 4, tn = tid & 15;
    float acc[8][8] = {};
    for (int d = 0; d < 64; d++) {
        float4 a0 = *(const float4*)&Qlt[d * 128 + tm * 8];
        float4 a1 = *(const float4*)&Qlt[d * 128 + tm * 8 + 4];
        float4 b0 = *(const float4*)&Klt[d * 128 + tn * 8];
        float4 b1 = *(const float4*)&Klt[d * 128 + tn * 8 + 4];
        float av[8] = {a0.x, a0.y, a0.z, a0.w, a1.x, a1.y, a1.z, a1.w};
        float bv[8] = {b0.x, b0.y, b0.z, b0.w, b1.x, b1.y, b1.z, b1.w};
        #pragma unroll
        for (int i = 0; i < 8; i++)
            #pragma unroll
            for (int j = 0; j < 8; j++) acc[i][j] += av[i] * bv[j];
    }
    #pragma unroll
    for (int i = 0; i < 8; i++)
        #pragma unroll
        for (int j = 0; j < 8; j++) S[(tm * 8 + i) * 128 + tn * 8 + j] = acc[i][j];
    __syncthreads();

    int lane = tid & 31, w = tid >> 5;
    for (int rr = 0; rr < 16; rr++) {
        int row = w * 16 + rr;
        float x0 = S[row * 128 + lane],      x1 = S[row * 128 + lane + 32];
        float x2 = S[row * 128 + lane + 64], x3 = S[row * 128 + lane + 96];
        float mx = fmaxf(fmaxf(x0, x1), fmaxf(x2, x3));
        #pragma unroll
        for (int o = 16; o; o >>= 1) mx = fmaxf(mx, __shfl_xor_sync(0xffffffffu, mx, o));
        float e0 = __expf(x0 - mx), e1 = __expf(x1 - mx);
        float e2 = __expf(x2 - mx), e3 = __expf(x3 - mx);
        float s = e0 + e1 + e2 + e3;
        #pragma unroll
        for (int o = 16; o; o >>= 1) s += __shfl_xor_sync(0xffffffffu, s, o);
        float inv = 1.f / s;
        float* o = g_k2 + bh * 16384 + row * 128;
        o[lane] = e0 * inv; o[lane + 32] = e1 * inv; o[lane + 64] = e2 * inv; o[lane + 96] = e3 * inv;
    }
}

// =====================================================================
// V0 = K^T / max(colsum(K))
// =====================================================================
__global__ __launch_bounds__(256) void vinit_kernel()
{
    int bh = blockIdx.x, tid = threadIdx.x;
    const float* K = g_k2 + bh * 16384;
    __shared__ float cs[128];
    __shared__ float sscale;
    if (tid < 128) {
        float s = 0.f;
        for (int r = 0; r < 128; r++) s += K[r * 128 + tid];
        cs[tid] = s;
    }
    __syncthreads();
    if (tid == 0) {
        float m = cs[0];
        for (int i = 1; i < 128; i++) m = fmaxf(m, cs[i]);
        sscale = 1.f / m;
    }
    __syncthreads();
    float scale = sscale;
    for (int f = tid; f < 16384; f += 256) {
        int i = f >> 7, j = f & 127;
        g_Va[bh * 16384 + f] = scale * K[j * 128 + i];
    }
}

// =====================================================================
// batched 128x128 bmm for Newton-Schulz (fp32)
// =====================================================================
__device__ __forceinline__ float* bufsel(int s)
{
    switch (s) {
        case 0: return g_k2; case 1: return g_P; case 2: return g_M1;
        case 3: return g_M2; case 4: return g_Va; default: return g_Vb;
    }
}

__global__ __launch_bounds__(256) void bmm_kernel(int as, int bs, int cs2, int os,
                                                  float alpha, float beta)
{
    float* sm = (float*)dynsm;
    float* Bs = sm;
    float* At = sm + 16384;
    int bh = blockIdx.y, r0 = blockIdx.x * 32, tid = threadIdx.x;
    const float* A  = bufsel(as)  + bh * 16384;
    const float* Bm = bufsel(bs)  + bh * 16384;
    const float* C  = bufsel(cs2) + bh * 16384;
    float* O        = bufsel(os)  + bh * 16384;

    #pragma unroll
    for (int i = 0; i < 16; i++) {
        int f = i * 1024 + tid * 4;
        *(float4*)&Bs[f] = *(const float4*)&Bm[f];
    }
    #pragma unroll
    for (int i = 0; i < 4; i++) {
        int f = i * 1024 + tid * 4; int r = f >> 7, k0 = f & 127;
        float4 t = *(const float4*)&A[(r0 + r) * 128 + k0];
        At[(k0 + 0) * 32 + r] = t.x; At[(k0 + 1) * 32 + r] = t.y;
        At[(k0 + 2) * 32 + r] = t.z; At[(k0 + 3) * 32 + r] = t.w;
    }
    __syncthreads();

    int rb = (tid >> 5) * 4, cb = (tid & 31) * 4;
    float acc[4][4] = {};
    for (int k = 0; k < 128; k++) {
        float a0 = At[k * 32 + rb + 0], a1 = At[k * 32 + rb + 1];
        float a2 = At[k * 32 + rb + 2], a3 = At[k * 32 + rb + 3];
        float4 b = *(const float4*)&Bs[k * 128 + cb];
        acc[0][0] += a0 * b.x; acc[0][1] += a0 * b.y; acc[0][2] += a0 * b.z; acc[0][3] += a0 * b.w;
        acc[1][0] += a1 * b.x; acc[1][1] += a1 * b.y; acc[1][2] += a1 * b.z; acc[1][3] += a1 * b.w;
        acc[2][0] += a2 * b.x; acc[2][1] += a2 * b.y; acc[2][2] += a2 * b.z; acc[2][3] += a2 * b.w;
        acc[3][0] += a3 * b.x; acc[3][1] += a3 * b.y; acc[3][2] += a3 * b.z; acc[3][3] += a3 * b.w;
    }
    #pragma unroll
    for (int i = 0; i < 4; i++)
        #pragma unroll
        for (int j = 0; j < 4; j++) {
            int idx = (r0 + rb + i) * 128 + cb + j;
            O[idx] = alpha * acc[i][j] + beta * C[idx];
        }
}

// =====================================================================
// k3v: partial C[m=128][d=64] = s3_fp16 @ v_fp16 (1-term, split-K 4)
// 2-stage pipeline. stage = A(18432) + B(9216) = 27648; dyn smem 55296
// =====================================================================
#define KV_TS_A 18432
#define KV_STG  27648

__global__ __launch_bounds__(256) void k3v_mma_kernel()
{
    char* sm = dynsm;
    const uint32_t sb = smem_to_u32(sm);
    int s = blockIdx.x, bh = blockIdx.y, tid = threadIdx.x;
    int lane = tid & 31, w = tid >> 5;
    int wm = w >> 1, wn = w & 1;
    const size_t abase = (size_t)bh * M_ * L_;
    const size_t vbase = (size_t)bh * L_ * D_;

    float acc[2][4][4];
    #pragma unroll
    for (int i = 0; i < 2; i++)
        #pragma unroll
        for (int j = 0; j < 4; j++)
            #pragma unroll
            for (int t = 0; t < 4; t++) acc[i][j][t] = 0.f;

    auto load = [&](int ck, int buf) {
        int k0 = s * 1024 + ck * 64;
        uint32_t S = sb + buf * KV_STG;
        #pragma unroll
        for (int i = 0; i < 4; i++) {               // A: probs, 128 rows x 128 B
            int q = tid + i * 256;
            int row = q >> 3, c8 = q & 7;
            uint32_t dst = S + (uint32_t)(row * 144 + c8 * 16);
            CP_ASYNC16(dst, g_s316 + abase + (size_t)row * L_ + k0 + c8 * 8);
        }
        #pragma unroll
        for (int i = 0; i < 2; i++) {               // B: v, 64 rows x 128 B
            int q = tid + i * 256;
            int row = q >> 3, c8 = q & 7;
            uint32_t dst = S + KV_TS_A + (uint32_t)(row * 144 + c8 * 16);
            CP_ASYNC16(dst, g_v16 + vbase + (size_t)(k0 + row) * D_ + c8 * 8);
        }
        CP_COMMIT();
    };

    auto compute = [&](int buf) {
        uint32_t S = sb + buf * KV_STG;
        #pragma unroll
        for (int k16 = 0; k16 < 4; k16++) {
            uint32_t af[2][4];
            #pragma unroll
            for (int mt = 0; mt < 2; mt++) {
                uint32_t addr = S
                    + (uint32_t)((wm * 32 + mt * 16 + (lane & 15)) * 144)
                    + (uint32_t)(k16 * 32) + (uint32_t)((lane >> 4) * 16);
                ldsm4(af[mt], addr);
            }
            uint32_t bf[2][4];
            #pragma unroll
            for (int np = 0; np < 2; np++) {
                uint32_t addr = S + KV_TS_A
                    + (uint32_t)((k16 * 16 + (lane & 15)) * 144)
                    + (uint32_t)((wn * 32 + np * 16 + (lane >> 4) * 8) * 2);
                ldsm4t(bf[np], addr);
            }
            #pragma unroll
            for (int mt = 0; mt < 2; mt++)
                #pragma unroll
                for (int nt = 0; nt < 4; nt++)
                    mma16816h(acc[mt][nt], af[mt], &bf[nt >> 1][(nt & 1) * 2]);
        }
    };

    load(0, 0);
    #pragma unroll 1
    for (int ck = 0; ck < 16; ck++) {
        if (ck + 1 < 16) {
            load(ck + 1, (ck + 1) & 1);
            CP_WAIT(1);
        } else {
            CP_WAIT(0);
        }
        __syncthreads();
        compute(ck & 1);
        __syncthreads();
    }

    #pragma unroll
    for (int mt = 0; mt < 2; mt++)
        #pragma unroll
        for (int nt = 0; nt < 4; nt++)
            #pragma unroll
            for (int half = 0; half < 2; half++) {
                int m_r = wm * 32 + mt * 16 + (lane >> 2) + half * 8;
                int d_c = wn * 32 + nt * 8 + (lane & 3) * 2;
                float2 t = {acc[mt][nt][half * 2 + 0], acc[mt][nt][half * 2 + 1]};
                *(float2*)&g_k3v_part[((size_t)(s * 64 + bh) * 128 + m_r) * 64 + d_c] = t;
            }
}

// =====================================================================
// y2 = inv(g_Va) @ sum(k3v parts) per head (fp32); emits y2^T single fp16
// =====================================================================
__global__ __launch_bounds__(256) void y2_kernel()
{
    float* sm = (float*)dynsm;
    float* At = sm;
    float* Bs = sm + 16384;
    int bh = blockIdx.x, tid = threadIdx.x;
    const float* inv = g_Va + bh * 16384;

    #pragma unroll
    for (int i = 0; i < 16; i++) {
        int f = i * 1024 + tid * 4; int r = f >> 7, k0 = f & 127;
        float4 t = *(const float4*)&inv[f];
        At[(k0 + 0) * 128 + r] = t.x; At[(k0 + 1) * 128 + r] = t.y;
        At[(k0 + 2) * 128 + r] = t.z; At[(k0 + 3) * 128 + r] = t.w;
    }
    #pragma unroll
    for (int i = 0; i < 8; i++) {
        int f = i * 1024 + tid * 4;
        size_t o = (size_t)bh * 8192 + f;
        float4 a = *(const float4*)&g_k3v_part[o];
        float4 b = *(const float4*)&g_k3v_part[o + 524288];
        float4 c = *(const float4*)&g_k3v_part[o + 2 * 524288];
        float4 d = *(const float4*)&g_k3v_part[o + 3 * 524288];
        float4 t = {a.x + b.x + c.x + d.x, a.y + b.y + c.y + d.y,
                    a.z + b.z + c.z + d.z, a.w + b.w + c.w + d.w};
        *(float4*)&Bs[f] = t;
    }
    __syncthreads();

    int rt = tid >> 4, ct = tid & 15;
    float acc[8][4] = {};
    for (int k = 0; k < 128; k++) {
        float4 a0 = *(const float4*)&At[k * 128 + rt * 8];
        float4 a1 = *(const float4*)&At[k * 128 + rt * 8 + 4];
        float4 b  = *(const float4*)&Bs[k * 64 + ct * 4];
        float av[8] = {a0.x, a0.y, a0.z, a0.w, a1.x, a1.y, a1.z, a1.w};
        #pragma unroll
        for (int i = 0; i < 8; i++) {
            acc[i][0] += av[i] * b.x; acc[i][1] += av[i] * b.y;
            acc[i][2] += av[i] * b.z; acc[i][3] += av[i] * b.w;
        }
    }
    #pragma unroll
    for (int i = 0; i < 8; i++)
        #pragma unroll
        for (int j = 0; j < 4; j++) {
            size_t o = (size_t)bh * 8192 + (ct * 4 + j) * 128 + rt * 8 + i;
            g_y2t16[o] = __float2half_rn(acc[i][j]);
        }
}

// =====================================================================
// x1: C[l=128][d=64] = k1_fp16 @ y2t_fp16 (1-term) -> g_a16 slot 0
// smem: A 34816 | B 17408 ; dyn smem 52224 (pitch 272 B)
// =====================================================================
__global__ __launch_bounds__(256) void x1_mma_kernel()
{
    char* sm = dynsm;
    const uint32_t sb = smem_to_u32(sm);
    int bh = blockIdx.y, l0 = blockIdx.x * 128, tid = threadIdx.x;
    int lane = tid & 31, w = tid >> 5;
    int wm = w >> 1, wn = w & 1;

    {
        const __half* ap = g_k116 + ((size_t)bh * L_ + l0) * 128;
        #pragma unroll
        for (int i = 0; i < 8; i++) {
            int q = tid + i * 256;                 // 0..2047
            int row = q >> 4, c16 = q & 15;
            uint32_t so = (uint32_t)(row * 272 + c16 * 16);
            *(uint4*)(sm + so) = *(const uint4*)&ap[(size_t)row * 128 + c16 * 8];
        }
        const __half* bp = g_y2t16 + (size_t)bh * 8192;
        #pragma unroll
        for (int i = 0; i < 4; i++) {
            int q = tid + i * 256;                 // 0..1023
            int row = q >> 4, c16 = q & 15;
            uint32_t so = (uint32_t)(34816 + row * 272 + c16 * 16);
            *(uint4*)(sm + so) = *(const uint4*)&bp[(size_t)row * 128 + c16 * 8];
        }
    }
    __syncthreads();

    float acc[2][4][4];
    #pragma unroll
    for (int i = 0; i < 2; i++)
        #pragma unroll
        for (int j = 0; j < 4; j++)
            #pragma unroll
            for (int t = 0; t < 4; t++) acc[i][j][t] = 0.f;

    #pragma unroll
    for (int k16 = 0; k16 < 8; k16++) {
        uint32_t af[2][4];
        #pragma unroll
        for (int mt = 0; mt < 2; mt++) {
            uint32_t addr = sb
                + (uint32_t)((wm * 32 + mt * 16 + (lane & 15)) * 272)
                + (uint32_t)(k16 * 32) + (uint32_t)((lane >> 4) * 16);
            ldsm4(af[mt], addr);
        }
        uint32_t bf[2][4];
        #pragma unroll
        for (int np = 0; np < 2; np++) {
            uint32_t nrow = (uint32_t)(wn * 32 + np * 16 + ((lane >> 4) * 8) + (lane & 7));
            uint32_t addr = sb + 34816 + nrow * 272
                + (uint32_t)(k16 * 32) + (uint32_t)(((lane >> 3) & 1) * 16);
            ldsm4(bf[np], addr);
        }
        #pragma unroll
        for (int mt = 0; mt < 2; mt++)
            #pragma unroll
            for (int nt = 0; nt < 4; nt++)
                mma16816h(acc[mt][nt], af[mt], &bf[nt >> 1][(nt & 1) * 2]);
    }

    int b = bh >> 4, h = bh & 15;
    #pragma unroll
    for (int mt = 0; mt < 2; mt++)
        #pragma unroll
        for (int nt = 0; nt < 4; nt++)
            #pragma unroll
            for (int half = 0; half < 2; half++) {
                int l = l0 + wm * 32 + mt * 16 + (lane >> 2) + half * 8;
                int d_c = wn * 32 + nt * 8 + (lane & 3) * 2;
                size_t o = ((size_t)(b * L_ + l)) * DM_ + h * 64 + d_c;
                __half hp[2];
                hp[0] = __float2half_rn(acc[mt][nt][half * 2 + 0]);
                hp[1] = __float2half_rn(acc[mt][nt][half * 2 + 1]);
                *(uint32_t*)&g_a16[o] = *(uint32_t*)hp;
            }
}

// =====================================================================
// launch — capture-legal fork/join (side stream enters capture via ev_start)
// =====================================================================
extern "C" void kernel_launch(void* const* d_in, const int* in_sizes, int n_in,
                              void* d_out, int out_size)
{
    const float* queries = (const float*)d_in[0];
    const float* keys    = (const float*)d_in[1];
    const float* values  = (const float*)d_in[2];
    const float* Wq = (const float*)d_in[3];
    const float* bq = (const float*)d_in[4];
    const float* Wk = (const float*)d_in[5];
    const float* bk = (const float*)d_in[6];
    const float* Wv = (const float*)d_in[7];
    const float* bv = (const float*)d_in[8];
    const float* Wo = (const float*)d_in[9];
    const float* bo = (const float*)d_in[10];
    float* out = (float*)d_out;

    cudaFuncSetAttribute(gemm_fp16_kernel,   cudaFuncAttributeMaxDynamicSharedMemorySize, H_SM);
    cudaFuncSetAttribute(k1_mma_kernel,      cudaFuncAttributeMaxDynamicSharedMemorySize, 73728);
    cudaFuncSetAttribute(k3score_mma_kernel, cudaFuncAttributeMaxDynamicSharedMemorySize, 73728);
    cudaFuncSetAttribute(k3v_mma_kernel,     cudaFuncAttributeMaxDynamicSharedMemorySize, 55296);
    cudaFuncSetAttribute(x1_mma_kernel,      cudaFuncAttributeMaxDynamicSharedMemorySize, 52224);
    cudaFuncSetAttribute(k2_kernel,          cudaFuncAttributeMaxDynamicSharedMemorySize, 131072);
    cudaFuncSetAttribute(bmm_kernel,         cudaFuncAttributeMaxDynamicSharedMemorySize, 81920);
    cudaFuncSetAttribute(y2_kernel,          cudaFuncAttributeMaxDynamicSharedMemorySize, 98304);

    static cudaStream_t s_b = nullptr;
    static cudaEvent_t ev_start = nullptr, ev_wt = nullptr, ev_fork = nullptr, ev_join = nullptr;
    if (!s_b) {
        cudaStreamCreateWithFlags(&s_b, cudaStreamNonBlocking);
        cudaEventCreateWithFlags(&ev_start, cudaEventDisableTiming);
        cudaEventCreateWithFlags(&ev_wt,    cudaEventDisableTiming);
        cudaEventCreateWithFlags(&ev_fork,  cudaEventDisableTiming);
        cudaEventCreateWithFlags(&ev_join,  cudaEventDisableTiming);
    }

    dim3 wt_grid(32, 32), wt_blk(32, 8);

    // fork side stream INTO the capture before any s_b work
    cudaEventRecord(ev_start, 0);
    cudaStreamWaitEvent(s_b, ev_start, 0);

    // weight conversions on side stream, activation conversion on main
    conv_wt_kernel<<<wt_grid, wt_blk, 0, s_b>>>(Wq, 0);
    conv_wt_kernel<<<wt_grid, wt_blk, 0, s_b>>>(Wk, 1);
    conv_wt_kernel<<<wt_grid, wt_blk, 0, s_b>>>(Wv, 2);
    conv_wt_kernel<<<wt_grid, wt_blk, 0, s_b>>>(Wo, 3);
    cudaEventRecord(ev_wt, s_b);
    conv_act3_kernel<<<dim3(16384, 3), 256>>>(queries, keys, values);
    cudaStreamWaitEvent(0, ev_wt, 0);

    // fused QKV projection (fp16 1-term, 3-stage BK=64)
    gemm_fp16_kernel<<<dim3(8, 128, 3), 256, H_SM>>>(bq, bk, bv, nullptr, -1);

    // landmarks (both branches depend on this)
    pool_kernel<<<2048, 256>>>();

    // ---- fork: Newton-Schulz chain on side stream ----
    cudaEventRecord(ev_fork, 0);
    cudaStreamWaitEvent(s_b, ev_fork, 0);
    k2_kernel<<<64, 256, 131072, s_b>>>();
    vinit_kernel<<<64, 256, 0, s_b>>>();
    {
        int cur = 4, nxt = 5;
        for (int it = 0; it < 6; it++) {
            bmm_kernel<<<dim3(4, 64), 256, 81920, s_b>>>(0,   cur, 0,   1,   1.0f,  0.0f);
            bmm_kernel<<<dim3(4, 64), 256, 81920, s_b>>>(1,   1,   1,   2,  -1.0f,  7.0f);
            bmm_kernel<<<dim3(4, 64), 256, 81920, s_b>>>(1,   2,   1,   3,  -1.0f, 15.0f);
            bmm_kernel<<<dim3(4, 64), 256, 81920, s_b>>>(cur, 3,   cur, nxt, -0.25f, 3.25f);
            int t = cur; cur = nxt; nxt = t;
        }
    }
    cudaEventRecord(ev_join, s_b);

    // ---- main stream: big attention chain ----
    k1_mma_kernel<<<dim3(32, 64), 256, 73728>>>();
    k3score_mma_kernel<<<dim3(32, 64), 256, 73728>>>();
    softmax4096_kernel<<<8192, 256>>>();
    k3v_mma_kernel<<<dim3(4, 64), 256, 55296>>>();

    // ---- join: y2 needs g_Va (side) + k3v parts (main) ----
    cudaStreamWaitEvent(0, ev_join, 0);
    y2_kernel<<<64, 256, 98304>>>();
    x1_mma_kernel<<<dim3(32, 64), 256, 52224>>>();

    // output projection (A slot 0, W slot 3)
    gemm_fp16_kernel<<<dim3(8, 128, 1), 256, H_SM>>>(bo, nullptr, nullptr, out, 3);
}